// round 4
// baseline (speedup 1.0000x reference)
#include <cuda_runtime.h>
#include <math.h>
#include <stdint.h>

#define Bb 16
#define Ss 4096
#define Dd 64
#define Hh 8
#define NB 64          // buckets per hash
#define NCHUNK 512     // Hh * NB
#define NEGV (-50000.0f)

typedef unsigned long long ull;

// ---------------- f32x2 packed-math helpers (sm_103a FFMA2) -----------------
__device__ __forceinline__ ull ffma2(ull a, ull b, ull c) {
    ull d;
    asm("fma.rn.f32x2 %0, %1, %2, %3;" : "=l"(d) : "l"(a), "l"(b), "l"(c));
    return d;
}
__device__ __forceinline__ ull pack2(float lo, float hi) {
    ull r;
    asm("mov.b64 %0, {%1, %2};" : "=l"(r) : "f"(lo), "f"(hi));
    return r;
}
__device__ __forceinline__ float f32x2_sum(ull v) {
    float lo, hi;
    asm("mov.b64 {%0, %1}, %2;" : "=f"(lo), "=f"(hi) : "l"(v));
    return lo + hi;
}
__device__ __forceinline__ void unpack2(ull v, float& lo, float& hi) {
    asm("mov.b64 {%0, %1}, %2;" : "=f"(lo), "=f"(hi) : "l"(v));
}
__device__ __forceinline__ ull ld64s(const float* p) {
    return *(const ull*)p;   // caller guarantees 8B alignment
}

// ---------------- device scratch (static globals: no runtime allocation) ----
__device__ int   g_bucket[Bb*Hh*Ss];     // local bucket id 0..63 per (b,h,t)
__device__ int   g_perm  [Bb*Hh*Ss];     // sorted rank -> t  (per (b,h) segment)
__device__ float g_o     [(size_t)Bb*Hh*Ss*Dd]; // per-hash outputs
__device__ float g_logits[Bb*Hh*Ss];     // per-hash lse

// ---------------- 1) LSH hashing ---------------------------------------------
// FFMA2 packed over TOKEN PAIRS: each token's accumulator still sums f in the
// exact sequential order of the round-1 passing kernel -> bit-identical argmax.
#define TT 16
#define QT_STRIDE 18
#define HASH_SMEM ((64*256 + 64*QT_STRIDE) * 4)
__global__ void __launch_bounds__(256) hash_kernel(
    const float* __restrict__ qk, const float* __restrict__ rot)
{
    extern __shared__ float sm[];
    float* rotS = sm;               // [64][256]  (f major, hi = tid)
    float* qsT  = sm + 64*256;      // [64][18]   qsT[f*18 + i] = qk[t0+i][f]

    int blocksPerB = Ss / TT;                 // 256
    int b  = blockIdx.x / blocksPerB;
    int t0 = (blockIdx.x % blocksPerB) * TT;
    int tid = threadIdx.x;

    const float* rb = rot + (size_t)b * 64 * 256;
    for (int f = 0; f < 64; f++)
        rotS[f*256 + tid] = rb[f*256 + tid];
    {   // transposed q tile: thread = (i = tid>>6, f = tid&63), i strided by 4
        int f = tid & 63;
        int i0 = tid >> 6;
        #pragma unroll
        for (int i = i0; i < TT; i += 4)
            qsT[f*QT_STRIDE + i] = qk[((size_t)b*Ss + t0 + i)*Dd + f];
    }
    __syncthreads();

    ull acc2[TT/2];
    #pragma unroll
    for (int ip = 0; ip < TT/2; ip++) acc2[ip] = 0ull;
    for (int f = 0; f < 64; f++) {
        float rv = rotS[f*256 + tid];
        ull rv2 = pack2(rv, rv);
        #pragma unroll
        for (int ip = 0; ip < TT/2; ip++)
            acc2[ip] = ffma2(ld64s(qsT + f*QT_STRIDE + 2*ip), rv2, acc2[ip]);
    }

    int lane = tid & 31;
    int h    = tid >> 5;            // warp w handles hash w
    #pragma unroll
    for (int ip = 0; ip < TT/2; ip++) {
        float va[2];
        unpack2(acc2[ip], va[0], va[1]);
        #pragma unroll
        for (int s = 0; s < 2; s++) {
            float v = va[s];
            float val; int idx;
            if (v >= -v) { val = v;  idx = lane; }        // tie (v==0) -> first idx
            else         { val = -v; idx = lane + 32; }
            #pragma unroll
            for (int m = 16; m > 0; m >>= 1) {
                float ov = __shfl_xor_sync(0xffffffffu, val, m);
                int   oi = __shfl_xor_sync(0xffffffffu, idx, m);
                if (ov > val || (ov == val && oi < idx)) { val = ov; idx = oi; }
            }
            if (lane == 0)
                g_bucket[((size_t)b*Hh + h)*Ss + t0 + 2*ip + s] = idx;
        }
    }
}

// ---------------- 2) stable counting sort per (b,h) -------------------------
__global__ void __launch_bounds__(256) sort_kernel()
{
    __shared__ int sb[Ss];
    __shared__ int cnt[NB];
    __shared__ int offs[NB + 1];
    int bh  = blockIdx.x;           // b*Hh + h
    int tid = threadIdx.x;
    const int base = bh * Ss;

    for (int i = tid; i < NB; i += 256) cnt[i] = 0;
    __syncthreads();
    for (int i = tid; i < Ss; i += 256) {
        int v = g_bucket[base + i];
        sb[i] = v;
        atomicAdd(&cnt[v], 1);
    }
    __syncthreads();
    if (tid == 0) {
        offs[0] = 0;
        for (int k = 0; k < NB; k++) offs[k+1] = offs[k] + cnt[k];
    }
    __syncthreads();
    if (tid < NB) {                 // thread = bucket; stable in t order
        int w = tid, pos = offs[w];
        for (int t = 0; t < Ss; t++)
            if (sb[t] == w) g_perm[base + pos++] = t;
    }
}

// ---------------- 3) chunked attention + scatter (128 threads) --------------
#define ATH 128
#define KS_STRIDE 66
#define P_STRIDE 130
#define V_STRIDE 134
#define ATTN_SMEM ((64*KS_STRIDE + 128*KS_STRIDE + 64*V_STRIDE) * 4 + 192 * 4)
__global__ void __launch_bounds__(ATH) attn_kernel(
    const float* __restrict__ qk, const float* __restrict__ v)
{
    extern __shared__ float sm[];
    float* qs  = sm;                          // [64][66] raw q
    float* ks  = qs + 64*KS_STRIDE;           // [128][66] normalized k; reused as probs[64][130]
    float* vst = ks + 128*KS_STRIDE;          // transposed V: [64 cols][134] (+ per-col offset)
    int*   tq  = (int*)(vst + 64*V_STRIDE);   // [64]
    int*   tk  = tq + 64;                     // [128]

    int b = blockIdx.x >> 9;
    int c = blockIdx.x & (NCHUNK - 1);
    int h = c >> 6;
    int cprev = (c + NCHUNK - 1) & (NCHUNK - 1);
    int tid = threadIdx.x;
    const int pbase = b * (Hh * Ss);

    {
        int tkv = (tid < 64) ? g_perm[pbase + c*64 + tid]
                             : g_perm[pbase + cprev*64 + (tid - 64)];
        tk[tid] = tkv;
        if (tid < 64) tq[tid] = tkv;
    }
    __syncthreads();

    const float* qkb = qk + (size_t)b*Ss*Dd;
    const float* vb  = v  + (size_t)b*Ss*Dd;

    for (int idx = tid; idx < 64*16; idx += ATH) {
        int r = idx >> 4, q4 = idx & 15;
        float4 x = *(const float4*)(qkb + (size_t)tq[r]*Dd + q4*4);
        float* d = qs + r*KS_STRIDE + q4*4;
        d[0]=x.x; d[1]=x.y; d[2]=x.z; d[3]=x.w;
    }
    for (int idx = tid; idx < 128*16; idx += ATH) {
        int r = idx >> 4, q4 = idx & 15;
        float4 x = *(const float4*)(qkb + (size_t)tk[r]*Dd + q4*4);
        float* d = ks + r*KS_STRIDE + q4*4;
        d[0]=x.x; d[1]=x.y; d[2]=x.z; d[3]=x.w;
        // V transposed: element (row j=r, col c) -> vst[c*134 + g(c) + r]
        float4 y = *(const float4*)(vb + (size_t)tk[r]*Dd + q4*4);
        int c0 = q4*4;
        vst[(c0+0)*V_STRIDE + 2*(((c0+0)>>4)&3) + r] = y.x;
        vst[(c0+1)*V_STRIDE + 2*(((c0+1)>>4)&3) + r] = y.y;
        vst[(c0+2)*V_STRIDE + 2*(((c0+2)>>4)&3) + r] = y.z;
        vst[(c0+3)*V_STRIDE + 2*(((c0+3)>>4)&3) + r] = y.w;
    }
    __syncthreads();

    // normalize k rows (make_unit_length: x / (||x|| + 1e-6))
    {
        float* row = ks + tid*KS_STRIDE;
        ull s2 = 0ull;
        #pragma unroll
        for (int f = 0; f < 64; f += 2) {
            ull x = ld64s(row + f);
            s2 = ffma2(x, x, s2);
        }
        float ssq = f32x2_sum(s2);
        float inv = 1.0f / (sqrtf(ssq) + 1e-6f);
        #pragma unroll
        for (int f = 0; f < 64; f++) row[f] *= inv;
    }
    __syncthreads();

    // dots[64][128]: thread (rt,ct) owns rows 8rt+a (a<8), cols ct+16*jj (jj<8)
    int rt = tid >> 4;               // 0..7
    int ct = tid & 15;               // 0..15
    ull dacc2[8][8];
    #pragma unroll
    for (int a = 0; a < 8; a++)
        #pragma unroll
        for (int jj = 0; jj < 8; jj++) dacc2[a][jj] = 0ull;

    #pragma unroll 1
    for (int f = 0; f < 64; f += 2) {
        ull qv2[8], kv2[8];
        #pragma unroll
        for (int a = 0; a < 8; a++)  qv2[a]  = ld64s(qs + (8*rt + a)*KS_STRIDE + f);
        #pragma unroll
        for (int jj = 0; jj < 8; jj++) kv2[jj] = ld64s(ks + (ct + 16*jj)*KS_STRIDE + f);
        #pragma unroll
        for (int a = 0; a < 8; a++)
            #pragma unroll
            for (int jj = 0; jj < 8; jj++)
                dacc2[a][jj] = ffma2(qv2[a], kv2[jj], dacc2[a][jj]);
    }

    // mask (t==t' -> -5e4, unscaled), scale others by 0.125, per-row lse
    float dacc[8][8];
    float lse[8];
    #pragma unroll
    for (int a = 0; a < 8; a++) {
        int r  = 8*rt + a;
        int tr = tq[r];
        float m = -1e30f;
        #pragma unroll
        for (int jj = 0; jj < 8; jj++) {
            int j = ct + 16*jj;
            float dv = f32x2_sum(dacc2[a][jj]);
            dv = (tk[j] == tr) ? NEGV : dv*0.125f;
            dacc[a][jj] = dv;
            m = fmaxf(m, dv);
        }
        #pragma unroll
        for (int s = 1; s < 16; s <<= 1)
            m = fmaxf(m, __shfl_xor_sync(0xffffffffu, m, s));
        float sum = 0.f;
        #pragma unroll
        for (int jj = 0; jj < 8; jj++) sum += __expf(dacc[a][jj] - m);
        #pragma unroll
        for (int s = 1; s < 16; s <<= 1)
            sum += __shfl_xor_sync(0xffffffffu, sum, s);
        lse[a] = m + __logf(sum);
    }
    __syncthreads();   // all threads done reading ks before overwrite

    float* probs = ks;  // reuse (128*66 >= 64*130)
    #pragma unroll
    for (int a = 0; a < 8; a++) {
        int r = 8*rt + a;
        #pragma unroll
        for (int jj = 0; jj < 8; jj++)
            probs[r*P_STRIDE + ct + 16*jj] = __expf(dacc[a][jj] - lse[a]);
        if (ct == 0)
            g_logits[pbase + h*Ss + tq[r]] = lse[a];
    }
    __syncthreads();

    // bo = probs @ V : thread owns rows 8rt+a (a<8), cols ct+16*e (e<4)
    ull oacc2[8][4];
    #pragma unroll
    for (int a = 0; a < 8; a++)
        #pragma unroll
        for (int e = 0; e < 4; e++) oacc2[a][e] = 0ull;

    const float* vcol[4];
    #pragma unroll
    for (int e = 0; e < 4; e++)
        vcol[e] = vst + (ct + 16*e)*V_STRIDE + 2*e;   // g(ct+16e) = 2e

    #pragma unroll 1
    for (int j = 0; j < 128; j += 2) {
        ull pv2[8], vv2[4];
        #pragma unroll
        for (int a = 0; a < 8; a++) pv2[a] = ld64s(probs + (8*rt + a)*P_STRIDE + j);
        #pragma unroll
        for (int e = 0; e < 4; e++) vv2[e] = ld64s(vcol[e] + j);
        #pragma unroll
        for (int a = 0; a < 8; a++)
            #pragma unroll
            for (int e = 0; e < 4; e++)
                oacc2[a][e] = ffma2(pv2[a], vv2[e], oacc2[a][e]);
    }
    #pragma unroll
    for (int a = 0; a < 8; a++) {
        int t = tq[8*rt + a];
        float* orow = g_o + ((size_t)(pbase + h*Ss + t))*Dd;
        #pragma unroll
        for (int e = 0; e < 4; e++)
            orow[ct + 16*e] = f32x2_sum(oacc2[a][e]);
    }
}

// ---------------- 4) combine hash rounds via softmax(logits) ----------------
__global__ void __launch_bounds__(256) combine_kernel(float* __restrict__ out)
{
    size_t gid = (size_t)blockIdx.x*256 + threadIdx.x;   // one float4 per thread
    if (gid >= (size_t)Bb*Ss*Dd/4) return;
    int e4 = (int)(gid & 15);
    size_t bt = gid >> 4;
    int t = (int)(bt & (Ss - 1));
    int b = (int)(bt >> 12);

    float l[Hh];
    float m = -1e30f;
    #pragma unroll
    for (int h = 0; h < Hh; h++) {
        l[h] = g_logits[((size_t)(b*Hh + h))*Ss + t];
        m = fmaxf(m, l[h]);
    }
    float ssum = 0.f;
    #pragma unroll
    for (int h = 0; h < Hh; h++) { l[h] = __expf(l[h] - m); ssum += l[h]; }
    float inv = 1.f / ssum;

    float4 acc = make_float4(0.f, 0.f, 0.f, 0.f);
    #pragma unroll
    for (int h = 0; h < Hh; h++) {
        float w = l[h]*inv;
        float4 o = *(const float4*)(g_o + (((size_t)(b*Hh + h))*Ss + t)*Dd + e4*4);
        acc.x += w*o.x; acc.y += w*o.y; acc.z += w*o.z; acc.w += w*o.w;
    }
    *(float4*)(out + gid*4) = acc;
}

// ---------------- 5) buckets output (global bucket ids as float) ------------
__global__ void __launch_bounds__(256) buckets_kernel(float* __restrict__ outb)
{
    int gid = blockIdx.x*256 + threadIdx.x;
    if (gid >= Bb*Hh*Ss) return;
    int h = (gid >> 12) & 7;
    outb[gid] = (float)(g_bucket[gid] + h*NB);
}

// ---------------- launch -----------------------------------------------------
extern "C" void kernel_launch(void* const* d_in, const int* in_sizes, int n_in,
                              void* d_out, int out_size)
{
    const float* qk  = (const float*)d_in[0];
    const float* v   = (const float*)d_in[1];
    const float* rot = (const float*)d_in[2];
    float* out = (float*)d_out;

    cudaFuncSetAttribute(hash_kernel, cudaFuncAttributeMaxDynamicSharedMemorySize, HASH_SMEM);
    cudaFuncSetAttribute(attn_kernel, cudaFuncAttributeMaxDynamicSharedMemorySize, ATTN_SMEM);

    hash_kernel<<<Bb*(Ss/TT), 256, HASH_SMEM>>>(qk, rot);
    sort_kernel<<<Bb*Hh, 256>>>();
    attn_kernel<<<Bb*NCHUNK, ATH, ATTN_SMEM>>>(qk, v);
    combine_kernel<<<(int)(((size_t)Bb*Ss*Dd/4 + 255)/256), 256>>>(out);

    if (out_size >= Bb*Ss*Dd + Bb*Hh*Ss) {
        buckets_kernel<<<(Bb*Hh*Ss + 255)/256, 256>>>(out + (size_t)Bb*Ss*Dd);
    }
}

// round 5
// speedup vs baseline: 1.1191x; 1.1191x over previous
#include <cuda_runtime.h>
#include <math.h>
#include <stdint.h>

#define Bb 16
#define Ss 4096
#define Dd 64
#define Hh 8
#define NB 64          // buckets per hash
#define NCHUNK 512     // Hh * NB
#define NEGV (-50000.0f)

typedef unsigned long long ull;

// ---------------- f32x2 packed-math helpers (sm_103a FFMA2) -----------------
__device__ __forceinline__ ull ffma2(ull a, ull b, ull c) {
    ull d;
    asm("fma.rn.f32x2 %0, %1, %2, %3;" : "=l"(d) : "l"(a), "l"(b), "l"(c));
    return d;
}
__device__ __forceinline__ ull pack2(float lo, float hi) {
    ull r;
    asm("mov.b64 %0, {%1, %2};" : "=l"(r) : "f"(lo), "f"(hi));
    return r;
}
__device__ __forceinline__ float f32x2_sum(ull v) {
    float lo, hi;
    asm("mov.b64 {%0, %1}, %2;" : "=f"(lo), "=f"(hi) : "l"(v));
    return lo + hi;
}
__device__ __forceinline__ void unpack2(ull v, float& lo, float& hi) {
    asm("mov.b64 {%0, %1}, %2;" : "=f"(lo), "=f"(hi) : "l"(v));
}
__device__ __forceinline__ ull ld64s(const float* p) {
    return *(const ull*)p;   // caller guarantees 8B alignment
}

// ---------------- device scratch (static globals: no runtime allocation) ----
__device__ int   g_bucket[Bb*Hh*Ss];     // local bucket id 0..63 per (b,h,t)
__device__ int   g_perm  [Bb*Hh*Ss];     // sorted rank -> t  (per (b,h) segment)
__device__ float g_o     [(size_t)Bb*Hh*Ss*Dd]; // per-hash outputs
__device__ float g_logits[Bb*Hh*Ss];     // per-hash lse

// ---------------- 1) LSH hashing ---------------------------------------------
// FFMA2 packed over TOKEN PAIRS: each token's accumulator sums f in the exact
// sequential order of the round-1 passing kernel -> bit-identical argmax.
#define TT 16
#define QT_STRIDE 18
#define HASH_SMEM ((64*256 + 64*QT_STRIDE) * 4)
__global__ void __launch_bounds__(256) hash_kernel(
    const float* __restrict__ qk, const float* __restrict__ rot)
{
    extern __shared__ float sm[];
    float* rotS = sm;               // [64][256]  (f major, hi = tid)
    float* qsT  = sm + 64*256;      // [64][18]   qsT[f*18 + i] = qk[t0+i][f]

    int blocksPerB = Ss / TT;                 // 256
    int b  = blockIdx.x / blocksPerB;
    int t0 = (blockIdx.x % blocksPerB) * TT;
    int tid = threadIdx.x;

    const float* rb = rot + (size_t)b * 64 * 256;
    for (int f = 0; f < 64; f++)
        rotS[f*256 + tid] = rb[f*256 + tid];
    {   // transposed q tile
        int f = tid & 63;
        int i0 = tid >> 6;
        #pragma unroll
        for (int i = i0; i < TT; i += 4)
            qsT[f*QT_STRIDE + i] = qk[((size_t)b*Ss + t0 + i)*Dd + f];
    }
    __syncthreads();

    ull acc2[TT/2];
    #pragma unroll
    for (int ip = 0; ip < TT/2; ip++) acc2[ip] = 0ull;
    for (int f = 0; f < 64; f++) {
        float rv = rotS[f*256 + tid];
        ull rv2 = pack2(rv, rv);
        #pragma unroll
        for (int ip = 0; ip < TT/2; ip++)
            acc2[ip] = ffma2(ld64s(qsT + f*QT_STRIDE + 2*ip), rv2, acc2[ip]);
    }

    int lane = tid & 31;
    int h    = tid >> 5;            // warp w handles hash w
    #pragma unroll
    for (int ip = 0; ip < TT/2; ip++) {
        float va[2];
        unpack2(acc2[ip], va[0], va[1]);
        #pragma unroll
        for (int s = 0; s < 2; s++) {
            float v = va[s];
            float val; int idx;
            if (v >= -v) { val = v;  idx = lane; }        // tie (v==0) -> first idx
            else         { val = -v; idx = lane + 32; }
            #pragma unroll
            for (int m = 16; m > 0; m >>= 1) {
                float ov = __shfl_xor_sync(0xffffffffu, val, m);
                int   oi = __shfl_xor_sync(0xffffffffu, idx, m);
                if (ov > val || (ov == val && oi < idx)) { val = ov; idx = oi; }
            }
            if (lane == 0)
                g_bucket[((size_t)b*Hh + h)*Ss + t0 + 2*ip + s] = idx;
        }
    }
}

// ---------------- 2) stable counting sort per (b,h) -------------------------
__global__ void __launch_bounds__(256) sort_kernel()
{
    __shared__ int sb[Ss];
    __shared__ int cnt[NB];
    __shared__ int offs[NB + 1];
    int bh  = blockIdx.x;           // b*Hh + h
    int tid = threadIdx.x;
    const int base = bh * Ss;

    for (int i = tid; i < NB; i += 256) cnt[i] = 0;
    __syncthreads();
    for (int i = tid; i < Ss; i += 256) {
        int v = g_bucket[base + i];
        sb[i] = v;
        atomicAdd(&cnt[v], 1);
    }
    __syncthreads();
    if (tid == 0) {
        offs[0] = 0;
        for (int k = 0; k < NB; k++) offs[k+1] = offs[k] + cnt[k];
    }
    __syncthreads();
    if (tid < NB) {                 // thread = bucket; stable in t order
        int w = tid, pos = offs[w];
        for (int t = 0; t < Ss; t++)
            if (sb[t] == w) g_perm[base + pos++] = t;
    }
}

// ---------------- 3) chunked attention + scatter -----------------------------
// bq == raw K rows 0..63, so we keep only the normalized K tile and a per-row
// scale s_r = ||q_r||+eps:  dots = s_r * (q_hat . k_hat) * 0.125
#define KS_STRIDE 66
#define P_STRIDE 130
#define V_STRIDE 134
#define ATTN_SMEM ((128*KS_STRIDE + 64*V_STRIDE + 64) * 4 + 192 * 4)
__global__ void __launch_bounds__(256, 2) attn_kernel(
    const float* __restrict__ qk, const float* __restrict__ v)
{
    extern __shared__ float sm[];
    float* ks  = sm;                          // [128][66] normalized k; reused as probs[64][130]
    float* vst = ks + 128*KS_STRIDE;          // transposed V: [64 cols][134] (+ per-col offset)
    float* qsc = vst + 64*V_STRIDE;           // [64] per-q-row scale
    int*   tq  = (int*)(qsc + 64);            // [64]
    int*   tk  = tq + 64;                     // [128]

    int b = blockIdx.x >> 9;
    int c = blockIdx.x & (NCHUNK - 1);
    int h = c >> 6;
    int cprev = (c + NCHUNK - 1) & (NCHUNK - 1);
    int tid = threadIdx.x;
    const int pbase = b * (Hh * Ss);

    if (tid < 64) {
        tq[tid] = g_perm[pbase + c*64 + tid];
    } else if (tid < 192) {
        int j = tid - 64;
        tk[j] = (j < 64) ? g_perm[pbase + c*64 + j]
                         : g_perm[pbase + cprev*64 + (j - 64)];
    }
    __syncthreads();
    if (tid < 64) tk[tid] = tq[tid];   // rows 0..63 of K == q tokens
    __syncthreads();

    const float* qkb = qk + (size_t)b*Ss*Dd;
    const float* vb  = v  + (size_t)b*Ss*Dd;

    for (int idx = tid; idx < 128*16; idx += 256) {
        int r = idx >> 4, q4 = idx & 15;
        float4 x = *(const float4*)(qkb + (size_t)tk[r]*Dd + q4*4);
        float* d = ks + r*KS_STRIDE + q4*4;
        d[0]=x.x; d[1]=x.y; d[2]=x.z; d[3]=x.w;
        // V transposed: element (row j=r, col c) -> vst[c*134 + g(c) + r]
        float4 y = *(const float4*)(vb + (size_t)tk[r]*Dd + q4*4);
        int c0 = q4*4;
        vst[(c0+0)*V_STRIDE + 2*(((c0+0)>>4)&3) + r] = y.x;
        vst[(c0+1)*V_STRIDE + 2*(((c0+1)>>4)&3) + r] = y.y;
        vst[(c0+2)*V_STRIDE + 2*(((c0+2)>>4)&3) + r] = y.z;
        vst[(c0+3)*V_STRIDE + 2*(((c0+3)>>4)&3) + r] = y.w;
    }
    __syncthreads();

    // normalize k rows in place; rows 0..63 also record scale = ||q||+eps
    if (tid < 128) {
        float* row = ks + tid*KS_STRIDE;
        ull s2 = 0ull;
        #pragma unroll
        for (int f = 0; f < 64; f += 2) {
            ull x = ld64s(row + f);
            s2 = ffma2(x, x, s2);
        }
        float nrm = sqrtf(f32x2_sum(s2)) + 1e-6f;
        float inv = 1.0f / nrm;
        #pragma unroll
        for (int f = 0; f < 64; f++) row[f] *= inv;
        if (tid < 64) qsc[tid] = nrm * 0.125f;
    }
    __syncthreads();

    // dots[64][128]: thread (rt,ct) owns rows 4rt+a, cols ct+16*jj (f packed)
    int rt = tid >> 4;
    int ct = tid & 15;
    ull dacc2[4][8];
    #pragma unroll
    for (int a = 0; a < 4; a++)
        #pragma unroll
        for (int jj = 0; jj < 8; jj++) dacc2[a][jj] = 0ull;

    #pragma unroll 2
    for (int f = 0; f < 64; f += 2) {
        ull qv2[4];
        #pragma unroll
        for (int a = 0; a < 4; a++) qv2[a] = ld64s(ks + (4*rt + a)*KS_STRIDE + f);
        #pragma unroll
        for (int jj = 0; jj < 8; jj++) {
            ull kv2 = ld64s(ks + (ct + 16*jj)*KS_STRIDE + f);
            #pragma unroll
            for (int a = 0; a < 4; a++)
                dacc2[a][jj] = ffma2(qv2[a], kv2, dacc2[a][jj]);
        }
    }

    float dacc[4][8];
    #pragma unroll
    for (int a = 0; a < 4; a++) {
        float sc = qsc[4*rt + a];
        #pragma unroll
        for (int jj = 0; jj < 8; jj++) dacc[a][jj] = f32x2_sum(dacc2[a][jj]) * sc;
    }

    // mask (t==t' -> -5e4), per-row lse
    float lse[4];
    #pragma unroll
    for (int a = 0; a < 4; a++) {
        int r  = 4*rt + a;
        int tr = tq[r];
        float m = -1e30f;
        #pragma unroll
        for (int jj = 0; jj < 8; jj++) {
            int j = ct + 16*jj;
            float dv = (tk[j] == tr) ? NEGV : dacc[a][jj];
            dacc[a][jj] = dv;
            m = fmaxf(m, dv);
        }
        #pragma unroll
        for (int s = 1; s < 16; s <<= 1)
            m = fmaxf(m, __shfl_xor_sync(0xffffffffu, m, s));
        float sum = 0.f;
        #pragma unroll
        for (int jj = 0; jj < 8; jj++) sum += __expf(dacc[a][jj] - m);
        #pragma unroll
        for (int s = 1; s < 16; s <<= 1)
            sum += __shfl_xor_sync(0xffffffffu, sum, s);
        lse[a] = m + __logf(sum);
    }
    __syncthreads();   // all threads done reading ks before overwrite

    float* probs = ks;  // reuse (128*66 >= 64*130)
    #pragma unroll
    for (int a = 0; a < 4; a++) {
        int r = 4*rt + a;
        #pragma unroll
        for (int jj = 0; jj < 8; jj++)
            probs[r*P_STRIDE + ct + 16*jj] = __expf(dacc[a][jj] - lse[a]);
        if (ct == 0)
            g_logits[pbase + h*Ss + tq[r]] = lse[a];
    }
    __syncthreads();

    // bo = probs @ V : thread owns rows 4rt+a, cols ct+16*e; packed over j
    ull oacc2[4][4];
    #pragma unroll
    for (int a = 0; a < 4; a++)
        #pragma unroll
        for (int e = 0; e < 4; e++) oacc2[a][e] = 0ull;

    const float* vcol[4];
    #pragma unroll
    for (int e = 0; e < 4; e++)
        vcol[e] = vst + (ct + 16*e)*V_STRIDE + 2*e;   // g(ct+16e) = 2e

    #pragma unroll 2
    for (int j = 0; j < 128; j += 2) {
        ull pv2[4];
        #pragma unroll
        for (int a = 0; a < 4; a++) pv2[a] = ld64s(probs + (4*rt + a)*P_STRIDE + j);
        #pragma unroll
        for (int e = 0; e < 4; e++) {
            ull vv2 = ld64s(vcol[e] + j);
            #pragma unroll
            for (int a = 0; a < 4; a++)
                oacc2[a][e] = ffma2(pv2[a], vv2, oacc2[a][e]);
        }
    }
    #pragma unroll
    for (int a = 0; a < 4; a++) {
        int t = tq[4*rt + a];
        float* orow = g_o + ((size_t)(pbase + h*Ss + t))*Dd;
        #pragma unroll
        for (int e = 0; e < 4; e++)
            orow[ct + 16*e] = f32x2_sum(oacc2[a][e]);
    }
}

// ---------------- 4) combine hash rounds via softmax(logits) ----------------
__global__ void __launch_bounds__(256) combine_kernel(float* __restrict__ out)
{
    size_t gid = (size_t)blockIdx.x*256 + threadIdx.x;   // one float4 per thread
    if (gid >= (size_t)Bb*Ss*Dd/4) return;
    int e4 = (int)(gid & 15);
    size_t bt = gid >> 4;
    int t = (int)(bt & (Ss - 1));
    int b = (int)(bt >> 12);

    float l[Hh];
    float m = -1e30f;
    #pragma unroll
    for (int h = 0; h < Hh; h++) {
        l[h] = g_logits[((size_t)(b*Hh + h))*Ss + t];
        m = fmaxf(m, l[h]);
    }
    float ssum = 0.f;
    #pragma unroll
    for (int h = 0; h < Hh; h++) { l[h] = __expf(l[h] - m); ssum += l[h]; }
    float inv = 1.f / ssum;

    float4 acc = make_float4(0.f, 0.f, 0.f, 0.f);
    #pragma unroll
    for (int h = 0; h < Hh; h++) {
        float w = l[h]*inv;
        float4 o = *(const float4*)(g_o + (((size_t)(b*Hh + h))*Ss + t)*Dd + e4*4);
        acc.x += w*o.x; acc.y += w*o.y; acc.z += w*o.z; acc.w += w*o.w;
    }
    *(float4*)(out + gid*4) = acc;
}

// ---------------- 5) buckets output (global bucket ids as float) ------------
__global__ void __launch_bounds__(256) buckets_kernel(float* __restrict__ outb)
{
    int gid = blockIdx.x*256 + threadIdx.x;
    if (gid >= Bb*Hh*Ss) return;
    int h = (gid >> 12) & 7;
    outb[gid] = (float)(g_bucket[gid] + h*NB);
}

// ---------------- launch -----------------------------------------------------
extern "C" void kernel_launch(void* const* d_in, const int* in_sizes, int n_in,
                              void* d_out, int out_size)
{
    const float* qk  = (const float*)d_in[0];
    const float* v   = (const float*)d_in[1];
    const float* rot = (const float*)d_in[2];
    float* out = (float*)d_out;

    cudaFuncSetAttribute(hash_kernel, cudaFuncAttributeMaxDynamicSharedMemorySize, HASH_SMEM);
    cudaFuncSetAttribute(attn_kernel, cudaFuncAttributeMaxDynamicSharedMemorySize, ATTN_SMEM);

    hash_kernel<<<Bb*(Ss/TT), 256, HASH_SMEM>>>(qk, rot);
    sort_kernel<<<Bb*Hh, 256>>>();
    attn_kernel<<<Bb*NCHUNK, 256, ATTN_SMEM>>>(qk, v);
    combine_kernel<<<(int)(((size_t)Bb*Ss*Dd/4 + 255)/256), 256>>>(out);

    if (out_size >= Bb*Ss*Dd + Bb*Hh*Ss) {
        buckets_kernel<<<(Bb*Hh*Ss + 255)/256, 256>>>(out + (size_t)Bb*Ss*Dd);
    }
}

// round 6
// speedup vs baseline: 1.1623x; 1.0387x over previous
#include <cuda_runtime.h>
#include <math.h>
#include <stdint.h>

#define Bb 16
#define Ss 4096
#define Dd 64
#define Hh 8
#define NB 64          // buckets per hash
#define NCHUNK 512     // Hh * NB
#define NEGV (-50000.0f)

typedef unsigned long long ull;

// ---------------- f32x2 packed-math helpers (sm_103a FFMA2) -----------------
__device__ __forceinline__ ull ffma2(ull a, ull b, ull c) {
    ull d;
    asm("fma.rn.f32x2 %0, %1, %2, %3;" : "=l"(d) : "l"(a), "l"(b), "l"(c));
    return d;
}
__device__ __forceinline__ ull pack2(float lo, float hi) {
    ull r;
    asm("mov.b64 %0, {%1, %2};" : "=l"(r) : "f"(lo), "f"(hi));
    return r;
}
__device__ __forceinline__ float f32x2_sum(ull v) {
    float lo, hi;
    asm("mov.b64 {%0, %1}, %2;" : "=f"(lo), "=f"(hi) : "l"(v));
    return lo + hi;
}
__device__ __forceinline__ void unpack2(ull v, float& lo, float& hi) {
    asm("mov.b64 {%0, %1}, %2;" : "=f"(lo), "=f"(hi) : "l"(v));
}
__device__ __forceinline__ ull ld64s(const float* p) {
    return *(const ull*)p;   // caller guarantees 8B alignment
}

// ---------------- device scratch (static globals: no runtime allocation) ----
__device__ int   g_bucket[Bb*Hh*Ss];     // local bucket id 0..63 per (b,h,t)
__device__ int   g_perm  [Bb*Hh*Ss];     // sorted rank -> t  (per (b,h) segment)
__device__ float g_o     [(size_t)Bb*Hh*Ss*Dd]; // per-hash outputs
__device__ float g_logits[Bb*Hh*Ss];     // per-hash lse

// ---------------- 1) LSH hashing ---------------------------------------------
// Rotation column read straight from gmem (L2-resident, 256-block reuse).
// f-sequential accumulation per token (token pairs packed) -> bit-exact argmax.
#define TT 16
#define QT_STRIDE 18
__global__ void __launch_bounds__(256) hash_kernel(
    const float* __restrict__ qk, const float* __restrict__ rot)
{
    __shared__ float qsT[64*QT_STRIDE];   // qsT[f*18 + i] = qk[t0+i][f]

    int blocksPerB = Ss / TT;                 // 256
    int b  = blockIdx.x / blocksPerB;
    int t0 = (blockIdx.x % blocksPerB) * TT;
    int tid = threadIdx.x;

    {   // transposed q tile
        int f = tid & 63;
        int i0 = tid >> 6;
        #pragma unroll
        for (int i = i0; i < TT; i += 4)
            qsT[f*QT_STRIDE + i] = qk[((size_t)b*Ss + t0 + i)*Dd + f];
    }
    __syncthreads();

    const float* rb = rot + (size_t)b*64*256 + tid;  // this thread's (h,i) column

    ull acc2[TT/2];
    #pragma unroll
    for (int ip = 0; ip < TT/2; ip++) acc2[ip] = 0ull;
    #pragma unroll 8
    for (int f = 0; f < 64; f++) {
        float rv = __ldg(rb + f*256);
        ull rv2 = pack2(rv, rv);
        #pragma unroll
        for (int ip = 0; ip < TT/2; ip++)
            acc2[ip] = ffma2(ld64s(qsT + f*QT_STRIDE + 2*ip), rv2, acc2[ip]);
    }

    int lane = tid & 31;
    int h    = tid >> 5;            // warp w handles hash w
    #pragma unroll
    for (int ip = 0; ip < TT/2; ip++) {
        float va[2];
        unpack2(acc2[ip], va[0], va[1]);
        #pragma unroll
        for (int s = 0; s < 2; s++) {
            float v = va[s];
            float val; int idx;
            if (v >= -v) { val = v;  idx = lane; }        // tie (v==0) -> first idx
            else         { val = -v; idx = lane + 32; }
            #pragma unroll
            for (int m = 16; m > 0; m >>= 1) {
                float ov = __shfl_xor_sync(0xffffffffu, val, m);
                int   oi = __shfl_xor_sync(0xffffffffu, idx, m);
                if (ov > val || (ov == val && oi < idx)) { val = ov; idx = oi; }
            }
            if (lane == 0)
                g_bucket[((size_t)b*Hh + h)*Ss + t0 + 2*ip + s] = idx;
        }
    }
}

// ---------------- 2) stable counting sort per (b,h), ballot-ranked ----------
__global__ void __launch_bounds__(256) sort_kernel()
{
    __shared__ int sb[Ss];
    __shared__ int cnt[NB];
    __shared__ int offs[NB + 1];
    int bh   = blockIdx.x;           // b*Hh + h
    int tid  = threadIdx.x;
    int lane = tid & 31;
    int w    = tid >> 5;             // warp id: owns buckets 8w..8w+7
    const int base = bh * Ss;

    if (tid < NB) cnt[tid] = 0;
    __syncthreads();
    for (int i = tid; i < Ss; i += 256) {
        int v = g_bucket[base + i];
        sb[i] = v;
        atomicAdd(&cnt[v], 1);
    }
    __syncthreads();
    if (tid == 0) {
        offs[0] = 0;
        for (int k = 0; k < NB; k++) offs[k+1] = offs[k] + cnt[k];
    }
    __syncthreads();

    int off[8];
    #pragma unroll
    for (int k = 0; k < 8; k++) off[k] = offs[8*w + k];

    for (int step = 0; step < Ss/32; step++) {
        int t   = step*32 + lane;
        int rel = sb[t] - 8*w;       // 0..7 if this warp owns the bucket
        #pragma unroll
        for (int k = 0; k < 8; k++) {
            unsigned mask = __ballot_sync(0xffffffffu, rel == k);
            if (rel == k) {
                int pos = off[k] + __popc(mask & ((1u << lane) - 1u));
                g_perm[base + pos] = t;
            }
            off[k] += __popc(mask);
        }
    }
}

// ---------------- 3) chunked attention + scatter -----------------------------
// bq == raw K rows 0..63: keep only normalized K and per-q-row scale
// s_r = (||q_r||+eps)*0.125:  dots = s_r * (q_hat . k_hat)
#define KS_STRIDE 66
#define P_STRIDE 130
#define V_STRIDE 134
#define ATTN_SMEM ((128*KS_STRIDE + 64*V_STRIDE + 64) * 4 + 192 * 4)
__global__ void __launch_bounds__(256, 2) attn_kernel(
    const float* __restrict__ qk, const float* __restrict__ v)
{
    extern __shared__ float sm[];
    float* ks  = sm;                          // [128][66] normalized k; reused as probs[64][130]
    float* vst = ks + 128*KS_STRIDE;          // transposed V: [64 cols][134] (+ per-col offset)
    float* qsc = vst + 64*V_STRIDE;           // [64] per-q-row scale
    int*   tq  = (int*)(qsc + 64);            // [64]
    int*   tk  = tq + 64;                     // [128]

    int b = blockIdx.x >> 9;
    int c = blockIdx.x & (NCHUNK - 1);
    int h = c >> 6;
    int cprev = (c + NCHUNK - 1) & (NCHUNK - 1);
    int tid = threadIdx.x;
    const int pbase = b * (Hh * Ss);

    if (tid < 64) {
        int val = g_perm[pbase + c*64 + tid];
        tq[tid] = val;
        tk[tid] = val;
    } else if (tid < 128) {
        tk[tid] = g_perm[pbase + cprev*64 + (tid - 64)];
    }
    __syncthreads();

    const float* qkb = qk + (size_t)b*Ss*Dd;
    const float* vb  = v  + (size_t)b*Ss*Dd;

    for (int idx = tid; idx < 128*16; idx += 256) {
        int r = idx >> 4, q4 = idx & 15;
        float4 x = *(const float4*)(qkb + (size_t)tk[r]*Dd + q4*4);
        float* d = ks + r*KS_STRIDE + q4*4;
        d[0]=x.x; d[1]=x.y; d[2]=x.z; d[3]=x.w;
        // V transposed: element (row j=r, col c) -> vst[c*134 + g(c) + r]
        float4 y = *(const float4*)(vb + (size_t)tk[r]*Dd + q4*4);
        int c0 = q4*4;
        vst[(c0+0)*V_STRIDE + 2*(((c0+0)>>4)&3) + r] = y.x;
        vst[(c0+1)*V_STRIDE + 2*(((c0+1)>>4)&3) + r] = y.y;
        vst[(c0+2)*V_STRIDE + 2*(((c0+2)>>4)&3) + r] = y.z;
        vst[(c0+3)*V_STRIDE + 2*(((c0+3)>>4)&3) + r] = y.w;
    }
    __syncthreads();

    // normalize k rows in place; rows 0..63 also record scale = (||q||+eps)/8
    if (tid < 128) {
        float* row = ks + tid*KS_STRIDE;
        ull s2 = 0ull;
        #pragma unroll
        for (int f = 0; f < 64; f += 2) {
            ull x = ld64s(row + f);
            s2 = ffma2(x, x, s2);
        }
        float nrm = sqrtf(f32x2_sum(s2)) + 1e-6f;
        float inv = 1.0f / nrm;
        #pragma unroll
        for (int f = 0; f < 64; f++) row[f] *= inv;
        if (tid < 64) qsc[tid] = nrm * 0.125f;
    }
    __syncthreads();

    // dots[64][128]: thread (rt,ct) owns rows 4rt+a, cols ct+16*jj (f packed)
    int rt = tid >> 4;
    int ct = tid & 15;
    ull dacc2[4][8];
    #pragma unroll
    for (int a = 0; a < 4; a++)
        #pragma unroll
        for (int jj = 0; jj < 8; jj++) dacc2[a][jj] = 0ull;

    #pragma unroll 2
    for (int f = 0; f < 64; f += 2) {
        ull qv2[4];
        #pragma unroll
        for (int a = 0; a < 4; a++) qv2[a] = ld64s(ks + (4*rt + a)*KS_STRIDE + f);
        #pragma unroll
        for (int jj = 0; jj < 8; jj++) {
            ull kv2 = ld64s(ks + (ct + 16*jj)*KS_STRIDE + f);
            #pragma unroll
            for (int a = 0; a < 4; a++)
                dacc2[a][jj] = ffma2(qv2[a], kv2, dacc2[a][jj]);
        }
    }

    float dacc[4][8];
    #pragma unroll
    for (int a = 0; a < 4; a++) {
        float sc = qsc[4*rt + a];
        #pragma unroll
        for (int jj = 0; jj < 8; jj++) dacc[a][jj] = f32x2_sum(dacc2[a][jj]) * sc;
    }

    // mask (t==t' -> -5e4), per-row lse
    float lse[4];
    #pragma unroll
    for (int a = 0; a < 4; a++) {
        int r  = 4*rt + a;
        int tr = tq[r];
        float m = -1e30f;
        #pragma unroll
        for (int jj = 0; jj < 8; jj++) {
            int j = ct + 16*jj;
            float dv = (tk[j] == tr) ? NEGV : dacc[a][jj];
            dacc[a][jj] = dv;
            m = fmaxf(m, dv);
        }
        #pragma unroll
        for (int s = 1; s < 16; s <<= 1)
            m = fmaxf(m, __shfl_xor_sync(0xffffffffu, m, s));
        float sum = 0.f;
        #pragma unroll
        for (int jj = 0; jj < 8; jj++) sum += __expf(dacc[a][jj] - m);
        #pragma unroll
        for (int s = 1; s < 16; s <<= 1)
            sum += __shfl_xor_sync(0xffffffffu, sum, s);
        lse[a] = m + __logf(sum);
    }
    __syncthreads();   // all threads done reading ks before overwrite

    float* probs = ks;  // reuse (128*66 >= 64*130)
    #pragma unroll
    for (int a = 0; a < 4; a++) {
        int r = 4*rt + a;
        #pragma unroll
        for (int jj = 0; jj < 8; jj++)
            probs[r*P_STRIDE + ct + 16*jj] = __expf(dacc[a][jj] - lse[a]);
        if (ct == 0)
            g_logits[pbase + h*Ss + tq[r]] = lse[a];
    }
    __syncthreads();

    // bo = probs @ V : thread owns rows 4rt+a, cols ct+16*e; packed over j
    ull oacc2[4][4];
    #pragma unroll
    for (int a = 0; a < 4; a++)
        #pragma unroll
        for (int e = 0; e < 4; e++) oacc2[a][e] = 0ull;

    const float* vcol[4];
    #pragma unroll
    for (int e = 0; e < 4; e++)
        vcol[e] = vst + (ct + 16*e)*V_STRIDE + 2*e;   // g(ct+16e) = 2e

    #pragma unroll 2
    for (int j = 0; j < 128; j += 2) {
        ull pv2[4];
        #pragma unroll
        for (int a = 0; a < 4; a++) pv2[a] = ld64s(probs + (4*rt + a)*P_STRIDE + j);
        #pragma unroll
        for (int e = 0; e < 4; e++) {
            ull vv2 = ld64s(vcol[e] + j);
            #pragma unroll
            for (int a = 0; a < 4; a++)
                oacc2[a][e] = ffma2(pv2[a], vv2, oacc2[a][e]);
        }
    }
    #pragma unroll
    for (int a = 0; a < 4; a++) {
        int t = tq[4*rt + a];
        float* orow = g_o + ((size_t)(pbase + h*Ss + t))*Dd;
        #pragma unroll
        for (int e = 0; e < 4; e++)
            orow[ct + 16*e] = f32x2_sum(oacc2[a][e]);
    }
}

// ---------------- 4) combine hash rounds via softmax(logits) ----------------
// two float4 per thread for higher MLP
__global__ void __launch_bounds__(256) combine_kernel(float* __restrict__ out)
{
    size_t gid = (size_t)blockIdx.x*256 + threadIdx.x;
    if (gid >= (size_t)Bb*Ss*Dd/8) return;
    int pair = (int)(gid & 7);          // which pair of float4s (e = pair*8 ..)
    size_t bt = gid >> 3;
    int t = (int)(bt & (Ss - 1));
    int b = (int)(bt >> 12);

    float l[Hh];
    float m = -1e30f;
    #pragma unroll
    for (int h = 0; h < Hh; h++) {
        l[h] = g_logits[((size_t)(b*Hh + h))*Ss + t];
        m = fmaxf(m, l[h]);
    }
    float ssum = 0.f;
    #pragma unroll
    for (int h = 0; h < Hh; h++) { l[h] = __expf(l[h] - m); ssum += l[h]; }
    float inv = 1.f / ssum;

    float4 acc0 = make_float4(0.f, 0.f, 0.f, 0.f);
    float4 acc1 = make_float4(0.f, 0.f, 0.f, 0.f);
    #pragma unroll
    for (int h = 0; h < Hh; h++) {
        float w = l[h]*inv;
        const float* op = g_o + (((size_t)(b*Hh + h))*Ss + t)*Dd + pair*8;
        float4 o0 = *(const float4*)(op);
        float4 o1 = *(const float4*)(op + 4);
        acc0.x += w*o0.x; acc0.y += w*o0.y; acc0.z += w*o0.z; acc0.w += w*o0.w;
        acc1.x += w*o1.x; acc1.y += w*o1.y; acc1.z += w*o1.z; acc1.w += w*o1.w;
    }
    float* dst = out + bt*Dd + pair*8;
    *(float4*)(dst)     = acc0;
    *(float4*)(dst + 4) = acc1;
}

// ---------------- 5) buckets output (global bucket ids as float) ------------
__global__ void __launch_bounds__(256) buckets_kernel(float* __restrict__ outb)
{
    int gid = blockIdx.x*256 + threadIdx.x;
    if (gid >= Bb*Hh*Ss) return;
    int h = (gid >> 12) & 7;
    outb[gid] = (float)(g_bucket[gid] + h*NB);
}

// ---------------- launch -----------------------------------------------------
extern "C" void kernel_launch(void* const* d_in, const int* in_sizes, int n_in,
                              void* d_out, int out_size)
{
    const float* qk  = (const float*)d_in[0];
    const float* v   = (const float*)d_in[1];
    const float* rot = (const float*)d_in[2];
    float* out = (float*)d_out;

    cudaFuncSetAttribute(attn_kernel, cudaFuncAttributeMaxDynamicSharedMemorySize, ATTN_SMEM);

    hash_kernel<<<Bb*(Ss/TT), 256>>>(qk, rot);
    sort_kernel<<<Bb*Hh, 256>>>();
    attn_kernel<<<Bb*NCHUNK, 256, ATTN_SMEM>>>(qk, v);
    combine_kernel<<<(int)(((size_t)Bb*Ss*Dd/8 + 255)/256), 256>>>(out);

    if (out_size >= Bb*Ss*Dd + Bb*Hh*Ss) {
        buckets_kernel<<<(Bb*Hh*Ss + 255)/256, 256>>>(out + (size_t)Bb*Ss*Dd);
    }
}

// round 7
// speedup vs baseline: 1.1624x; 1.0001x over previous
#include <cuda_runtime.h>
#include <math.h>
#include <stdint.h>

#define Bb 16
#define Ss 4096
#define Dd 64
#define Hh 8
#define NB 64          // buckets per hash
#define NCHUNK 512     // Hh * NB
#define NEGV (-50000.0f)

typedef unsigned long long ull;

// ---------------- f32x2 packed-math helpers (sm_103a FFMA2) -----------------
__device__ __forceinline__ ull ffma2(ull a, ull b, ull c) {
    ull d;
    asm("fma.rn.f32x2 %0, %1, %2, %3;" : "=l"(d) : "l"(a), "l"(b), "l"(c));
    return d;
}
__device__ __forceinline__ ull pack2(float lo, float hi) {
    ull r;
    asm("mov.b64 %0, {%1, %2};" : "=l"(r) : "f"(lo), "f"(hi));
    return r;
}
__device__ __forceinline__ float f32x2_sum(ull v) {
    float lo, hi;
    asm("mov.b64 {%0, %1}, %2;" : "=f"(lo), "=f"(hi) : "l"(v));
    return lo + hi;
}
__device__ __forceinline__ void unpack2(ull v, float& lo, float& hi) {
    asm("mov.b64 {%0, %1}, %2;" : "=f"(lo), "=f"(hi) : "l"(v));
}
__device__ __forceinline__ ull ld64s(const float* p) {
    return *(const ull*)p;   // caller guarantees 8B alignment
}

// ---------------- device scratch (static globals: no runtime allocation) ----
__device__ int   g_bucket[Bb*Hh*Ss];     // local bucket id 0..63 per (b,h,t)
__device__ int   g_perm  [Bb*Hh*Ss];     // sorted rank -> t  (per (b,h) segment)
__device__ float g_o     [(size_t)Bb*Hh*Ss*Dd]; // per-hash outputs
__device__ float g_logits[Bb*Hh*Ss];     // per-hash lse

// ---------------- 1) LSH hashing ---------------------------------------------
// Rotation column read straight from gmem (L2-resident, 256-block reuse).
// f-sequential accumulation per token (token pairs packed) -> bit-exact argmax.
#define TT 16
#define QT_STRIDE 18
__global__ void __launch_bounds__(256) hash_kernel(
    const float* __restrict__ qk, const float* __restrict__ rot)
{
    __shared__ float qsT[64*QT_STRIDE];   // qsT[f*18 + i] = qk[t0+i][f]

    int blocksPerB = Ss / TT;                 // 256
    int b  = blockIdx.x / blocksPerB;
    int t0 = (blockIdx.x % blocksPerB) * TT;
    int tid = threadIdx.x;

    {   // transposed q tile
        int f = tid & 63;
        int i0 = tid >> 6;
        #pragma unroll
        for (int i = i0; i < TT; i += 4)
            qsT[f*QT_STRIDE + i] = qk[((size_t)b*Ss + t0 + i)*Dd + f];
    }
    __syncthreads();

    const float* rb = rot + (size_t)b*64*256 + tid;  // this thread's (h,i) column

    ull acc2[TT/2];
    #pragma unroll
    for (int ip = 0; ip < TT/2; ip++) acc2[ip] = 0ull;
    #pragma unroll 8
    for (int f = 0; f < 64; f++) {
        float rv = __ldg(rb + f*256);
        ull rv2 = pack2(rv, rv);
        #pragma unroll
        for (int ip = 0; ip < TT/2; ip++)
            acc2[ip] = ffma2(ld64s(qsT + f*QT_STRIDE + 2*ip), rv2, acc2[ip]);
    }

    int lane = tid & 31;
    int h    = tid >> 5;            // warp w handles hash w
    #pragma unroll
    for (int ip = 0; ip < TT/2; ip++) {
        float va[2];
        unpack2(acc2[ip], va[0], va[1]);
        #pragma unroll
        for (int s = 0; s < 2; s++) {
            float v = va[s];
            float val; int idx;
            if (v >= -v) { val = v;  idx = lane; }        // tie (v==0) -> first idx
            else         { val = -v; idx = lane + 32; }
            #pragma unroll
            for (int m = 16; m > 0; m >>= 1) {
                float ov = __shfl_xor_sync(0xffffffffu, val, m);
                int   oi = __shfl_xor_sync(0xffffffffu, idx, m);
                if (ov > val || (ov == val && oi < idx)) { val = ov; idx = oi; }
            }
            if (lane == 0)
                g_bucket[((size_t)b*Hh + h)*Ss + t0 + 2*ip + s] = idx;
        }
    }
}

// ---------------- 2) stable counting sort per (b,h), ballot-ranked ----------
__global__ void __launch_bounds__(256) sort_kernel()
{
    __shared__ int sb[Ss];
    __shared__ int cnt[NB];
    __shared__ int offs[NB + 1];
    int bh   = blockIdx.x;           // b*Hh + h
    int tid  = threadIdx.x;
    int lane = tid & 31;
    int w    = tid >> 5;             // warp id: owns buckets 8w..8w+7
    const int base = bh * Ss;

    if (tid < NB) cnt[tid] = 0;
    __syncthreads();
    for (int i = tid; i < Ss; i += 256) {
        int v = g_bucket[base + i];
        sb[i] = v;
        atomicAdd(&cnt[v], 1);
    }
    __syncthreads();
    if (tid == 0) {
        offs[0] = 0;
        for (int k = 0; k < NB; k++) offs[k+1] = offs[k] + cnt[k];
    }
    __syncthreads();

    int off[8];
    #pragma unroll
    for (int k = 0; k < 8; k++) off[k] = offs[8*w + k];

    for (int step = 0; step < Ss/32; step++) {
        int t   = step*32 + lane;
        int rel = sb[t] - 8*w;       // 0..7 if this warp owns the bucket
        #pragma unroll
        for (int k = 0; k < 8; k++) {
            unsigned mask = __ballot_sync(0xffffffffu, rel == k);
            if (rel == k) {
                int pos = off[k] + __popc(mask & ((1u << lane) - 1u));
                g_perm[base + pos] = t;
            }
            off[k] += __popc(mask);
        }
    }
}

// ---------------- 3) chunked attention + scatter -----------------------------
// bq == raw K rows 0..63: keep only normalized K and per-q-row scale
// s_r = (||q_r||+eps)*0.125:  dots = s_r * (q_hat . k_hat)
#define KS_STRIDE 66
#define P_STRIDE 130
#define V_STRIDE 134
#define ATTN_SMEM ((128*KS_STRIDE + 64*V_STRIDE + 64) * 4 + 192 * 4)
__global__ void __launch_bounds__(256, 2) attn_kernel(
    const float* __restrict__ qk, const float* __restrict__ v)
{
    extern __shared__ float sm[];
    float* ks  = sm;                          // [128][66] normalized k; reused as probs[64][130]
    float* vst = ks + 128*KS_STRIDE;          // transposed V: [64 cols][134] (+ per-col offset)
    float* qsc = vst + 64*V_STRIDE;           // [64] per-q-row scale
    int*   tq  = (int*)(qsc + 64);            // [64]
    int*   tk  = tq + 64;                     // [128]

    int b = blockIdx.x >> 9;
    int c = blockIdx.x & (NCHUNK - 1);
    int h = c >> 6;
    int cprev = (c + NCHUNK - 1) & (NCHUNK - 1);
    int tid = threadIdx.x;
    const int pbase = b * (Hh * Ss);

    if (tid < 64) {
        int val = g_perm[pbase + c*64 + tid];
        tq[tid] = val;
        tk[tid] = val;
    } else if (tid < 128) {
        tk[tid] = g_perm[pbase + cprev*64 + (tid - 64)];
    }
    __syncthreads();

    const float* qkb = qk + (size_t)b*Ss*Dd;
    const float* vb  = v  + (size_t)b*Ss*Dd;

    for (int idx = tid; idx < 128*16; idx += 256) {
        int r = idx >> 4, q4 = idx & 15;
        float4 x = *(const float4*)(qkb + (size_t)tk[r]*Dd + q4*4);
        float* d = ks + r*KS_STRIDE + q4*4;
        d[0]=x.x; d[1]=x.y; d[2]=x.z; d[3]=x.w;
        // V transposed: element (row j=r, col c) -> vst[c*134 + g(c) + r]
        float4 y = *(const float4*)(vb + (size_t)tk[r]*Dd + q4*4);
        int c0 = q4*4;
        vst[(c0+0)*V_STRIDE + 2*(((c0+0)>>4)&3) + r] = y.x;
        vst[(c0+1)*V_STRIDE + 2*(((c0+1)>>4)&3) + r] = y.y;
        vst[(c0+2)*V_STRIDE + 2*(((c0+2)>>4)&3) + r] = y.z;
        vst[(c0+3)*V_STRIDE + 2*(((c0+3)>>4)&3) + r] = y.w;
    }
    __syncthreads();

    // normalize k rows in place; rows 0..63 also record scale = (||q||+eps)/8
    if (tid < 128) {
        float* row = ks + tid*KS_STRIDE;
        ull s2 = 0ull;
        #pragma unroll
        for (int f = 0; f < 64; f += 2) {
            ull x = ld64s(row + f);
            s2 = ffma2(x, x, s2);
        }
        float nrm = sqrtf(f32x2_sum(s2)) + 1e-6f;
        float inv = 1.0f / nrm;
        #pragma unroll
        for (int f = 0; f < 64; f++) row[f] *= inv;
        if (tid < 64) qsc[tid] = nrm * 0.125f;
    }
    __syncthreads();

    // dots[64][128]: thread (rt,ct) owns rows 4rt+a, cols ct+16*jj (f packed)
    int rt = tid >> 4;
    int ct = tid & 15;
    ull dacc2[4][8];
    #pragma unroll
    for (int a = 0; a < 4; a++)
        #pragma unroll
        for (int jj = 0; jj < 8; jj++) dacc2[a][jj] = 0ull;

    #pragma unroll 2
    for (int f = 0; f < 64; f += 2) {
        ull qv2[4];
        #pragma unroll
        for (int a = 0; a < 4; a++) qv2[a] = ld64s(ks + (4*rt + a)*KS_STRIDE + f);
        #pragma unroll
        for (int jj = 0; jj < 8; jj++) {
            ull kv2 = ld64s(ks + (ct + 16*jj)*KS_STRIDE + f);
            #pragma unroll
            for (int a = 0; a < 4; a++)
                dacc2[a][jj] = ffma2(qv2[a], kv2, dacc2[a][jj]);
        }
    }

    float dacc[4][8];
    #pragma unroll
    for (int a = 0; a < 4; a++) {
        float sc = qsc[4*rt + a];
        #pragma unroll
        for (int jj = 0; jj < 8; jj++) dacc[a][jj] = f32x2_sum(dacc2[a][jj]) * sc;
    }

    // mask (t==t' -> -5e4), per-row lse
    float lse[4];
    #pragma unroll
    for (int a = 0; a < 4; a++) {
        int r  = 4*rt + a;
        int tr = tq[r];
        float m = -1e30f;
        #pragma unroll
        for (int jj = 0; jj < 8; jj++) {
            int j = ct + 16*jj;
            float dv = (tk[j] == tr) ? NEGV : dacc[a][jj];
            dacc[a][jj] = dv;
            m = fmaxf(m, dv);
        }
        #pragma unroll
        for (int s = 1; s < 16; s <<= 1)
            m = fmaxf(m, __shfl_xor_sync(0xffffffffu, m, s));
        float sum = 0.f;
        #pragma unroll
        for (int jj = 0; jj < 8; jj++) sum += __expf(dacc[a][jj] - m);
        #pragma unroll
        for (int s = 1; s < 16; s <<= 1)
            sum += __shfl_xor_sync(0xffffffffu, sum, s);
        lse[a] = m + __logf(sum);
    }
    __syncthreads();   // all threads done reading ks before overwrite

    float* probs = ks;  // reuse (128*66 >= 64*130)
    #pragma unroll
    for (int a = 0; a < 4; a++) {
        int r = 4*rt + a;
        #pragma unroll
        for (int jj = 0; jj < 8; jj++)
            probs[r*P_STRIDE + ct + 16*jj] = __expf(dacc[a][jj] - lse[a]);
        if (ct == 0)
            g_logits[pbase + h*Ss + tq[r]] = lse[a];
    }
    __syncthreads();

    // bo = probs @ V : thread owns rows 4rt+a, cols ct+16*e; packed over j
    ull oacc2[4][4];
    #pragma unroll
    for (int a = 0; a < 4; a++)
        #pragma unroll
        for (int e = 0; e < 4; e++) oacc2[a][e] = 0ull;

    const float* vcol[4];
    #pragma unroll
    for (int e = 0; e < 4; e++)
        vcol[e] = vst + (ct + 16*e)*V_STRIDE + 2*e;   // g(ct+16e) = 2e

    #pragma unroll 2
    for (int j = 0; j < 128; j += 2) {
        ull pv2[4];
        #pragma unroll
        for (int a = 0; a < 4; a++) pv2[a] = ld64s(probs + (4*rt + a)*P_STRIDE + j);
        #pragma unroll
        for (int e = 0; e < 4; e++) {
            ull vv2 = ld64s(vcol[e] + j);
            #pragma unroll
            for (int a = 0; a < 4; a++)
                oacc2[a][e] = ffma2(pv2[a], vv2, oacc2[a][e]);
        }
    }
    #pragma unroll
    for (int a = 0; a < 4; a++) {
        int t = tq[4*rt + a];
        float* orow = g_o + ((size_t)(pbase + h*Ss + t))*Dd;
        #pragma unroll
        for (int e = 0; e < 4; e++)
            orow[ct + 16*e] = f32x2_sum(oacc2[a][e]);
    }
}

// ---------------- 4) combine hash rounds via softmax(logits) ----------------
// two float4 per thread for higher MLP
__global__ void __launch_bounds__(256) combine_kernel(float* __restrict__ out)
{
    size_t gid = (size_t)blockIdx.x*256 + threadIdx.x;
    if (gid >= (size_t)Bb*Ss*Dd/8) return;
    int pair = (int)(gid & 7);          // which pair of float4s (e = pair*8 ..)
    size_t bt = gid >> 3;
    int t = (int)(bt & (Ss - 1));
    int b = (int)(bt >> 12);

    float l[Hh];
    float m = -1e30f;
    #pragma unroll
    for (int h = 0; h < Hh; h++) {
        l[h] = g_logits[((size_t)(b*Hh + h))*Ss + t];
        m = fmaxf(m, l[h]);
    }
    float ssum = 0.f;
    #pragma unroll
    for (int h = 0; h < Hh; h++) { l[h] = __expf(l[h] - m); ssum += l[h]; }
    float inv = 1.f / ssum;

    float4 acc0 = make_float4(0.f, 0.f, 0.f, 0.f);
    float4 acc1 = make_float4(0.f, 0.f, 0.f, 0.f);
    #pragma unroll
    for (int h = 0; h < Hh; h++) {
        float w = l[h]*inv;
        const float* op = g_o + (((size_t)(b*Hh + h))*Ss + t)*Dd + pair*8;
        float4 o0 = *(const float4*)(op);
        float4 o1 = *(const float4*)(op + 4);
        acc0.x += w*o0.x; acc0.y += w*o0.y; acc0.z += w*o0.z; acc0.w += w*o0.w;
        acc1.x += w*o1.x; acc1.y += w*o1.y; acc1.z += w*o1.z; acc1.w += w*o1.w;
    }
    float* dst = out + bt*Dd + pair*8;
    *(float4*)(dst)     = acc0;
    *(float4*)(dst + 4) = acc1;
}

// ---------------- 5) buckets output (global bucket ids as float) ------------
__global__ void __launch_bounds__(256) buckets_kernel(float* __restrict__ outb)
{
    int gid = blockIdx.x*256 + threadIdx.x;
    if (gid >= Bb*Hh*Ss) return;
    int h = (gid >> 12) & 7;
    outb[gid] = (float)(g_bucket[gid] + h*NB);
}

// ---------------- launch -----------------------------------------------------
extern "C" void kernel_launch(void* const* d_in, const int* in_sizes, int n_in,
                              void* d_out, int out_size)
{
    const float* qk  = (const float*)d_in[0];
    const float* v   = (const float*)d_in[1];
    const float* rot = (const float*)d_in[2];
    float* out = (float*)d_out;

    cudaFuncSetAttribute(attn_kernel, cudaFuncAttributeMaxDynamicSharedMemorySize, ATTN_SMEM);

    hash_kernel<<<Bb*(Ss/TT), 256>>>(qk, rot);
    sort_kernel<<<Bb*Hh, 256>>>();
    attn_kernel<<<Bb*NCHUNK, 256, ATTN_SMEM>>>(qk, v);
    combine_kernel<<<(int)(((size_t)Bb*Ss*Dd/8 + 255)/256), 256>>>(out);

    if (out_size >= Bb*Ss*Dd + Bb*Hh*Ss) {
        buckets_kernel<<<(Bb*Hh*Ss + 255)/256, 256>>>(out + (size_t)Bb*Ss*Dd);
    }
}

// round 8
// speedup vs baseline: 1.6109x; 1.3858x over previous
#include <cuda_runtime.h>
#include <math.h>
#include <stdint.h>

#define Bb 16
#define Ss 4096
#define Dd 64
#define Hh 8
#define NB 64          // buckets per hash
#define NCHUNK 512     // Hh * NB
#define NEGV (-50000.0f)

typedef unsigned long long ull;
typedef unsigned int uint;

// ---------------- f32x2 packed-math helpers (sm_103a) -----------------------
__device__ __forceinline__ ull ffma2(ull a, ull b, ull c) {
    ull d;
    asm("fma.rn.f32x2 %0, %1, %2, %3;" : "=l"(d) : "l"(a), "l"(b), "l"(c));
    return d;
}
__device__ __forceinline__ ull pack2(float lo, float hi) {
    ull r;
    asm("mov.b64 %0, {%1, %2};" : "=l"(r) : "f"(lo), "f"(hi));
    return r;
}
__device__ __forceinline__ float f32x2_sum(ull v) {
    float lo, hi;
    asm("mov.b64 {%0, %1}, %2;" : "=f"(lo), "=f"(hi) : "l"(v));
    return lo + hi;
}
__device__ __forceinline__ void unpack2(ull v, float& lo, float& hi) {
    asm("mov.b64 {%0, %1}, %2;" : "=f"(lo), "=f"(hi) : "l"(v));
}
__device__ __forceinline__ ull ld64s(const float* p) {
    return *(const ull*)p;
}

// ---------------- tf32 mma helpers -------------------------------------------
__device__ __forceinline__ uint cvt_tf32(float x) {
    uint r;
    asm("cvt.rna.tf32.f32 %0, %1;" : "=r"(r) : "f"(x));
    return r;
}
__device__ __forceinline__ void mma_tf32(float* c,
    uint a0, uint a1, uint a2, uint a3, uint b0, uint b1)
{
    asm("mma.sync.aligned.m16n8k8.row.col.f32.tf32.tf32.f32 "
        "{%0,%1,%2,%3}, {%4,%5,%6,%7}, {%8,%9}, {%0,%1,%2,%3};"
        : "+f"(c[0]), "+f"(c[1]), "+f"(c[2]), "+f"(c[3])
        : "r"(a0), "r"(a1), "r"(a2), "r"(a3), "r"(b0), "r"(b1));
}
__device__ __forceinline__ uint ldu(const float* p) { return __float_as_uint(*p); }

// ---------------- device scratch ---------------------------------------------
__device__ int   g_bucket[Bb*Hh*Ss];
__device__ int   g_perm  [Bb*Hh*Ss];
__device__ float g_o     [(size_t)Bb*Hh*Ss*Dd];
__device__ float g_logits[Bb*Hh*Ss];

// ---------------- 1) LSH hashing (bit-exact f-sequential accumulation) -------
#define TT 16
#define QT_STRIDE 18
__global__ void __launch_bounds__(256) hash_kernel(
    const float* __restrict__ qk, const float* __restrict__ rot)
{
    __shared__ float qsT[64*QT_STRIDE];

    int blocksPerB = Ss / TT;
    int b  = blockIdx.x / blocksPerB;
    int t0 = (blockIdx.x % blocksPerB) * TT;
    int tid = threadIdx.x;

    {
        int f = tid & 63;
        int i0 = tid >> 6;
        #pragma unroll
        for (int i = i0; i < TT; i += 4)
            qsT[f*QT_STRIDE + i] = qk[((size_t)b*Ss + t0 + i)*Dd + f];
    }
    __syncthreads();

    const float* rb = rot + (size_t)b*64*256 + tid;

    ull acc2[TT/2];
    #pragma unroll
    for (int ip = 0; ip < TT/2; ip++) acc2[ip] = 0ull;
    #pragma unroll 8
    for (int f = 0; f < 64; f++) {
        float rv = __ldg(rb + f*256);
        ull rv2 = pack2(rv, rv);
        #pragma unroll
        for (int ip = 0; ip < TT/2; ip++)
            acc2[ip] = ffma2(ld64s(qsT + f*QT_STRIDE + 2*ip), rv2, acc2[ip]);
    }

    int lane = tid & 31;
    int h    = tid >> 5;
    #pragma unroll
    for (int ip = 0; ip < TT/2; ip++) {
        float va[2];
        unpack2(acc2[ip], va[0], va[1]);
        #pragma unroll
        for (int s = 0; s < 2; s++) {
            float v = va[s];
            float val; int idx;
            if (v >= -v) { val = v;  idx = lane; }
            else         { val = -v; idx = lane + 32; }
            #pragma unroll
            for (int m = 16; m > 0; m >>= 1) {
                float ov = __shfl_xor_sync(0xffffffffu, val, m);
                int   oi = __shfl_xor_sync(0xffffffffu, idx, m);
                if (ov > val || (ov == val && oi < idx)) { val = ov; idx = oi; }
            }
            if (lane == 0)
                g_bucket[((size_t)b*Hh + h)*Ss + t0 + 2*ip + s] = idx;
        }
    }
}

// ---------------- 2) stable counting sort per (b,h), ballot-ranked ----------
__global__ void __launch_bounds__(256) sort_kernel()
{
    __shared__ int sb[Ss];
    __shared__ int cnt[NB];
    __shared__ int offs[NB + 1];
    int bh   = blockIdx.x;
    int tid  = threadIdx.x;
    int lane = tid & 31;
    int w    = tid >> 5;
    const int base = bh * Ss;

    if (tid < NB) cnt[tid] = 0;
    __syncthreads();
    for (int i = tid; i < Ss; i += 256) {
        int v = g_bucket[base + i];
        sb[i] = v;
        atomicAdd(&cnt[v], 1);
    }
    __syncthreads();
    if (tid == 0) {
        offs[0] = 0;
        for (int k = 0; k < NB; k++) offs[k+1] = offs[k] + cnt[k];
    }
    __syncthreads();

    int off[8];
    #pragma unroll
    for (int k = 0; k < 8; k++) off[k] = offs[8*w + k];

    for (int step = 0; step < Ss/32; step++) {
        int t   = step*32 + lane;
        int rel = sb[t] - 8*w;
        #pragma unroll
        for (int k = 0; k < 8; k++) {
            unsigned mask = __ballot_sync(0xffffffffu, rel == k);
            if (rel == k) {
                int pos = off[k] + __popc(mask & ((1u << lane) - 1u));
                g_perm[base + pos] = t;
            }
            off[k] += __popc(mask);
        }
    }
}

// ---------------- 3) chunked attention via tf32 mma.sync --------------------
// ks[128][68]  : normalized K (tf32 bit patterns); rows 0..63 double as Q
// probs[64][132] overlays ks after the QK phase
// vsm[128][72] : V rows (fp32; split to tf32 hi/lo at fragment load)
#define KS_LD 68
#define P_LD 132
#define V_LD 72
#define SM_KS   0
#define SM_VS   (128*KS_LD)                 // 8704
#define SM_PM   (SM_VS + 128*V_LD)          // +9216 = 17920
#define SM_PS   (SM_PM + 128)
#define SM_QSC  (SM_PS + 128)
#define SM_TK   (SM_QSC + 64)
#define ATTN_SMEM ((SM_TK + 128) * 4)       // 73472 bytes
__global__ void __launch_bounds__(256, 3) attn_kernel(
    const float* __restrict__ qk, const float* __restrict__ v)
{
    extern __shared__ float sm[];
    float* ks    = sm + SM_KS;
    float* vsm   = sm + SM_VS;
    float* pm    = sm + SM_PM;     // [2][64] partial max
    float* ps    = sm + SM_PS;     // [2][64] partial sumexp
    float* qsc   = sm + SM_QSC;    // [64] row scale
    int*   tk    = (int*)(sm + SM_TK);   // [128]
    float* probs = ks;             // overlay

    int b = blockIdx.x >> 9;
    int c = blockIdx.x & (NCHUNK - 1);
    int h = c >> 6;
    int cprev = (c + NCHUNK - 1) & (NCHUNK - 1);
    int tid = threadIdx.x;
    const int pbase = b * (Hh * Ss);

    if (tid < 64)        tk[tid] = g_perm[pbase + c*64 + tid];
    else if (tid < 128)  tk[tid] = g_perm[pbase + cprev*64 + (tid - 64)];
    __syncthreads();

    const float* qkb = qk + (size_t)b*Ss*Dd;
    const float* vb  = v  + (size_t)b*Ss*Dd;

    // gather q/k and v rows (row-major, padded)
    for (int idx = tid; idx < 128*16; idx += 256) {
        int r = idx >> 4, q4 = idx & 15;
        int t = tk[r];
        float4 x = *(const float4*)(qkb + (size_t)t*Dd + q4*4);
        *(float4*)(ks + r*KS_LD + q4*4) = x;
        float4 y = *(const float4*)(vb + (size_t)t*Dd + q4*4);
        *(float4*)(vsm + r*V_LD + q4*4) = y;
    }
    __syncthreads();

    // normalize rows in place -> tf32 bit patterns; rows<64 record scale
    if (tid < 128) {
        float* row = ks + tid*KS_LD;
        ull s2 = 0ull;
        #pragma unroll
        for (int f = 0; f < 64; f += 2) {
            ull x = ld64s(row + f);
            s2 = ffma2(x, x, s2);
        }
        float nrm = sqrtf(f32x2_sum(s2)) + 1e-6f;
        float inv = 1.0f / nrm;
        #pragma unroll
        for (int f = 0; f < 64; f++)
            row[f] = __uint_as_float(cvt_tf32(row[f] * inv));
        if (tid < 64) qsc[tid] = nrm * 0.125f;
    }
    __syncthreads();

    // ---- QK^T : 64x128x64, per warp m16 x n64 ----
    int wid   = tid >> 5;
    int lane  = tid & 31;
    int gr    = lane >> 2;       // group row 0..7
    int cl    = lane & 3;        // thread-in-group 0..3
    int mrow  = 16*(wid & 3);
    int chalf = wid >> 2;        // column half 0/1
    int ncol  = 64*chalf;

    float acc[8][4];
    #pragma unroll
    for (int n = 0; n < 8; n++)
        #pragma unroll
        for (int i = 0; i < 4; i++) acc[n][i] = 0.f;

    #pragma unroll 2
    for (int k0 = 0; k0 < 8; k0++) {
        const float* ab = ks + (mrow + gr)*KS_LD + 8*k0 + cl;
        uint a0 = ldu(ab), a1 = ldu(ab + 8*KS_LD), a2 = ldu(ab + 4), a3 = ldu(ab + 8*KS_LD + 4);
        #pragma unroll
        for (int n = 0; n < 8; n++) {
            const float* bbp = ks + (ncol + 8*n + gr)*KS_LD + 8*k0 + cl;
            uint b0 = ldu(bbp), b1 = ldu(bbp + 4);
            mma_tf32(acc[n], a0, a1, a2, a3, b0, b1);
        }
    }

    // ---- mask + scale + per-half softmax partials ----
    int row0 = mrow + gr, row1 = row0 + 8;
    int tr0 = tk[row0], tr1 = tk[row1];
    float sc0 = qsc[row0], sc1 = qsc[row1];
    float m0 = -1e30f, m1 = -1e30f;
    #pragma unroll
    for (int n = 0; n < 8; n++) {
        int j0 = ncol + 8*n + 2*cl;
        int tj0 = tk[j0], tj1 = tk[j0 + 1];
        float d0 = (tj0 == tr0) ? NEGV : acc[n][0]*sc0;
        float d1 = (tj1 == tr0) ? NEGV : acc[n][1]*sc0;
        float d2 = (tj0 == tr1) ? NEGV : acc[n][2]*sc1;
        float d3 = (tj1 == tr1) ? NEGV : acc[n][3]*sc1;
        acc[n][0] = d0; acc[n][1] = d1; acc[n][2] = d2; acc[n][3] = d3;
        m0 = fmaxf(m0, fmaxf(d0, d1));
        m1 = fmaxf(m1, fmaxf(d2, d3));
    }
    #pragma unroll
    for (int s = 1; s < 4; s <<= 1) {
        m0 = fmaxf(m0, __shfl_xor_sync(0xffffffffu, m0, s));
        m1 = fmaxf(m1, __shfl_xor_sync(0xffffffffu, m1, s));
    }
    float s0 = 0.f, s1 = 0.f;
    #pragma unroll
    for (int n = 0; n < 8; n++) {
        s0 += __expf(acc[n][0] - m0) + __expf(acc[n][1] - m0);
        s1 += __expf(acc[n][2] - m1) + __expf(acc[n][3] - m1);
    }
    #pragma unroll
    for (int s = 1; s < 4; s <<= 1) {
        s0 += __shfl_xor_sync(0xffffffffu, s0, s);
        s1 += __shfl_xor_sync(0xffffffffu, s1, s);
    }
    if (cl == 0) {
        pm[chalf*64 + row0] = m0;  ps[chalf*64 + row0] = s0;
        pm[chalf*64 + row1] = m1;  ps[chalf*64 + row1] = s1;
    }
    __syncthreads();   // partials visible; ALL warps done reading ks

    // global lse per row (both halves)
    float Ma0 = pm[row0], Mb0 = pm[64 + row0];
    float M0  = fmaxf(Ma0, Mb0);
    float S0  = ps[row0]*__expf(Ma0 - M0) + ps[64 + row0]*__expf(Mb0 - M0);
    float lse0 = M0 + __logf(S0);
    float Ma1 = pm[row1], Mb1 = pm[64 + row1];
    float M1  = fmaxf(Ma1, Mb1);
    float S1  = ps[row1]*__expf(Ma1 - M1) + ps[64 + row1]*__expf(Mb1 - M1);
    float lse1 = M1 + __logf(S1);

    if (cl == 0 && chalf == 0) {
        g_logits[pbase + h*Ss + tr0] = lse0;
        g_logits[pbase + h*Ss + tr1] = lse1;
    }

    // probs = exp(d - lse) -> smem (overlays ks)
    #pragma unroll
    for (int n = 0; n < 8; n++) {
        int j0 = ncol + 8*n + 2*cl;
        float2 p0 = make_float2(__expf(acc[n][0] - lse0), __expf(acc[n][1] - lse0));
        float2 p1 = make_float2(__expf(acc[n][2] - lse1), __expf(acc[n][3] - lse1));
        *(float2*)(probs + row0*P_LD + j0) = p0;
        *(float2*)(probs + row1*P_LD + j0) = p1;
    }
    __syncthreads();

    // ---- PV : 64x64x128, tf32 x3, per warp m16 x n32 ----
    int ocol = 32*chalf;
    float oacc[4][4];
    #pragma unroll
    for (int n = 0; n < 4; n++)
        #pragma unroll
        for (int i = 0; i < 4; i++) oacc[n][i] = 0.f;

    #pragma unroll 1
    for (int k0 = 0; k0 < 16; k0++) {
        const float* pb = probs + (mrow + gr)*P_LD + 8*k0 + cl;
        float pa0 = pb[0], pa1 = pb[8*P_LD], pa2 = pb[4], pa3 = pb[8*P_LD + 4];
        uint ah0 = cvt_tf32(pa0), ah1 = cvt_tf32(pa1), ah2 = cvt_tf32(pa2), ah3 = cvt_tf32(pa3);
        uint al0 = cvt_tf32(pa0 - __uint_as_float(ah0));
        uint al1 = cvt_tf32(pa1 - __uint_as_float(ah1));
        uint al2 = cvt_tf32(pa2 - __uint_as_float(ah2));
        uint al3 = cvt_tf32(pa3 - __uint_as_float(ah3));
        #pragma unroll
        for (int n = 0; n < 4; n++) {
            const float* vbp = vsm + (8*k0 + cl)*V_LD + ocol + 8*n + gr;
            float v0 = vbp[0], v1 = vbp[4*V_LD];
            uint bh0 = cvt_tf32(v0), bh1 = cvt_tf32(v1);
            uint bl0 = cvt_tf32(v0 - __uint_as_float(bh0));
            uint bl1 = cvt_tf32(v1 - __uint_as_float(bh1));
            mma_tf32(oacc[n], ah0, ah1, ah2, ah3, bh0, bh1);
            mma_tf32(oacc[n], ah0, ah1, ah2, ah3, bl0, bl1);
            mma_tf32(oacc[n], al0, al1, al2, al3, bh0, bh1);
        }
    }

    // ---- scatter to g_o ----
    {
        float* orow0 = g_o + ((size_t)(pbase + h*Ss + tr0))*Dd;
        float* orow1 = g_o + ((size_t)(pbase + h*Ss + tr1))*Dd;
        #pragma unroll
        for (int n = 0; n < 4; n++) {
            int col = ocol + 8*n + 2*cl;
            *(float2*)(orow0 + col) = make_float2(oacc[n][0], oacc[n][1]);
            *(float2*)(orow1 + col) = make_float2(oacc[n][2], oacc[n][3]);
        }
    }
}

// ---------------- 4) combine hash rounds via softmax(logits) ----------------
__global__ void __launch_bounds__(256) combine_kernel(float* __restrict__ out)
{
    size_t gid = (size_t)blockIdx.x*256 + threadIdx.x;
    if (gid >= (size_t)Bb*Ss*Dd/8) return;
    int pair = (int)(gid & 7);
    size_t bt = gid >> 3;
    int t = (int)(bt & (Ss - 1));
    int b = (int)(bt >> 12);

    float l[Hh];
    float m = -1e30f;
    #pragma unroll
    for (int h = 0; h < Hh; h++) {
        l[h] = g_logits[((size_t)(b*Hh + h))*Ss + t];
        m = fmaxf(m, l[h]);
    }
    float ssum = 0.f;
    #pragma unroll
    for (int h = 0; h < Hh; h++) { l[h] = __expf(l[h] - m); ssum += l[h]; }
    float inv = 1.f / ssum;

    float4 acc0 = make_float4(0.f, 0.f, 0.f, 0.f);
    float4 acc1 = make_float4(0.f, 0.f, 0.f, 0.f);
    #pragma unroll
    for (int h = 0; h < Hh; h++) {
        float w = l[h]*inv;
        const float* op = g_o + (((size_t)(b*Hh + h))*Ss + t)*Dd + pair*8;
        float4 o0 = *(const float4*)(op);
        float4 o1 = *(const float4*)(op + 4);
        acc0.x += w*o0.x; acc0.y += w*o0.y; acc0.z += w*o0.z; acc0.w += w*o0.w;
        acc1.x += w*o1.x; acc1.y += w*o1.y; acc1.z += w*o1.z; acc1.w += w*o1.w;
    }
    float* dst = out + bt*Dd + pair*8;
    *(float4*)(dst)     = acc0;
    *(float4*)(dst + 4) = acc1;
}

// ---------------- 5) buckets output ------------------------------------------
__global__ void __launch_bounds__(256) buckets_kernel(float* __restrict__ outb)
{
    int gid = blockIdx.x*256 + threadIdx.x;
    if (gid >= Bb*Hh*Ss) return;
    int h = (gid >> 12) & 7;
    outb[gid] = (float)(g_bucket[gid] + h*NB);
}

// ---------------- launch ------------------------------------------------------
extern "C" void kernel_launch(void* const* d_in, const int* in_sizes, int n_in,
                              void* d_out, int out_size)
{
    const float* qk  = (const float*)d_in[0];
    const float* v   = (const float*)d_in[1];
    const float* rot = (const float*)d_in[2];
    float* out = (float*)d_out;

    cudaFuncSetAttribute(attn_kernel, cudaFuncAttributeMaxDynamicSharedMemorySize, ATTN_SMEM);

    hash_kernel<<<Bb*(Ss/TT), 256>>>(qk, rot);
    sort_kernel<<<Bb*Hh, 256>>>();
    attn_kernel<<<Bb*NCHUNK, 256, ATTN_SMEM>>>(qk, v);
    combine_kernel<<<(int)(((size_t)Bb*Ss*Dd/8 + 255)/256), 256>>>(out);

    if (out_size >= Bb*Ss*Dd + Bb*Hh*Ss) {
        buckets_kernel<<<(Bb*Hh*Ss + 255)/256, 256>>>(out + (size_t)Bb*Ss*Dd);
    }
}

// round 10
// speedup vs baseline: 1.9229x; 1.1937x over previous
#include <cuda_runtime.h>
#include <cuda_bf16.h>
#include <math.h>
#include <stdint.h>

#define Bb 16
#define Ss 4096
#define Dd 64
#define Hh 8
#define NB 64          // buckets per hash
#define NCHUNK 512     // Hh * NB
#define NEGV (-50000.0f)

typedef unsigned long long ull;
typedef unsigned int uint;

// ---------------- f32x2 packed-math helpers (sm_103a) -----------------------
__device__ __forceinline__ ull ffma2(ull a, ull b, ull c) {
    ull d;
    asm("fma.rn.f32x2 %0, %1, %2, %3;" : "=l"(d) : "l"(a), "l"(b), "l"(c));
    return d;
}
__device__ __forceinline__ ull pack2(float lo, float hi) {
    ull r;
    asm("mov.b64 %0, {%1, %2};" : "=l"(r) : "f"(lo), "f"(hi));
    return r;
}
__device__ __forceinline__ float f32x2_sum(ull v) {
    float lo, hi;
    asm("mov.b64 {%0, %1}, %2;" : "=f"(lo), "=f"(hi) : "l"(v));
    return lo + hi;
}
__device__ __forceinline__ void unpack2(ull v, float& lo, float& hi) {
    asm("mov.b64 {%0, %1}, %2;" : "=f"(lo), "=f"(hi) : "l"(v));
}
__device__ __forceinline__ ull ld64s(const float* p) {
    return *(const ull*)p;
}

// ---------------- mma helpers -------------------------------------------------
__device__ __forceinline__ uint cvt_tf32(float x) {
    uint r;
    asm("cvt.rna.tf32.f32 %0, %1;" : "=r"(r) : "f"(x));
    return r;
}
__device__ __forceinline__ void mma_tf32(float* c,
    uint a0, uint a1, uint a2, uint a3, uint b0, uint b1)
{
    asm("mma.sync.aligned.m16n8k8.row.col.f32.tf32.tf32.f32 "
        "{%0,%1,%2,%3}, {%4,%5,%6,%7}, {%8,%9}, {%0,%1,%2,%3};"
        : "+f"(c[0]), "+f"(c[1]), "+f"(c[2]), "+f"(c[3])
        : "r"(a0), "r"(a1), "r"(a2), "r"(a3), "r"(b0), "r"(b1));
}
__device__ __forceinline__ void mma_bf16(float* c,
    uint a0, uint a1, uint a2, uint a3, uint b0, uint b1)
{
    asm("mma.sync.aligned.m16n8k16.row.col.f32.bf16.bf16.f32 "
        "{%0,%1,%2,%3}, {%4,%5,%6,%7}, {%8,%9}, {%0,%1,%2,%3};"
        : "+f"(c[0]), "+f"(c[1]), "+f"(c[2]), "+f"(c[3])
        : "r"(a0), "r"(a1), "r"(a2), "r"(a3), "r"(b0), "r"(b1));
}
__device__ __forceinline__ uint ldu(const float* p) { return __float_as_uint(*p); }
// pack two f32 -> bf16x2 word: lower half = 'lo' (even k), upper half = 'hi'
__device__ __forceinline__ uint pack_bf16x2(float lo, float hi) {
    uint r;
    asm("cvt.rn.bf16x2.f32 %0, %1, %2;" : "=r"(r) : "f"(hi), "f"(lo));
    return r;
}
__device__ __forceinline__ float bf_lo_f32(uint w) { return __uint_as_float(w << 16); }
__device__ __forceinline__ float bf_hi_f32(uint w) { return __uint_as_float(w & 0xffff0000u); }

// ---------------- device scratch ---------------------------------------------
__device__ int   g_bucket[Bb*Hh*Ss];
__device__ int   g_perm  [Bb*Hh*Ss];
__device__ float g_o     [(size_t)Bb*Hh*Ss*Dd];
__device__ float g_logits[Bb*Hh*Ss];

// ---------------- 1) LSH hashing (bit-exact f-sequential accumulation) -------
#define TT 16
#define QT_STRIDE 18
__global__ void __launch_bounds__(256) hash_kernel(
    const float* __restrict__ qk, const float* __restrict__ rot)
{
    __shared__ float qsT[64*QT_STRIDE];

    int blocksPerB = Ss / TT;
    int b  = blockIdx.x / blocksPerB;
    int t0 = (blockIdx.x % blocksPerB) * TT;
    int tid = threadIdx.x;

    {
        int f = tid & 63;
        int i0 = tid >> 6;
        #pragma unroll
        for (int i = i0; i < TT; i += 4)
            qsT[f*QT_STRIDE + i] = qk[((size_t)b*Ss + t0 + i)*Dd + f];
    }
    __syncthreads();

    const float* rb = rot + (size_t)b*64*256 + tid;

    ull acc2[TT/2];
    #pragma unroll
    for (int ip = 0; ip < TT/2; ip++) acc2[ip] = 0ull;
    #pragma unroll 8
    for (int f = 0; f < 64; f++) {
        float rv = __ldg(rb + f*256);
        ull rv2 = pack2(rv, rv);
        #pragma unroll
        for (int ip = 0; ip < TT/2; ip++)
            acc2[ip] = ffma2(ld64s(qsT + f*QT_STRIDE + 2*ip), rv2, acc2[ip]);
    }

    int lane = tid & 31;
    int h    = tid >> 5;
    #pragma unroll
    for (int ip = 0; ip < TT/2; ip++) {
        float va[2];
        unpack2(acc2[ip], va[0], va[1]);
        #pragma unroll
        for (int s = 0; s < 2; s++) {
            float v = va[s];
            float val; int idx;
            if (v >= -v) { val = v;  idx = lane; }
            else         { val = -v; idx = lane + 32; }
            #pragma unroll
            for (int m = 16; m > 0; m >>= 1) {
                float ov = __shfl_xor_sync(0xffffffffu, val, m);
                int   oi = __shfl_xor_sync(0xffffffffu, idx, m);
                if (ov > val || (ov == val && oi < idx)) { val = ov; idx = oi; }
            }
            if (lane == 0)
                g_bucket[((size_t)b*Hh + h)*Ss + t0 + 2*ip + s] = idx;
        }
    }
}

// ---------------- 2) stable counting sort per (b,h), ballot-ranked ----------
__global__ void __launch_bounds__(256) sort_kernel()
{
    __shared__ int sb[Ss];
    __shared__ int cnt[NB];
    __shared__ int offs[NB + 1];
    int bh   = blockIdx.x;
    int tid  = threadIdx.x;
    int lane = tid & 31;
    int w    = tid >> 5;
    const int base = bh * Ss;

    if (tid < NB) cnt[tid] = 0;
    __syncthreads();
    for (int i = tid; i < Ss; i += 256) {
        int v = g_bucket[base + i];
        sb[i] = v;
        atomicAdd(&cnt[v], 1);
    }
    __syncthreads();
    if (tid == 0) {
        offs[0] = 0;
        for (int k = 0; k < NB; k++) offs[k+1] = offs[k] + cnt[k];
    }
    __syncthreads();

    int off[8];
    #pragma unroll
    for (int k = 0; k < 8; k++) off[k] = offs[8*w + k];

    for (int step = 0; step < Ss/32; step++) {
        int t   = step*32 + lane;
        int rel = sb[t] - 8*w;
        #pragma unroll
        for (int k = 0; k < 8; k++) {
            unsigned mask = __ballot_sync(0xffffffffu, rel == k);
            if (rel == k) {
                int pos = off[k] + __popc(mask & ((1u << lane) - 1u));
                g_perm[base + pos] = t;
            }
            off[k] += __popc(mask);
        }
    }
}

// ---------------- 3) chunked attention: tf32 QK + bf16x2 PV -----------------
// ks[128][68]     : normalized K (tf32 bits); rows 0..63 double as Q
// ph2/pl2[64][68] : packed bf16x2 probs hi/lo words (overlay ks after QK)
// vh/vl           : V split bf16, transposed [col e][k], pair-packed + swizzled
#define KS_LD 68
#define PH_LD 68                      // 64 data words (128 cols) + 4 pad
#define SM_KS   0
#define SM_PH   0                     // overlay (word offsets)
#define SM_PL   (64*PH_LD)            // 4352
#define SM_VH   (128*KS_LD)           // float offset 8704 (= PL end: 2*4352)
#define SM_VL   (SM_VH + 64*136/2)    // +4352 = 13056
#define SM_PM   (SM_VL + 64*136/2)    // 17408
#define SM_PS   (SM_PM + 128)
#define SM_QSC  (SM_PS + 128)
#define SM_TK   (SM_QSC + 64)
#define ATTN_SMEM ((SM_TK + 128) * 4) // 71424 bytes
__global__ void __launch_bounds__(256, 3) attn_kernel(
    const float* __restrict__ qk, const float* __restrict__ v)
{
    extern __shared__ float sm[];
    float* ks  = sm + SM_KS;
    uint*  ph2 = (uint*)(sm + SM_PH);
    uint*  pl2 = (uint*)(sm + SM_PL);
    __nv_bfloat16* vhh = (__nv_bfloat16*)(sm + SM_VH);
    __nv_bfloat16* vlh = (__nv_bfloat16*)(sm + SM_VL);
    uint*  vhw = (uint*)(sm + SM_VH);
    uint*  vlw = (uint*)(sm + SM_VL);
    float* pm  = sm + SM_PM;
    float* ps  = sm + SM_PS;
    float* qsc = sm + SM_QSC;
    int*   tk  = (int*)(sm + SM_TK);

    int b = blockIdx.x >> 9;
    int c = blockIdx.x & (NCHUNK - 1);
    int h = c >> 6;
    int cprev = (c + NCHUNK - 1) & (NCHUNK - 1);
    int tid = threadIdx.x;
    const int pbase = b * (Hh * Ss);

    if (tid < 64)        tk[tid] = g_perm[pbase + c*64 + tid];
    else if (tid < 128)  tk[tid] = g_perm[pbase + cprev*64 + (tid - 64)];
    __syncthreads();

    const float* qkb = qk + (size_t)b*Ss*Dd;
    const float* vb  = v  + (size_t)b*Ss*Dd;

    // gather: K rows -> ks (fp32); V rows -> bf16 hi/lo transposed (swizzled)
    for (int idx = tid; idx < 128*16; idx += 256) {
        int r = idx >> 4, q4 = idx & 15;
        int t = tk[r];
        float4 x = *(const float4*)(qkb + (size_t)t*Dd + q4*4);
        *(float4*)(ks + r*KS_LD + q4*4) = x;
        float4 y = *(const float4*)(vb + (size_t)t*Dd + q4*4);
        int c0 = q4*4;
        #pragma unroll
        for (int cc = 0; cc < 4; cc++) {
            float val = (cc==0) ? y.x : (cc==1) ? y.y : (cc==2) ? y.z : y.w;
            int e = c0 + cc;
            int hidx = e*136 + (r ^ (2*(e >> 2)));      // swizzled half index
            __nv_bfloat16 bh = __float2bfloat16(val);
            float res = val - __bfloat162float(bh);
            vhh[hidx] = bh;
            vlh[hidx] = __float2bfloat16(res);
        }
    }
    __syncthreads();

    // normalize rows in place -> tf32 bits; rows<64 record scale
    if (tid < 128) {
        float* row = ks + tid*KS_LD;
        ull s2 = 0ull;
        #pragma unroll
        for (int f = 0; f < 64; f += 2) {
            ull x = ld64s(row + f);
            s2 = ffma2(x, x, s2);
        }
        float nrm = sqrtf(f32x2_sum(s2)) + 1e-6f;
        float inv = 1.0f / nrm;
        #pragma unroll
        for (int f = 0; f < 64; f++)
            row[f] = __uint_as_float(cvt_tf32(row[f] * inv));
        if (tid < 64) qsc[tid] = nrm * 0.125f;
    }
    __syncthreads();

    // ---- QK^T : 64x128x64 tf32, per warp m16 x n64 ----
    int wid   = tid >> 5;
    int lane  = tid & 31;
    int gr    = lane >> 2;
    int cl    = lane & 3;
    int mrow  = 16*(wid & 3);
    int chalf = wid >> 2;
    int ncol  = 64*chalf;

    float acc[8][4];
    #pragma unroll
    for (int n = 0; n < 8; n++)
        #pragma unroll
        for (int i = 0; i < 4; i++) acc[n][i] = 0.f;

    #pragma unroll 2
    for (int k0 = 0; k0 < 8; k0++) {
        const float* ab = ks + (mrow + gr)*KS_LD + 8*k0 + cl;
        uint a0 = ldu(ab), a1 = ldu(ab + 8*KS_LD), a2 = ldu(ab + 4), a3 = ldu(ab + 8*KS_LD + 4);
        #pragma unroll
        for (int n = 0; n < 8; n++) {
            const float* bbp = ks + (ncol + 8*n + gr)*KS_LD + 8*k0 + cl;
            uint b0 = ldu(bbp), b1 = ldu(bbp + 4);
            mma_tf32(acc[n], a0, a1, a2, a3, b0, b1);
        }
    }

    // ---- mask + scale + per-half softmax partials ----
    int row0 = mrow + gr, row1 = row0 + 8;
    int tr0 = tk[row0], tr1 = tk[row1];
    float sc0 = qsc[row0], sc1 = qsc[row1];
    float m0 = -1e30f, m1 = -1e30f;
    #pragma unroll
    for (int n = 0; n < 8; n++) {
        int j0 = ncol + 8*n + 2*cl;
        int tj0 = tk[j0], tj1 = tk[j0 + 1];
        float d0 = (tj0 == tr0) ? NEGV : acc[n][0]*sc0;
        float d1 = (tj1 == tr0) ? NEGV : acc[n][1]*sc0;
        float d2 = (tj0 == tr1) ? NEGV : acc[n][2]*sc1;
        float d3 = (tj1 == tr1) ? NEGV : acc[n][3]*sc1;
        acc[n][0] = d0; acc[n][1] = d1; acc[n][2] = d2; acc[n][3] = d3;
        m0 = fmaxf(m0, fmaxf(d0, d1));
        m1 = fmaxf(m1, fmaxf(d2, d3));
    }
    #pragma unroll
    for (int s = 1; s < 4; s <<= 1) {
        m0 = fmaxf(m0, __shfl_xor_sync(0xffffffffu, m0, s));
        m1 = fmaxf(m1, __shfl_xor_sync(0xffffffffu, m1, s));
    }
    float s0 = 0.f, s1 = 0.f;
    #pragma unroll
    for (int n = 0; n < 8; n++) {
        s0 += __expf(acc[n][0] - m0) + __expf(acc[n][1] - m0);
        s1 += __expf(acc[n][2] - m1) + __expf(acc[n][3] - m1);
    }
    #pragma unroll
    for (int s = 1; s < 4; s <<= 1) {
        s0 += __shfl_xor_sync(0xffffffffu, s0, s);
        s1 += __shfl_xor_sync(0xffffffffu, s1, s);
    }
    if (cl == 0) {
        pm[chalf*64 + row0] = m0;  ps[chalf*64 + row0] = s0;
        pm[chalf*64 + row1] = m1;  ps[chalf*64 + row1] = s1;
    }
    __syncthreads();   // partials visible; ALL warps done reading ks

    float Ma0 = pm[row0], Mb0 = pm[64 + row0];
    float M0  = fmaxf(Ma0, Mb0);
    float S0  = ps[row0]*__expf(Ma0 - M0) + ps[64 + row0]*__expf(Mb0 - M0);
    float lse0 = M0 + __logf(S0);
    float Ma1 = pm[row1], Mb1 = pm[64 + row1];
    float M1  = fmaxf(Ma1, Mb1);
    float S1  = ps[row1]*__expf(Ma1 - M1) + ps[64 + row1]*__expf(Mb1 - M1);
    float lse1 = M1 + __logf(S1);

    if (cl == 0 && chalf == 0) {
        g_logits[pbase + h*Ss + tr0] = lse0;
        g_logits[pbase + h*Ss + tr1] = lse1;
    }

    // probs = exp(d - lse) split into bf16 hi/lo packed pairs (overlay ks)
    {
        int pw0 = row0*PH_LD + (ncol >> 1) + cl;
        int pw1 = row1*PH_LD + (ncol >> 1) + cl;
        #pragma unroll
        for (int n = 0; n < 8; n++) {
            float p00 = __expf(acc[n][0] - lse0);
            float p01 = __expf(acc[n][1] - lse0);
            float p10 = __expf(acc[n][2] - lse1);
            float p11 = __expf(acc[n][3] - lse1);
            uint h0 = pack_bf16x2(p00, p01);
            uint h1 = pack_bf16x2(p10, p11);
            uint l0 = pack_bf16x2(p00 - bf_lo_f32(h0), p01 - bf_hi_f32(h0));
            uint l1 = pack_bf16x2(p10 - bf_lo_f32(h1), p11 - bf_hi_f32(h1));
            ph2[pw0 + 4*n] = h0;  pl2[pw0 + 4*n] = l0;
            ph2[pw1 + 4*n] = h1;  pl2[pw1 + 4*n] = l1;
        }
    }
    __syncthreads();

    // ---- PV : 64x64x128, bf16x2 x3 terms, m16n8k16, per warp m16 x n32 ----
    int ocol = 32*chalf;
    float oacc[4][4];
    #pragma unroll
    for (int n = 0; n < 4; n++)
        #pragma unroll
        for (int i = 0; i < 4; i++) oacc[n][i] = 0.f;

    int ebase[4], sxor[4];
    #pragma unroll
    for (int n = 0; n < 4; n++) {
        int e = ocol + 8*n + gr;
        ebase[n] = e*68;        // word stride = 68 (136 halves)
        sxor[n]  = e >> 2;
    }
    const uint* ph2r0 = ph2 + row0*PH_LD;
    const uint* ph2r1 = ph2 + row1*PH_LD;
    const uint* pl2r0 = pl2 + row0*PH_LD;
    const uint* pl2r1 = pl2 + row1*PH_LD;

    #pragma unroll 1
    for (int k0 = 0; k0 < 8; k0++) {
        int wa = 8*k0 + cl;
        uint ah0 = ph2r0[wa], ah1 = ph2r1[wa], ah2 = ph2r0[wa+4], ah3 = ph2r1[wa+4];
        uint al0 = pl2r0[wa], al1 = pl2r1[wa], al2 = pl2r0[wa+4], al3 = pl2r1[wa+4];
        #pragma unroll
        for (int n = 0; n < 4; n++) {
            int w0 = ebase[n] + (wa ^ sxor[n]);
            int w1 = ebase[n] + ((wa + 4) ^ sxor[n]);
            uint bh0 = vhw[w0], bh1 = vhw[w1];
            uint bl0 = vlw[w0], bl1 = vlw[w1];
            mma_bf16(oacc[n], ah0, ah1, ah2, ah3, bh0, bh1);
            mma_bf16(oacc[n], ah0, ah1, ah2, ah3, bl0, bl1);
            mma_bf16(oacc[n], al0, al1, al2, al3, bh0, bh1);
        }
    }

    // ---- scatter to g_o ----
    {
        float* orow0 = g_o + ((size_t)(pbase + h*Ss + tr0))*Dd;
        float* orow1 = g_o + ((size_t)(pbase + h*Ss + tr1))*Dd;
        #pragma unroll
        for (int n = 0; n < 4; n++) {
            int col = ocol + 8*n + 2*cl;
            *(float2*)(orow0 + col) = make_float2(oacc[n][0], oacc[n][1]);
            *(float2*)(orow1 + col) = make_float2(oacc[n][2], oacc[n][3]);
        }
    }
}

// ---------------- 4) combine hash rounds via softmax(logits) ----------------
__global__ void __launch_bounds__(256) combine_kernel(float* __restrict__ out)
{
    size_t gid = (size_t)blockIdx.x*256 + threadIdx.x;
    if (gid >= (size_t)Bb*Ss*Dd/8) return;
    int pair = (int)(gid & 7);
    size_t bt = gid >> 3;
    int t = (int)(bt & (Ss - 1));
    int b = (int)(bt >> 12);

    float l[Hh];
    float m = -1e30f;
    #pragma unroll
    for (int h = 0; h < Hh; h++) {
        l[h] = g_logits[((size_t)(b*Hh + h))*Ss + t];
        m = fmaxf(m, l[h]);
    }
    float ssum = 0.f;
    #pragma unroll
    for (int h = 0; h < Hh; h++) { l[h] = __expf(l[h] - m); ssum += l[h]; }
    float inv = 1.f / ssum;

    float4 acc0 = make_float4(0.f, 0.f, 0.f, 0.f);
    float4 acc1 = make_float4(0.f, 0.f, 0.f, 0.f);
    #pragma unroll
    for (int h = 0; h < Hh; h++) {
        float w = l[h]*inv;
        const float* op = g_o + (((size_t)(b*Hh + h))*Ss + t)*Dd + pair*8;
        float4 o0 = *(const float4*)(op);
        float4 o1 = *(const float4*)(op + 4);
        acc0.x += w*o0.x; acc0.y += w*o0.y; acc0.z += w*o0.z; acc0.w += w*o0.w;
        acc1.x += w*o1.x; acc1.y += w*o1.y; acc1.z += w*o1.z; acc1.w += w*o1.w;
    }
    float* dst = out + bt*Dd + pair*8;
    *(float4*)(dst)     = acc0;
    *(float4*)(dst + 4) = acc1;
}

// ---------------- 5) buckets output ------------------------------------------
__global__ void __launch_bounds__(256) buckets_kernel(float* __restrict__ outb)
{
    int gid = blockIdx.x*256 + threadIdx.x;
    if (gid >= Bb*Hh*Ss) return;
    int h = (gid >> 12) & 7;
    outb[gid] = (float)(g_bucket[gid] + h*NB);
}

// ---------------- launch ------------------------------------------------------
extern "C" void kernel_launch(void* const* d_in, const int* in_sizes, int n_in,
                              void* d_out, int out_size)
{
    const float* qk  = (const float*)d_in[0];
    const float* v   = (const float*)d_in[1];
    const float* rot = (const float*)d_in[2];
    float* out = (float*)d_out;

    cudaFuncSetAttribute(attn_kernel, cudaFuncAttributeMaxDynamicSharedMemorySize, ATTN_SMEM);

    hash_kernel<<<Bb*(Ss/TT), 256>>>(qk, rot);
    sort_kernel<<<Bb*Hh, 256>>>();
    attn_kernel<<<Bb*NCHUNK, 256, ATTN_SMEM>>>(qk, v);
    combine_kernel<<<(int)(((size_t)Bb*Ss*Dd/8 + 255)/256), 256>>>(out);

    if (out_size >= Bb*Ss*Dd + Bb*Hh*Ss) {
        buckets_kernel<<<(Bb*Hh*Ss + 255)/256, 256>>>(out + (size_t)Bb*Ss*Dd);
    }
}

// round 11
// speedup vs baseline: 2.0093x; 1.0450x over previous
#include <cuda_runtime.h>
#include <cuda_bf16.h>
#include <cuda_fp16.h>
#include <math.h>
#include <stdint.h>

#define Bb 16
#define Ss 4096
#define Dd 64
#define Hh 8
#define NB 64          // buckets per hash
#define NCHUNK 512     // Hh * NB
#define NEGV (-50000.0f)

typedef unsigned long long ull;
typedef unsigned int uint;

// ---------------- f32x2 packed-math helpers (sm_103a) -----------------------
__device__ __forceinline__ ull ffma2(ull a, ull b, ull c) {
    ull d;
    asm("fma.rn.f32x2 %0, %1, %2, %3;" : "=l"(d) : "l"(a), "l"(b), "l"(c));
    return d;
}
__device__ __forceinline__ ull pack2(float lo, float hi) {
    ull r;
    asm("mov.b64 %0, {%1, %2};" : "=l"(r) : "f"(lo), "f"(hi));
    return r;
}
__device__ __forceinline__ float f32x2_sum(ull v) {
    float lo, hi;
    asm("mov.b64 {%0, %1}, %2;" : "=f"(lo), "=f"(hi) : "l"(v));
    return lo + hi;
}
__device__ __forceinline__ void unpack2(ull v, float& lo, float& hi) {
    asm("mov.b64 {%0, %1}, %2;" : "=f"(lo), "=f"(hi) : "l"(v));
}
__device__ __forceinline__ ull ld64s(const float* p) {
    return *(const ull*)p;
}

// ---------------- mma helpers -------------------------------------------------
__device__ __forceinline__ uint cvt_tf32(float x) {
    uint r;
    asm("cvt.rna.tf32.f32 %0, %1;" : "=r"(r) : "f"(x));
    return r;
}
__device__ __forceinline__ void mma_tf32(float* c,
    uint a0, uint a1, uint a2, uint a3, uint b0, uint b1)
{
    asm("mma.sync.aligned.m16n8k8.row.col.f32.tf32.tf32.f32 "
        "{%0,%1,%2,%3}, {%4,%5,%6,%7}, {%8,%9}, {%0,%1,%2,%3};"
        : "+f"(c[0]), "+f"(c[1]), "+f"(c[2]), "+f"(c[3])
        : "r"(a0), "r"(a1), "r"(a2), "r"(a3), "r"(b0), "r"(b1));
}
__device__ __forceinline__ void mma_bf16(float* c,
    uint a0, uint a1, uint a2, uint a3, uint b0, uint b1)
{
    asm("mma.sync.aligned.m16n8k16.row.col.f32.bf16.bf16.f32 "
        "{%0,%1,%2,%3}, {%4,%5,%6,%7}, {%8,%9}, {%0,%1,%2,%3};"
        : "+f"(c[0]), "+f"(c[1]), "+f"(c[2]), "+f"(c[3])
        : "r"(a0), "r"(a1), "r"(a2), "r"(a3), "r"(b0), "r"(b1));
}
__device__ __forceinline__ uint ldu(const float* p) { return __float_as_uint(*p); }
// pack two f32 -> bf16x2 word: lower half = 'lo' (even k), upper half = 'hi'
__device__ __forceinline__ uint pack_bf16x2(float lo, float hi) {
    uint r;
    asm("cvt.rn.bf16x2.f32 %0, %1, %2;" : "=r"(r) : "f"(hi), "f"(lo));
    return r;
}
__device__ __forceinline__ float bf_lo_f32(uint w) { return __uint_as_float(w << 16); }
__device__ __forceinline__ float bf_hi_f32(uint w) { return __uint_as_float(w & 0xffff0000u); }

// ---------------- device scratch ---------------------------------------------
__device__ int   g_bucket[Bb*Hh*Ss];
__device__ int   g_perm  [Bb*Hh*Ss];
__device__ uint  g_o16 [(size_t)Bb*Hh*Ss*(Dd/2)];   // per-hash outputs, fp16x2
__device__ float g_logits[Bb*Hh*Ss];

// ---------------- 1) LSH hashing (bit-exact f-sequential accumulation) -------
#define TT 16
#define QT_STRIDE 18
__global__ void __launch_bounds__(256) hash_kernel(
    const float* __restrict__ qk, const float* __restrict__ rot)
{
    __shared__ float qsT[64*QT_STRIDE];

    int blocksPerB = Ss / TT;
    int b  = blockIdx.x / blocksPerB;
    int t0 = (blockIdx.x % blocksPerB) * TT;
    int tid = threadIdx.x;

    {
        int f = tid & 63;
        int i0 = tid >> 6;
        #pragma unroll
        for (int i = i0; i < TT; i += 4)
            qsT[f*QT_STRIDE + i] = qk[((size_t)b*Ss + t0 + i)*Dd + f];
    }
    __syncthreads();

    const float* rb = rot + (size_t)b*64*256 + tid;

    ull acc2[TT/2];
    #pragma unroll
    for (int ip = 0; ip < TT/2; ip++) acc2[ip] = 0ull;
    #pragma unroll 8
    for (int f = 0; f < 64; f++) {
        float rv = __ldg(rb + f*256);
        ull rv2 = pack2(rv, rv);
        #pragma unroll
        for (int ip = 0; ip < TT/2; ip++)
            acc2[ip] = ffma2(ld64s(qsT + f*QT_STRIDE + 2*ip), rv2, acc2[ip]);
    }

    int lane = tid & 31;
    int h    = tid >> 5;
    #pragma unroll
    for (int ip = 0; ip < TT/2; ip++) {
        float va[2];
        unpack2(acc2[ip], va[0], va[1]);
        #pragma unroll
        for (int s = 0; s < 2; s++) {
            float v = va[s];
            float val; int idx;
            if (v >= -v) { val = v;  idx = lane; }
            else         { val = -v; idx = lane + 32; }
            #pragma unroll
            for (int m = 16; m > 0; m >>= 1) {
                float ov = __shfl_xor_sync(0xffffffffu, val, m);
                int   oi = __shfl_xor_sync(0xffffffffu, idx, m);
                if (ov > val || (ov == val && oi < idx)) { val = ov; idx = oi; }
            }
            if (lane == 0)
                g_bucket[((size_t)b*Hh + h)*Ss + t0 + 2*ip + s] = idx;
        }
    }
}

// ---------------- 2) stable counting sort per (b,h), ballot-ranked ----------
__global__ void __launch_bounds__(256) sort_kernel()
{
    __shared__ int sb[Ss];
    __shared__ int cnt[NB];
    __shared__ int offs[NB + 1];
    int bh   = blockIdx.x;
    int tid  = threadIdx.x;
    int lane = tid & 31;
    int w    = tid >> 5;
    const int base = bh * Ss;

    if (tid < NB) cnt[tid] = 0;
    __syncthreads();
    for (int i = tid; i < Ss; i += 256) {
        int v = g_bucket[base + i];
        sb[i] = v;
        atomicAdd(&cnt[v], 1);
    }
    __syncthreads();
    if (tid == 0) {
        offs[0] = 0;
        for (int k = 0; k < NB; k++) offs[k+1] = offs[k] + cnt[k];
    }
    __syncthreads();

    int off[8];
    #pragma unroll
    for (int k = 0; k < 8; k++) off[k] = offs[8*w + k];

    for (int step = 0; step < Ss/32; step++) {
        int t   = step*32 + lane;
        int rel = sb[t] - 8*w;
        #pragma unroll
        for (int k = 0; k < 8; k++) {
            unsigned mask = __ballot_sync(0xffffffffu, rel == k);
            if (rel == k) {
                int pos = off[k] + __popc(mask & ((1u << lane) - 1u));
                g_perm[base + pos] = t;
            }
            off[k] += __popc(mask);
        }
    }
}

// ---------------- 3) chunked attention: tf32 QK + bf16x2 PV -----------------
#define KS_LD 68
#define PH_LD 68                      // 64 data words (128 cols) + 4 pad
#define SM_KS   0
#define SM_PH   0                     // overlay (word offsets)
#define SM_PL   (64*PH_LD)            // 4352
#define SM_VH   (128*KS_LD)           // float offset 8704 (= PL end: 2*4352)
#define SM_VL   (SM_VH + 64*136/2)    // +4352 = 13056
#define SM_PM   (SM_VL + 64*136/2)    // 17408
#define SM_PS   (SM_PM + 128)
#define SM_QSC  (SM_PS + 128)
#define SM_TK   (SM_QSC + 64)
#define ATTN_SMEM ((SM_TK + 128) * 4) // 71424 bytes
__global__ void __launch_bounds__(256, 3) attn_kernel(
    const float* __restrict__ qk, const float* __restrict__ v)
{
    extern __shared__ float sm[];
    float* ks  = sm + SM_KS;
    uint*  ph2 = (uint*)(sm + SM_PH);
    uint*  pl2 = (uint*)(sm + SM_PL);
    __nv_bfloat16* vhh = (__nv_bfloat16*)(sm + SM_VH);
    __nv_bfloat16* vlh = (__nv_bfloat16*)(sm + SM_VL);
    uint*  vhw = (uint*)(sm + SM_VH);
    uint*  vlw = (uint*)(sm + SM_VL);
    float* pm  = sm + SM_PM;
    float* ps  = sm + SM_PS;
    float* qsc = sm + SM_QSC;
    int*   tk  = (int*)(sm + SM_TK);

    int b = blockIdx.x >> 9;
    int c = blockIdx.x & (NCHUNK - 1);
    int h = c >> 6;
    int cprev = (c + NCHUNK - 1) & (NCHUNK - 1);
    int tid = threadIdx.x;
    const int pbase = b * (Hh * Ss);

    if (tid < 64)        tk[tid] = g_perm[pbase + c*64 + tid];
    else if (tid < 128)  tk[tid] = g_perm[pbase + cprev*64 + (tid - 64)];
    __syncthreads();

    const float* qkb = qk + (size_t)b*Ss*Dd;
    const float* vb  = v  + (size_t)b*Ss*Dd;

    // gather: thread owns column q4 of rows rb, rb+16, ..., rb+112.
    // Batch LDGs (4 rows at a time) for high MLP before any processing.
    {
        int q4 = tid & 15, rb0 = tid >> 4;
        int c0 = q4*4;
        #pragma unroll
        for (int half = 0; half < 2; half++) {
            float4 xq[4], xv[4];
            int rr[4];
            #pragma unroll
            for (int i = 0; i < 4; i++) {
                int r = rb0 + 16*(4*half + i);
                rr[i] = r;
                int t = tk[r];
                xq[i] = *(const float4*)(qkb + (size_t)t*Dd + c0);
                xv[i] = *(const float4*)(vb  + (size_t)t*Dd + c0);
            }
            #pragma unroll
            for (int i = 0; i < 4; i++) {
                int r = rr[i];
                *(float4*)(ks + r*KS_LD + c0) = xq[i];
                #pragma unroll
                for (int cc = 0; cc < 4; cc++) {
                    float val = (cc==0) ? xv[i].x : (cc==1) ? xv[i].y
                              : (cc==2) ? xv[i].z : xv[i].w;
                    int e = c0 + cc;
                    int hidx = e*136 + (r ^ (2*(e >> 2)));   // swizzled half index
                    __nv_bfloat16 bh = __float2bfloat16(val);
                    float res = val - __bfloat162float(bh);
                    vhh[hidx] = bh;
                    vlh[hidx] = __float2bfloat16(res);
                }
            }
        }
    }
    __syncthreads();

    // normalize rows in place -> tf32 bits; 2 threads per row
    {
        int r  = tid >> 1;
        int hf = tid & 1;
        float* rowh = ks + r*KS_LD + hf*32;
        ull s2 = 0ull;
        #pragma unroll
        for (int f = 0; f < 32; f += 2) {
            ull x = ld64s(rowh + f);
            s2 = ffma2(x, x, s2);
        }
        float part = f32x2_sum(s2);
        part += __shfl_xor_sync(0xffffffffu, part, 1);
        float nrm = sqrtf(part) + 1e-6f;
        float inv = 1.0f / nrm;
        #pragma unroll
        for (int f = 0; f < 32; f++)
            rowh[f] = __uint_as_float(cvt_tf32(rowh[f] * inv));
        if (r < 64 && hf == 0) qsc[r] = nrm * 0.125f;
    }
    __syncthreads();

    // ---- QK^T : 64x128x64 tf32, per warp m16 x n64 ----
    int wid   = tid >> 5;
    int lane  = tid & 31;
    int gr    = lane >> 2;
    int cl    = lane & 3;
    int mrow  = 16*(wid & 3);
    int chalf = wid >> 2;
    int ncol  = 64*chalf;

    float acc[8][4];
    #pragma unroll
    for (int n = 0; n < 8; n++)
        #pragma unroll
        for (int i = 0; i < 4; i++) acc[n][i] = 0.f;

    #pragma unroll 2
    for (int k0 = 0; k0 < 8; k0++) {
        const float* ab = ks + (mrow + gr)*KS_LD + 8*k0 + cl;
        uint a0 = ldu(ab), a1 = ldu(ab + 8*KS_LD), a2 = ldu(ab + 4), a3 = ldu(ab + 8*KS_LD + 4);
        #pragma unroll
        for (int n = 0; n < 8; n++) {
            const float* bbp = ks + (ncol + 8*n + gr)*KS_LD + 8*k0 + cl;
            uint b0 = ldu(bbp), b1 = ldu(bbp + 4);
            mma_tf32(acc[n], a0, a1, a2, a3, b0, b1);
        }
    }

    // ---- mask + scale + per-half softmax partials ----
    int row0 = mrow + gr, row1 = row0 + 8;
    int tr0 = tk[row0], tr1 = tk[row1];
    float sc0 = qsc[row0], sc1 = qsc[row1];
    float m0 = -1e30f, m1 = -1e30f;
    #pragma unroll
    for (int n = 0; n < 8; n++) {
        int j0 = ncol + 8*n + 2*cl;
        int tj0 = tk[j0], tj1 = tk[j0 + 1];
        float d0 = (tj0 == tr0) ? NEGV : acc[n][0]*sc0;
        float d1 = (tj1 == tr0) ? NEGV : acc[n][1]*sc0;
        float d2 = (tj0 == tr1) ? NEGV : acc[n][2]*sc1;
        float d3 = (tj1 == tr1) ? NEGV : acc[n][3]*sc1;
        acc[n][0] = d0; acc[n][1] = d1; acc[n][2] = d2; acc[n][3] = d3;
        m0 = fmaxf(m0, fmaxf(d0, d1));
        m1 = fmaxf(m1, fmaxf(d2, d3));
    }
    #pragma unroll
    for (int s = 1; s < 4; s <<= 1) {
        m0 = fmaxf(m0, __shfl_xor_sync(0xffffffffu, m0, s));
        m1 = fmaxf(m1, __shfl_xor_sync(0xffffffffu, m1, s));
    }
    // e = exp(d - m) kept in acc for reuse by the probs write
    float s0 = 0.f, s1 = 0.f;
    #pragma unroll
    for (int n = 0; n < 8; n++) {
        float e0 = __expf(acc[n][0] - m0);
        float e1 = __expf(acc[n][1] - m0);
        float e2 = __expf(acc[n][2] - m1);
        float e3 = __expf(acc[n][3] - m1);
        acc[n][0] = e0; acc[n][1] = e1; acc[n][2] = e2; acc[n][3] = e3;
        s0 += e0 + e1;
        s1 += e2 + e3;
    }
    #pragma unroll
    for (int s = 1; s < 4; s <<= 1) {
        s0 += __shfl_xor_sync(0xffffffffu, s0, s);
        s1 += __shfl_xor_sync(0xffffffffu, s1, s);
    }
    if (cl == 0) {
        pm[chalf*64 + row0] = m0;  ps[chalf*64 + row0] = s0;
        pm[chalf*64 + row1] = m1;  ps[chalf*64 + row1] = s1;
    }
    __syncthreads();   // partials visible; ALL warps done reading ks

    float Ma0 = pm[row0], Mb0 = pm[64 + row0];
    float M0  = fmaxf(Ma0, Mb0);
    float S0  = ps[row0]*__expf(Ma0 - M0) + ps[64 + row0]*__expf(Mb0 - M0);
    float lse0 = M0 + __logf(S0);
    float Ma1 = pm[row1], Mb1 = pm[64 + row1];
    float M1  = fmaxf(Ma1, Mb1);
    float S1  = ps[row1]*__expf(Ma1 - M1) + ps[64 + row1]*__expf(Mb1 - M1);
    float lse1 = M1 + __logf(S1);

    if (cl == 0 && chalf == 0) {
        g_logits[pbase + h*Ss + tr0] = lse0;
        g_logits[pbase + h*Ss + tr1] = lse1;
    }

    // probs = e * exp(m - lse), split into bf16 hi/lo packed pairs (overlay ks)
    {
        float f0 = __expf(m0 - lse0);
        float f1 = __expf(m1 - lse1);
        int pw0 = row0*PH_LD + (ncol >> 1) + cl;
        int pw1 = row1*PH_LD + (ncol >> 1) + cl;
        #pragma unroll
        for (int n = 0; n < 8; n++) {
            float p00 = acc[n][0] * f0;
            float p01 = acc[n][1] * f0;
            float p10 = acc[n][2] * f1;
            float p11 = acc[n][3] * f1;
            uint h0 = pack_bf16x2(p00, p01);
            uint h1 = pack_bf16x2(p10, p11);
            uint l0 = pack_bf16x2(p00 - bf_lo_f32(h0), p01 - bf_hi_f32(h0));
            uint l1 = pack_bf16x2(p10 - bf_lo_f32(h1), p11 - bf_hi_f32(h1));
            ph2[pw0 + 4*n] = h0;  pl2[pw0 + 4*n] = l0;
            ph2[pw1 + 4*n] = h1;  pl2[pw1 + 4*n] = l1;
        }
    }
    __syncthreads();

    // ---- PV : 64x64x128, bf16x2 x3 terms, m16n8k16, per warp m16 x n32 ----
    int ocol = 32*chalf;
    float oacc[4][4];
    #pragma unroll
    for (int n = 0; n < 4; n++)
        #pragma unroll
        for (int i = 0; i < 4; i++) oacc[n][i] = 0.f;

    int ebase[4], sxor[4];
    #pragma unroll
    for (int n = 0; n < 4; n++) {
        int e = ocol + 8*n + gr;
        ebase[n] = e*68;        // word stride = 68 (136 halves)
        sxor[n]  = e >> 2;
    }
    const uint* ph2r0 = ph2 + row0*PH_LD;
    const uint* ph2r1 = ph2 + row1*PH_LD;
    const uint* pl2r0 = pl2 + row0*PH_LD;
    const uint* pl2r1 = pl2 + row1*PH_LD;

    #pragma unroll 1
    for (int k0 = 0; k0 < 8; k0++) {
        int wa = 8*k0 + cl;
        uint ah0 = ph2r0[wa], ah1 = ph2r1[wa], ah2 = ph2r0[wa+4], ah3 = ph2r1[wa+4];
        uint al0 = pl2r0[wa], al1 = pl2r1[wa], al2 = pl2r0[wa+4], al3 = pl2r1[wa+4];
        #pragma unroll
        for (int n = 0; n < 4; n++) {
            int w0 = ebase[n] + (wa ^ sxor[n]);
            int w1 = ebase[n] + ((wa + 4) ^ sxor[n]);
            uint bh0 = vhw[w0], bh1 = vhw[w1];
            uint bl0 = vlw[w0], bl1 = vlw[w1];
            mma_bf16(oacc[n], ah0, ah1, ah2, ah3, bh0, bh1);
            mma_bf16(oacc[n], ah0, ah1, ah2, ah3, bl0, bl1);
            mma_bf16(oacc[n], al0, al1, al2, al3, bh0, bh1);
        }
    }

    // ---- scatter to g_o16 (fp16x2) ----
    {
        uint* orow0 = g_o16 + (size_t)(pbase + h*Ss + tr0)*(Dd/2);
        uint* orow1 = g_o16 + (size_t)(pbase + h*Ss + tr1)*(Dd/2);
        #pragma unroll
        for (int n = 0; n < 4; n++) {
            int wcol = (ocol >> 1) + 4*n + cl;
            __half2 h0 = __floats2half2_rn(oacc[n][0], oacc[n][1]);
            __half2 h1 = __floats2half2_rn(oacc[n][2], oacc[n][3]);
            orow0[wcol] = *(uint*)&h0;
            orow1[wcol] = *(uint*)&h1;
        }
    }
}

// ---------------- 4) combine hash rounds via softmax(logits) ----------------
__global__ void __launch_bounds__(256) combine_kernel(float* __restrict__ out)
{
    size_t gid = (size_t)blockIdx.x*256 + threadIdx.x;
    if (gid >= (size_t)Bb*Ss*Dd/8) return;
    int pair = (int)(gid & 7);
    size_t bt = gid >> 3;
    int t = (int)(bt & (Ss - 1));
    int b = (int)(bt >> 12);

    float l[Hh];
    float m = -1e30f;
    #pragma unroll
    for (int h = 0; h < Hh; h++) {
        l[h] = g_logits[((size_t)(b*Hh + h))*Ss + t];
        m = fmaxf(m, l[h]);
    }
    float ssum = 0.f;
    #pragma unroll
    for (int h = 0; h < Hh; h++) { l[h] = __expf(l[h] - m); ssum += l[h]; }
    float inv = 1.f / ssum;

    float4 acc0 = make_float4(0.f, 0.f, 0.f, 0.f);
    float4 acc1 = make_float4(0.f, 0.f, 0.f, 0.f);
    #pragma unroll
    for (int h = 0; h < Hh; h++) {
        float w = l[h]*inv;
        const uint4 ow = *(const uint4*)(g_o16 + (((size_t)(b*Hh + h))*Ss + t)*(Dd/2) + pair*4);
        float2 f0 = __half22float2(*(const __half2*)&ow.x);
        float2 f1 = __half22float2(*(const __half2*)&ow.y);
        float2 f2 = __half22float2(*(const __half2*)&ow.z);
        float2 f3 = __half22float2(*(const __half2*)&ow.w);
        acc0.x += w*f0.x; acc0.y += w*f0.y; acc0.z += w*f1.x; acc0.w += w*f1.y;
        acc1.x += w*f2.x; acc1.y += w*f2.y; acc1.z += w*f3.x; acc1.w += w*f3.y;
    }
    float* dst = out + bt*Dd + pair*8;
    *(float4*)(dst)     = acc0;
    *(float4*)(dst + 4) = acc1;
}

// ---------------- 5) buckets output ------------------------------------------
__global__ void __launch_bounds__(256) buckets_kernel(float* __restrict__ outb)
{
    int gid = blockIdx.x*256 + threadIdx.x;
    if (gid >= Bb*Hh*Ss) return;
    int h = (gid >> 12) & 7;
    outb[gid] = (float)(g_bucket[gid] + h*NB);
}

// ---------------- launch ------------------------------------------------------
extern "C" void kernel_launch(void* const* d_in, const int* in_sizes, int n_in,
                              void* d_out, int out_size)
{
    const float* qk  = (const float*)d_in[0];
    const float* v   = (const float*)d_in[1];
    const float* rot = (const float*)d_in[2];
    float* out = (float*)d_out;

    cudaFuncSetAttribute(attn_kernel, cudaFuncAttributeMaxDynamicSharedMemorySize, ATTN_SMEM);

    hash_kernel<<<Bb*(Ss/TT), 256>>>(qk, rot);
    sort_kernel<<<Bb*Hh, 256>>>();
    attn_kernel<<<Bb*NCHUNK, 256, ATTN_SMEM>>>(qk, v);
    combine_kernel<<<(int)(((size_t)Bb*Ss*Dd/8 + 255)/256), 256>>>(out);

    if (out_size >= Bb*Ss*Dd + Bb*Hh*Ss) {
        buckets_kernel<<<(Bb*Hh*Ss + 255)/256, 256>>>(out + (size_t)Bb*Ss*Dd);
    }
}

// round 12
// speedup vs baseline: 2.1078x; 1.0490x over previous
#include <cuda_runtime.h>
#include <cuda_bf16.h>
#include <cuda_fp16.h>
#include <math.h>
#include <stdint.h>

#define Bb 16
#define Ss 4096
#define Dd 64
#define Hh 8
#define NB 64          // buckets per hash
#define NCHUNK 512     // Hh * NB
#define NEGV (-50000.0f)

typedef unsigned long long ull;
typedef unsigned int uint;

// ---------------- f32x2 packed-math helpers (sm_103a) -----------------------
__device__ __forceinline__ ull ffma2(ull a, ull b, ull c) {
    ull d;
    asm("fma.rn.f32x2 %0, %1, %2, %3;" : "=l"(d) : "l"(a), "l"(b), "l"(c));
    return d;
}
__device__ __forceinline__ ull pack2(float lo, float hi) {
    ull r;
    asm("mov.b64 %0, {%1, %2};" : "=l"(r) : "f"(lo), "f"(hi));
    return r;
}
__device__ __forceinline__ void unpack2(ull v, float& lo, float& hi) {
    asm("mov.b64 {%0, %1}, %2;" : "=f"(lo), "=f"(hi) : "l"(v));
}
__device__ __forceinline__ ull ld64s(const float* p) {
    return *(const ull*)p;
}

// ---------------- mma helpers -------------------------------------------------
__device__ __forceinline__ uint cvt_tf32(float x) {
    uint r;
    asm("cvt.rna.tf32.f32 %0, %1;" : "=r"(r) : "f"(x));
    return r;
}
__device__ __forceinline__ void mma_tf32(float* c,
    uint a0, uint a1, uint a2, uint a3, uint b0, uint b1)
{
    asm("mma.sync.aligned.m16n8k8.row.col.f32.tf32.tf32.f32 "
        "{%0,%1,%2,%3}, {%4,%5,%6,%7}, {%8,%9}, {%0,%1,%2,%3};"
        : "+f"(c[0]), "+f"(c[1]), "+f"(c[2]), "+f"(c[3])
        : "r"(a0), "r"(a1), "r"(a2), "r"(a3), "r"(b0), "r"(b1));
}
__device__ __forceinline__ void mma_bf16(float* c,
    uint a0, uint a1, uint a2, uint a3, uint b0, uint b1)
{
    asm("mma.sync.aligned.m16n8k16.row.col.f32.bf16.bf16.f32 "
        "{%0,%1,%2,%3}, {%4,%5,%6,%7}, {%8,%9}, {%0,%1,%2,%3};"
        : "+f"(c[0]), "+f"(c[1]), "+f"(c[2]), "+f"(c[3])
        : "r"(a0), "r"(a1), "r"(a2), "r"(a3), "r"(b0), "r"(b1));
}
__device__ __forceinline__ uint ldu(const float* p) { return __float_as_uint(*p); }
// pack two f32 -> bf16x2 word: lower half = 'lo' (even k), upper half = 'hi'
__device__ __forceinline__ uint pack_bf16x2(float lo, float hi) {
    uint r;
    asm("cvt.rn.bf16x2.f32 %0, %1, %2;" : "=r"(r) : "f"(hi), "f"(lo));
    return r;
}
__device__ __forceinline__ float bf_lo_f32(uint w) { return __uint_as_float(w << 16); }
__device__ __forceinline__ float bf_hi_f32(uint w) { return __uint_as_float(w & 0xffff0000u); }

// ---------------- device scratch ---------------------------------------------
__device__ int   g_bucket[Bb*Hh*Ss];
__device__ int   g_perm  [Bb*Hh*Ss];
__device__ uint  g_o16 [(size_t)Bb*Hh*Ss*(Dd/2)];   // per-hash outputs, fp16x2
__device__ float g_logits[Bb*Hh*Ss];

// ---------------- 1) LSH hashing (bit-exact f-sequential accumulation) -------
// TT=32 tokens/block halves rot L2 traffic; also emits the float buckets output.
#define TT 32
#define QT_STRIDE 34
__global__ void __launch_bounds__(256) hash_kernel(
    const float* __restrict__ qk, const float* __restrict__ rot,
    float* __restrict__ outb)
{
    __shared__ float qsT[64*QT_STRIDE];

    int blocksPerB = Ss / TT;                 // 128
    int b  = blockIdx.x / blocksPerB;
    int t0 = (blockIdx.x % blocksPerB) * TT;
    int tid = threadIdx.x;

    {
        int f = tid & 63;
        int i0 = tid >> 6;
        #pragma unroll
        for (int i = i0; i < TT; i += 4)
            qsT[f*QT_STRIDE + i] = qk[((size_t)b*Ss + t0 + i)*Dd + f];
    }
    __syncthreads();

    const float* rb = rot + (size_t)b*64*256 + tid;

    ull acc2[TT/2];
    #pragma unroll
    for (int ip = 0; ip < TT/2; ip++) acc2[ip] = 0ull;
    #pragma unroll 4
    for (int f = 0; f < 64; f++) {
        float rv = __ldg(rb + f*256);
        ull rv2 = pack2(rv, rv);
        #pragma unroll
        for (int ip = 0; ip < TT/2; ip++)
            acc2[ip] = ffma2(ld64s(qsT + f*QT_STRIDE + 2*ip), rv2, acc2[ip]);
    }

    int lane = tid & 31;
    int h    = tid >> 5;
    #pragma unroll
    for (int ip = 0; ip < TT/2; ip++) {
        float va[2];
        unpack2(acc2[ip], va[0], va[1]);
        #pragma unroll
        for (int s = 0; s < 2; s++) {
            float v = va[s];
            float val; int idx;
            if (v >= -v) { val = v;  idx = lane; }
            else         { val = -v; idx = lane + 32; }
            #pragma unroll
            for (int m = 16; m > 0; m >>= 1) {
                float ov = __shfl_xor_sync(0xffffffffu, val, m);
                int   oi = __shfl_xor_sync(0xffffffffu, idx, m);
                if (ov > val || (ov == val && oi < idx)) { val = ov; idx = oi; }
            }
            if (lane == 0) {
                int pos = ((size_t)b*Hh + h)*Ss + t0 + 2*ip + s;
                g_bucket[pos] = idx;
                if (outb) outb[pos] = (float)(idx + h*NB);
            }
        }
    }
}

// ---------------- 2) stable counting sort per (b,h), ballot-ranked ----------
__global__ void __launch_bounds__(256) sort_kernel()
{
    __shared__ int sb[Ss];
    __shared__ int cnt[NB];
    __shared__ int offs[NB + 1];
    int bh   = blockIdx.x;
    int tid  = threadIdx.x;
    int lane = tid & 31;
    int w    = tid >> 5;
    const int base = bh * Ss;

    if (tid < NB) cnt[tid] = 0;
    __syncthreads();
    for (int i = tid; i < Ss; i += 256) {
        int v = g_bucket[base + i];
        sb[i] = v;
        atomicAdd(&cnt[v], 1);
    }
    __syncthreads();
    if (tid == 0) {
        offs[0] = 0;
        for (int k = 0; k < NB; k++) offs[k+1] = offs[k] + cnt[k];
    }
    __syncthreads();

    int off[8];
    #pragma unroll
    for (int k = 0; k < 8; k++) off[k] = offs[8*w + k];

    for (int step = 0; step < Ss/32; step++) {
        int t   = step*32 + lane;
        int rel = sb[t] - 8*w;
        #pragma unroll
        for (int k = 0; k < 8; k++) {
            unsigned mask = __ballot_sync(0xffffffffu, rel == k);
            if (rel == k) {
                int pos = off[k] + __popc(mask & ((1u << lane) - 1u));
                g_perm[base + pos] = t;
            }
            off[k] += __popc(mask);
        }
    }
}

// ---------------- 3) chunked attention: tf32 QK + bf16x2 PV -----------------
#define KS_LD 68
#define PH_LD 68                      // 64 data words (128 cols) + 4 pad
#define SM_KS   0
#define SM_PH   0                     // overlay (word offsets)
#define SM_PL   (64*PH_LD)            // 4352
#define SM_VH   (128*KS_LD)           // float offset 8704 (= PL end: 2*4352)
#define SM_VL   (SM_VH + 64*136/2)    // +4352 = 13056
#define SM_PM   (SM_VL + 64*136/2)    // 17408
#define SM_PS   (SM_PM + 128)
#define SM_QSC  (SM_PS + 128)
#define SM_TK   (SM_QSC + 64)
#define ATTN_SMEM ((SM_TK + 128) * 4) // 71424 bytes
__global__ void __launch_bounds__(256, 3) attn_kernel(
    const float* __restrict__ qk, const float* __restrict__ v)
{
    extern __shared__ float sm[];
    float* ks  = sm + SM_KS;
    uint*  ph2 = (uint*)(sm + SM_PH);
    uint*  pl2 = (uint*)(sm + SM_PL);
    uint*  vhw = (uint*)(sm + SM_VH);
    uint*  vlw = (uint*)(sm + SM_VL);
    float* pm  = sm + SM_PM;
    float* ps  = sm + SM_PS;
    float* qsc = sm + SM_QSC;
    int*   tk  = (int*)(sm + SM_TK);

    int b = blockIdx.x >> 9;
    int c = blockIdx.x & (NCHUNK - 1);
    int h = c >> 6;
    int cprev = (c + NCHUNK - 1) & (NCHUNK - 1);
    int tid = threadIdx.x;
    const int pbase = b * (Hh * Ss);

    if (tid < 64)        tk[tid] = g_perm[pbase + c*64 + tid];
    else if (tid < 128)  tk[tid] = g_perm[pbase + cprev*64 + (tid - 64)];
    __syncthreads();

    const float* qkb = qk + (size_t)b*Ss*Dd;
    const float* vb  = v  + (size_t)b*Ss*Dd;

    // ---- fused gather + normalize ----
    // thread = (col-quad q4, row-pair rp); half-warp holds a full row -> norms
    // via width-16 shfl reduce. Q stored normalized tf32 (STS.128); V split
    // bf16 hi/lo pair-packed along k (STS.32), layout identical to R10/R11.
    {
        int q4 = tid & 15;
        int rp = tid >> 4;
        int c0 = q4*4;
        #pragma unroll
        for (int halfp = 0; halfp < 2; halfp++) {
            float4 xq[2][2], xv[2][2];
            int r0s[2];
            #pragma unroll
            for (int p = 0; p < 2; p++) {
                int r0 = 32*(2*halfp + p) + 2*rp;
                r0s[p] = r0;
                int t0 = tk[r0], t1 = tk[r0 + 1];
                xq[p][0] = *(const float4*)(qkb + (size_t)t0*Dd + c0);
                xq[p][1] = *(const float4*)(qkb + (size_t)t1*Dd + c0);
                xv[p][0] = *(const float4*)(vb  + (size_t)t0*Dd + c0);
                xv[p][1] = *(const float4*)(vb  + (size_t)t1*Dd + c0);
            }
            #pragma unroll
            for (int p = 0; p < 2; p++) {
                int r0 = r0s[p], r1 = r0 + 1;
                float ss0 = xq[p][0].x*xq[p][0].x + xq[p][0].y*xq[p][0].y
                          + xq[p][0].z*xq[p][0].z + xq[p][0].w*xq[p][0].w;
                float ss1 = xq[p][1].x*xq[p][1].x + xq[p][1].y*xq[p][1].y
                          + xq[p][1].z*xq[p][1].z + xq[p][1].w*xq[p][1].w;
                #pragma unroll
                for (int s = 1; s < 16; s <<= 1) {
                    ss0 += __shfl_xor_sync(0xffffffffu, ss0, s, 16);
                    ss1 += __shfl_xor_sync(0xffffffffu, ss1, s, 16);
                }
                float n0 = sqrtf(ss0) + 1e-6f, n1 = sqrtf(ss1) + 1e-6f;
                float i0 = 1.0f/n0, i1 = 1.0f/n1;
                float4 q0, q1;
                q0.x = __uint_as_float(cvt_tf32(xq[p][0].x * i0));
                q0.y = __uint_as_float(cvt_tf32(xq[p][0].y * i0));
                q0.z = __uint_as_float(cvt_tf32(xq[p][0].z * i0));
                q0.w = __uint_as_float(cvt_tf32(xq[p][0].w * i0));
                q1.x = __uint_as_float(cvt_tf32(xq[p][1].x * i1));
                q1.y = __uint_as_float(cvt_tf32(xq[p][1].y * i1));
                q1.z = __uint_as_float(cvt_tf32(xq[p][1].z * i1));
                q1.w = __uint_as_float(cvt_tf32(xq[p][1].w * i1));
                *(float4*)(ks + r0*KS_LD + c0) = q0;
                *(float4*)(ks + r1*KS_LD + c0) = q1;
                if (r0 < 64 && q4 == 0) {
                    qsc[r0] = n0 * 0.125f;
                    qsc[r1] = n1 * 0.125f;
                }
                int kp = r0 >> 1;
                float v0a[4] = {xv[p][0].x, xv[p][0].y, xv[p][0].z, xv[p][0].w};
                float v1a[4] = {xv[p][1].x, xv[p][1].y, xv[p][1].z, xv[p][1].w};
                #pragma unroll
                for (int cc = 0; cc < 4; cc++) {
                    int e = c0 + cc;
                    int w = e*68 + (kp ^ (e >> 2));
                    uint hw = pack_bf16x2(v0a[cc], v1a[cc]);
                    uint lw = pack_bf16x2(v0a[cc] - bf_lo_f32(hw),
                                          v1a[cc] - bf_hi_f32(hw));
                    vhw[w] = hw;
                    vlw[w] = lw;
                }
            }
        }
    }
    __syncthreads();

    // ---- QK^T : 64x128x64 tf32, per warp m16 x n64 ----
    int wid   = tid >> 5;
    int lane  = tid & 31;
    int gr    = lane >> 2;
    int cl    = lane & 3;
    int mrow  = 16*(wid & 3);
    int chalf = wid >> 2;
    int ncol  = 64*chalf;

    float acc[8][4];
    #pragma unroll
    for (int n = 0; n < 8; n++)
        #pragma unroll
        for (int i = 0; i < 4; i++) acc[n][i] = 0.f;

    #pragma unroll 2
    for (int k0 = 0; k0 < 8; k0++) {
        const float* ab = ks + (mrow + gr)*KS_LD + 8*k0 + cl;
        uint a0 = ldu(ab), a1 = ldu(ab + 8*KS_LD), a2 = ldu(ab + 4), a3 = ldu(ab + 8*KS_LD + 4);
        #pragma unroll
        for (int n = 0; n < 8; n++) {
            const float* bbp = ks + (ncol + 8*n + gr)*KS_LD + 8*k0 + cl;
            uint b0 = ldu(bbp), b1 = ldu(bbp + 4);
            mma_tf32(acc[n], a0, a1, a2, a3, b0, b1);
        }
    }

    // ---- mask + scale + per-half softmax partials ----
    int row0 = mrow + gr, row1 = row0 + 8;
    int tr0 = tk[row0], tr1 = tk[row1];
    float sc0 = qsc[row0], sc1 = qsc[row1];
    float m0 = -1e30f, m1 = -1e30f;
    #pragma unroll
    for (int n = 0; n < 8; n++) {
        int j0 = ncol + 8*n + 2*cl;
        int tj0 = tk[j0], tj1 = tk[j0 + 1];
        float d0 = (tj0 == tr0) ? NEGV : acc[n][0]*sc0;
        float d1 = (tj1 == tr0) ? NEGV : acc[n][1]*sc0;
        float d2 = (tj0 == tr1) ? NEGV : acc[n][2]*sc1;
        float d3 = (tj1 == tr1) ? NEGV : acc[n][3]*sc1;
        acc[n][0] = d0; acc[n][1] = d1; acc[n][2] = d2; acc[n][3] = d3;
        m0 = fmaxf(m0, fmaxf(d0, d1));
        m1 = fmaxf(m1, fmaxf(d2, d3));
    }
    #pragma unroll
    for (int s = 1; s < 4; s <<= 1) {
        m0 = fmaxf(m0, __shfl_xor_sync(0xffffffffu, m0, s));
        m1 = fmaxf(m1, __shfl_xor_sync(0xffffffffu, m1, s));
    }
    float s0 = 0.f, s1 = 0.f;
    #pragma unroll
    for (int n = 0; n < 8; n++) {
        float e0 = __expf(acc[n][0] - m0);
        float e1 = __expf(acc[n][1] - m0);
        float e2 = __expf(acc[n][2] - m1);
        float e3 = __expf(acc[n][3] - m1);
        acc[n][0] = e0; acc[n][1] = e1; acc[n][2] = e2; acc[n][3] = e3;
        s0 += e0 + e1;
        s1 += e2 + e3;
    }
    #pragma unroll
    for (int s = 1; s < 4; s <<= 1) {
        s0 += __shfl_xor_sync(0xffffffffu, s0, s);
        s1 += __shfl_xor_sync(0xffffffffu, s1, s);
    }
    if (cl == 0) {
        pm[chalf*64 + row0] = m0;  ps[chalf*64 + row0] = s0;
        pm[chalf*64 + row1] = m1;  ps[chalf*64 + row1] = s1;
    }
    __syncthreads();   // partials visible; ALL warps done reading ks

    float Ma0 = pm[row0], Mb0 = pm[64 + row0];
    float M0  = fmaxf(Ma0, Mb0);
    float S0  = ps[row0]*__expf(Ma0 - M0) + ps[64 + row0]*__expf(Mb0 - M0);
    float lse0 = M0 + __logf(S0);
    float Ma1 = pm[row1], Mb1 = pm[64 + row1];
    float M1  = fmaxf(Ma1, Mb1);
    float S1  = ps[row1]*__expf(Ma1 - M1) + ps[64 + row1]*__expf(Mb1 - M1);
    float lse1 = M1 + __logf(S1);

    if (cl == 0 && chalf == 0) {
        g_logits[pbase + h*Ss + tr0] = lse0;
        g_logits[pbase + h*Ss + tr1] = lse1;
    }

    // probs = e * exp(m - lse), split into bf16 hi/lo packed pairs (overlay ks)
    {
        float f0 = __expf(m0 - lse0);
        float f1 = __expf(m1 - lse1);
        int pw0 = row0*PH_LD + (ncol >> 1) + cl;
        int pw1 = row1*PH_LD + (ncol >> 1) + cl;
        #pragma unroll
        for (int n = 0; n < 8; n++) {
            float p00 = acc[n][0] * f0;
            float p01 = acc[n][1] * f0;
            float p10 = acc[n][2] * f1;
            float p11 = acc[n][3] * f1;
            uint h0 = pack_bf16x2(p00, p01);
            uint h1 = pack_bf16x2(p10, p11);
            uint l0 = pack_bf16x2(p00 - bf_lo_f32(h0), p01 - bf_hi_f32(h0));
            uint l1 = pack_bf16x2(p10 - bf_lo_f32(h1), p11 - bf_hi_f32(h1));
            ph2[pw0 + 4*n] = h0;  pl2[pw0 + 4*n] = l0;
            ph2[pw1 + 4*n] = h1;  pl2[pw1 + 4*n] = l1;
        }
    }
    __syncthreads();

    // ---- PV : 64x64x128, bf16x2 x3 terms, m16n8k16, per warp m16 x n32 ----
    int ocol = 32*chalf;
    float oacc[4][4];
    #pragma unroll
    for (int n = 0; n < 4; n++)
        #pragma unroll
        for (int i = 0; i < 4; i++) oacc[n][i] = 0.f;

    int ebase[4], sxor[4];
    #pragma unroll
    for (int n = 0; n < 4; n++) {
        int e = ocol + 8*n + gr;
        ebase[n] = e*68;        // word stride = 68 (136 halves)
        sxor[n]  = e >> 2;
    }
    const uint* ph2r0 = ph2 + row0*PH_LD;
    const uint* ph2r1 = ph2 + row1*PH_LD;
    const uint* pl2r0 = pl2 + row0*PH_LD;
    const uint* pl2r1 = pl2 + row1*PH_LD;

    #pragma unroll 1
    for (int k0 = 0; k0 < 8; k0++) {
        int wa = 8*k0 + cl;
        uint ah0 = ph2r0[wa], ah1 = ph2r1[wa], ah2 = ph2r0[wa+4], ah3 = ph2r1[wa+4];
        uint al0 = pl2r0[wa], al1 = pl2r1[wa], al2 = pl2r0[wa+4], al3 = pl2r1[wa+4];
        #pragma unroll
        for (int n = 0; n < 4; n++) {
            int w0 = ebase[n] + (wa ^ sxor[n]);
            int w1 = ebase[n] + ((wa + 4) ^ sxor[n]);
            uint bh0 = vhw[w0], bh1 = vhw[w1];
            uint bl0 = vlw[w0], bl1 = vlw[w1];
            mma_bf16(oacc[n], ah0, ah1, ah2, ah3, bh0, bh1);
            mma_bf16(oacc[n], ah0, ah1, ah2, ah3, bl0, bl1);
            mma_bf16(oacc[n], al0, al1, al2, al3, bh0, bh1);
        }
    }

    // ---- scatter to g_o16 (fp16x2) ----
    {
        uint* orow0 = g_o16 + (size_t)(pbase + h*Ss + tr0)*(Dd/2);
        uint* orow1 = g_o16 + (size_t)(pbase + h*Ss + tr1)*(Dd/2);
        #pragma unroll
        for (int n = 0; n < 4; n++) {
            int wcol = (ocol >> 1) + 4*n + cl;
            __half2 h0 = __floats2half2_rn(oacc[n][0], oacc[n][1]);
            __half2 h1 = __floats2half2_rn(oacc[n][2], oacc[n][3]);
            orow0[wcol] = *(uint*)&h0;
            orow1[wcol] = *(uint*)&h1;
        }
    }
}

// ---------------- 4) combine hash rounds via softmax(logits) ----------------
__global__ void __launch_bounds__(256) combine_kernel(float* __restrict__ out)
{
    size_t gid = (size_t)blockIdx.x*256 + threadIdx.x;
    if (gid >= (size_t)Bb*Ss*Dd/8) return;
    int pair = (int)(gid & 7);
    size_t bt = gid >> 3;
    int t = (int)(bt & (Ss - 1));
    int b = (int)(bt >> 12);

    float l[Hh];
    float m = -1e30f;
    #pragma unroll
    for (int h = 0; h < Hh; h++) {
        l[h] = g_logits[((size_t)(b*Hh + h))*Ss + t];
        m = fmaxf(m, l[h]);
    }
    float ssum = 0.f;
    #pragma unroll
    for (int h = 0; h < Hh; h++) { l[h] = __expf(l[h] - m); ssum += l[h]; }
    float inv = 1.f / ssum;

    float4 acc0 = make_float4(0.f, 0.f, 0.f, 0.f);
    float4 acc1 = make_float4(0.f, 0.f, 0.f, 0.f);
    #pragma unroll
    for (int h = 0; h < Hh; h++) {
        float w = l[h]*inv;
        const uint4 ow = *(const uint4*)(g_o16 + (((size_t)(b*Hh + h))*Ss + t)*(Dd/2) + pair*4);
        float2 f0 = __half22float2(*(const __half2*)&ow.x);
        float2 f1 = __half22float2(*(const __half2*)&ow.y);
        float2 f2 = __half22float2(*(const __half2*)&ow.z);
        float2 f3 = __half22float2(*(const __half2*)&ow.w);
        acc0.x += w*f0.x; acc0.y += w*f0.y; acc0.z += w*f1.x; acc0.w += w*f1.y;
        acc1.x += w*f2.x; acc1.y += w*f2.y; acc1.z += w*f3.x; acc1.w += w*f3.y;
    }
    float* dst = out + bt*Dd + pair*8;
    *(float4*)(dst)     = acc0;
    *(float4*)(dst + 4) = acc1;
}

// ---------------- launch ------------------------------------------------------
extern "C" void kernel_launch(void* const* d_in, const int* in_sizes, int n_in,
                              void* d_out, int out_size)
{
    const float* qk  = (const float*)d_in[0];
    const float* v   = (const float*)d_in[1];
    const float* rot = (const float*)d_in[2];
    float* out = (float*)d_out;

    cudaFuncSetAttribute(attn_kernel, cudaFuncAttributeMaxDynamicSharedMemorySize, ATTN_SMEM);

    float* outb = (out_size >= Bb*Ss*Dd + Bb*Hh*Ss) ? (out + (size_t)Bb*Ss*Dd) : nullptr;

    hash_kernel<<<Bb*(Ss/TT), 256>>>(qk, rot, outb);
    sort_kernel<<<Bb*Hh, 256>>>();
    attn_kernel<<<Bb*NCHUNK, 256, ATTN_SMEM>>>(qk, v);
    combine_kernel<<<(int)(((size_t)Bb*Ss*Dd/8 + 255)/256), 256>>>(out);
}

// round 13
// speedup vs baseline: 2.2083x; 1.0477x over previous
#include <cuda_runtime.h>
#include <cuda_bf16.h>
#include <cuda_fp16.h>
#include <math.h>
#include <stdint.h>

#define Bb 16
#define Ss 4096
#define Dd 64
#define Hh 8
#define NB 64          // buckets per hash
#define NCHUNK 512     // Hh * NB
#define NEGV (-50000.0f)

typedef unsigned long long ull;
typedef unsigned int uint;

// ---------------- f32x2 packed-math helpers (sm_103a) -----------------------
__device__ __forceinline__ ull ffma2(ull a, ull b, ull c) {
    ull d;
    asm("fma.rn.f32x2 %0, %1, %2, %3;" : "=l"(d) : "l"(a), "l"(b), "l"(c));
    return d;
}
__device__ __forceinline__ ull pack2(float lo, float hi) {
    ull r;
    asm("mov.b64 %0, {%1, %2};" : "=l"(r) : "f"(lo), "f"(hi));
    return r;
}
__device__ __forceinline__ void unpack2(ull v, float& lo, float& hi) {
    asm("mov.b64 {%0, %1}, %2;" : "=f"(lo), "=f"(hi) : "l"(v));
}
__device__ __forceinline__ ull ld64s(const float* p) {
    return *(const ull*)p;
}

// ---------------- mma helpers -------------------------------------------------
__device__ __forceinline__ uint cvt_tf32(float x) {
    uint r;
    asm("cvt.rna.tf32.f32 %0, %1;" : "=r"(r) : "f"(x));
    return r;
}
__device__ __forceinline__ void mma_tf32(float* c,
    uint a0, uint a1, uint a2, uint a3, uint b0, uint b1)
{
    asm("mma.sync.aligned.m16n8k8.row.col.f32.tf32.tf32.f32 "
        "{%0,%1,%2,%3}, {%4,%5,%6,%7}, {%8,%9}, {%0,%1,%2,%3};"
        : "+f"(c[0]), "+f"(c[1]), "+f"(c[2]), "+f"(c[3])
        : "r"(a0), "r"(a1), "r"(a2), "r"(a3), "r"(b0), "r"(b1));
}
__device__ __forceinline__ void mma_f16(float* c,
    uint a0, uint a1, uint a2, uint a3, uint b0, uint b1)
{
    asm("mma.sync.aligned.m16n8k16.row.col.f32.f16.f16.f32 "
        "{%0,%1,%2,%3}, {%4,%5,%6,%7}, {%8,%9}, {%0,%1,%2,%3};"
        : "+f"(c[0]), "+f"(c[1]), "+f"(c[2]), "+f"(c[3])
        : "r"(a0), "r"(a1), "r"(a2), "r"(a3), "r"(b0), "r"(b1));
}
__device__ __forceinline__ uint ldu(const float* p) { return __float_as_uint(*p); }
// pack two f32 -> f16x2 word: lower half = 'lo' (even k), upper half = 'hi'
__device__ __forceinline__ uint pack_f16x2(float lo, float hi) {
    __half2 h = __floats2half2_rn(lo, hi);
    return *(uint*)&h;
}

// ---------------- device scratch ---------------------------------------------
__device__ int   g_bucket[Bb*Hh*Ss];
__device__ int   g_perm  [Bb*Hh*Ss];
__device__ uint  g_o16 [(size_t)Bb*Hh*Ss*(Dd/2)];   // per-hash outputs, fp16x2
__device__ float g_logits[Bb*Hh*Ss];

// ---------------- 1) LSH hashing (bit-exact f-sequential accumulation) -------
// TT=32 tokens/block halves rot L2 traffic; also emits the float buckets output.
#define TT 32
#define QT_STRIDE 34
__global__ void __launch_bounds__(256) hash_kernel(
    const float* __restrict__ qk, const float* __restrict__ rot,
    float* __restrict__ outb)
{
    __shared__ float qsT[64*QT_STRIDE];

    int blocksPerB = Ss / TT;                 // 128
    int b  = blockIdx.x / blocksPerB;
    int t0 = (blockIdx.x % blocksPerB) * TT;
    int tid = threadIdx.x;

    {
        int f = tid & 63;
        int i0 = tid >> 6;
        #pragma unroll
        for (int i = i0; i < TT; i += 4)
            qsT[f*QT_STRIDE + i] = qk[((size_t)b*Ss + t0 + i)*Dd + f];
    }
    __syncthreads();

    const float* rb = rot + (size_t)b*64*256 + tid;

    ull acc2[TT/2];
    #pragma unroll
    for (int ip = 0; ip < TT/2; ip++) acc2[ip] = 0ull;
    #pragma unroll 4
    for (int f = 0; f < 64; f++) {
        float rv = __ldg(rb + f*256);
        ull rv2 = pack2(rv, rv);
        #pragma unroll
        for (int ip = 0; ip < TT/2; ip++)
            acc2[ip] = ffma2(ld64s(qsT + f*QT_STRIDE + 2*ip), rv2, acc2[ip]);
    }

    int lane = tid & 31;
    int h    = tid >> 5;
    #pragma unroll
    for (int ip = 0; ip < TT/2; ip++) {
        float va[2];
        unpack2(acc2[ip], va[0], va[1]);
        #pragma unroll
        for (int s = 0; s < 2; s++) {
            float v = va[s];
            float val; int idx;
            if (v >= -v) { val = v;  idx = lane; }
            else         { val = -v; idx = lane + 32; }
            #pragma unroll
            for (int m = 16; m > 0; m >>= 1) {
                float ov = __shfl_xor_sync(0xffffffffu, val, m);
                int   oi = __shfl_xor_sync(0xffffffffu, idx, m);
                if (ov > val || (ov == val && oi < idx)) { val = ov; idx = oi; }
            }
            if (lane == 0) {
                int pos = ((size_t)b*Hh + h)*Ss + t0 + 2*ip + s;
                g_bucket[pos] = idx;
                if (outb) outb[pos] = (float)(idx + h*NB);
            }
        }
    }
}

// ---------------- 2) stable counting sort per (b,h), ballot-ranked ----------
__global__ void __launch_bounds__(256) sort_kernel()
{
    __shared__ int sb[Ss];
    __shared__ int cnt[NB];
    __shared__ int offs[NB + 1];
    int bh   = blockIdx.x;
    int tid  = threadIdx.x;
    int lane = tid & 31;
    int w    = tid >> 5;
    const int base = bh * Ss;

    if (tid < NB) cnt[tid] = 0;
    __syncthreads();
    for (int i = tid; i < Ss; i += 256) {
        int v = g_bucket[base + i];
        sb[i] = v;
        atomicAdd(&cnt[v], 1);
    }
    __syncthreads();
    if (tid == 0) {
        offs[0] = 0;
        for (int k = 0; k < NB; k++) offs[k+1] = offs[k] + cnt[k];
    }
    __syncthreads();

    int off[8];
    #pragma unroll
    for (int k = 0; k < 8; k++) off[k] = offs[8*w + k];

    for (int step = 0; step < Ss/32; step++) {
        int t   = step*32 + lane;
        int rel = sb[t] - 8*w;
        #pragma unroll
        for (int k = 0; k < 8; k++) {
            unsigned mask = __ballot_sync(0xffffffffu, rel == k);
            if (rel == k) {
                int pos = off[k] + __popc(mask & ((1u << lane) - 1u));
                g_perm[base + pos] = t;
            }
            off[k] += __popc(mask);
        }
    }
}

// ---------------- 3) chunked attention: tf32 QK + fp16 PV (2 terms) ---------
#define KS_LD 68
#define PH_LD 68                      // 64 data words (128 cols) + 4 pad
#define SM_KS   0
#define SM_PH   0                     // overlay ks (word offsets)
#define SM_VH   (128*KS_LD)           // float offset 8704
#define SM_VL   (SM_VH + 64*136/2)    // +4352 = 13056
#define SM_PM   (SM_VL + 64*136/2)    // 17408
#define SM_PS   (SM_PM + 128)
#define SM_QSC  (SM_PS + 128)
#define SM_TK   (SM_QSC + 64)
#define ATTN_SMEM ((SM_TK + 128) * 4) // 71424 bytes
__global__ void __launch_bounds__(256, 3) attn_kernel(
    const float* __restrict__ qk, const float* __restrict__ v)
{
    extern __shared__ float sm[];
    float* ks  = sm + SM_KS;
    uint*  ph2 = (uint*)(sm + SM_PH);   // fp16x2 probs words
    uint*  vhw = (uint*)(sm + SM_VH);   // fp16x2 V hi
    uint*  vlw = (uint*)(sm + SM_VL);   // fp16x2 V lo
    float* pm  = sm + SM_PM;
    float* ps  = sm + SM_PS;
    float* qsc = sm + SM_QSC;
    int*   tk  = (int*)(sm + SM_TK);

    int b = blockIdx.x >> 9;
    int c = blockIdx.x & (NCHUNK - 1);
    int h = c >> 6;
    int cprev = (c + NCHUNK - 1) & (NCHUNK - 1);
    int tid = threadIdx.x;
    const int pbase = b * (Hh * Ss);

    if (tid < 64)        tk[tid] = g_perm[pbase + c*64 + tid];
    else if (tid < 128)  tk[tid] = g_perm[pbase + cprev*64 + (tid - 64)];
    __syncthreads();

    const float* qkb = qk + (size_t)b*Ss*Dd;
    const float* vb  = v  + (size_t)b*Ss*Dd;

    // ---- fused gather + normalize ----
    // thread = (col-quad q4, row-pair rp); half-warp holds a full row -> norms
    // via width-16 shfl reduce. Q stored normalized tf32 (STS.128); V split
    // fp16 hi/lo pair-packed along k (STS.32).
    {
        int q4 = tid & 15;
        int rp = tid >> 4;
        int c0 = q4*4;
        #pragma unroll
        for (int halfp = 0; halfp < 2; halfp++) {
            float4 xq[2][2], xv[2][2];
            int r0s[2];
            #pragma unroll
            for (int p = 0; p < 2; p++) {
                int r0 = 32*(2*halfp + p) + 2*rp;
                r0s[p] = r0;
                int t0 = tk[r0], t1 = tk[r0 + 1];
                xq[p][0] = *(const float4*)(qkb + (size_t)t0*Dd + c0);
                xq[p][1] = *(const float4*)(qkb + (size_t)t1*Dd + c0);
                xv[p][0] = *(const float4*)(vb  + (size_t)t0*Dd + c0);
                xv[p][1] = *(const float4*)(vb  + (size_t)t1*Dd + c0);
            }
            #pragma unroll
            for (int p = 0; p < 2; p++) {
                int r0 = r0s[p], r1 = r0 + 1;
                float ss0 = xq[p][0].x*xq[p][0].x + xq[p][0].y*xq[p][0].y
                          + xq[p][0].z*xq[p][0].z + xq[p][0].w*xq[p][0].w;
                float ss1 = xq[p][1].x*xq[p][1].x + xq[p][1].y*xq[p][1].y
                          + xq[p][1].z*xq[p][1].z + xq[p][1].w*xq[p][1].w;
                #pragma unroll
                for (int s = 1; s < 16; s <<= 1) {
                    ss0 += __shfl_xor_sync(0xffffffffu, ss0, s, 16);
                    ss1 += __shfl_xor_sync(0xffffffffu, ss1, s, 16);
                }
                float n0 = sqrtf(ss0) + 1e-6f, n1 = sqrtf(ss1) + 1e-6f;
                float i0 = 1.0f/n0, i1 = 1.0f/n1;
                float4 q0, q1;
                q0.x = __uint_as_float(cvt_tf32(xq[p][0].x * i0));
                q0.y = __uint_as_float(cvt_tf32(xq[p][0].y * i0));
                q0.z = __uint_as_float(cvt_tf32(xq[p][0].z * i0));
                q0.w = __uint_as_float(cvt_tf32(xq[p][0].w * i0));
                q1.x = __uint_as_float(cvt_tf32(xq[p][1].x * i1));
                q1.y = __uint_as_float(cvt_tf32(xq[p][1].y * i1));
                q1.z = __uint_as_float(cvt_tf32(xq[p][1].z * i1));
                q1.w = __uint_as_float(cvt_tf32(xq[p][1].w * i1));
                *(float4*)(ks + r0*KS_LD + c0) = q0;
                *(float4*)(ks + r1*KS_LD + c0) = q1;
                if (r0 < 64 && q4 == 0) {
                    qsc[r0] = n0 * 0.125f;
                    qsc[r1] = n1 * 0.125f;
                }
                int kp = r0 >> 1;
                float v0a[4] = {xv[p][0].x, xv[p][0].y, xv[p][0].z, xv[p][0].w};
                float v1a[4] = {xv[p][1].x, xv[p][1].y, xv[p][1].z, xv[p][1].w};
                #pragma unroll
                for (int cc = 0; cc < 4; cc++) {
                    int e = c0 + cc;
                    int w = e*68 + (kp ^ (e >> 2));
                    float h0f = __half2float(__float2half_rn(v0a[cc]));
                    float h1f = __half2float(__float2half_rn(v1a[cc]));
                    vhw[w] = pack_f16x2(h0f, h1f);
                    vlw[w] = pack_f16x2(v0a[cc] - h0f, v1a[cc] - h1f);
                }
            }
        }
    }
    __syncthreads();

    // ---- QK^T : 64x128x64 tf32, per warp m16 x n64 ----
    int wid   = tid >> 5;
    int lane  = tid & 31;
    int gr    = lane >> 2;
    int cl    = lane & 3;
    int mrow  = 16*(wid & 3);
    int chalf = wid >> 2;
    int ncol  = 64*chalf;

    float acc[8][4];
    #pragma unroll
    for (int n = 0; n < 8; n++)
        #pragma unroll
        for (int i = 0; i < 4; i++) acc[n][i] = 0.f;

    #pragma unroll 2
    for (int k0 = 0; k0 < 8; k0++) {
        const float* ab = ks + (mrow + gr)*KS_LD + 8*k0 + cl;
        uint a0 = ldu(ab), a1 = ldu(ab + 8*KS_LD), a2 = ldu(ab + 4), a3 = ldu(ab + 8*KS_LD + 4);
        #pragma unroll
        for (int n = 0; n < 8; n++) {
            const float* bbp = ks + (ncol + 8*n + gr)*KS_LD + 8*k0 + cl;
            uint b0 = ldu(bbp), b1 = ldu(bbp + 4);
            mma_tf32(acc[n], a0, a1, a2, a3, b0, b1);
        }
    }

    // ---- mask + scale + per-half softmax partials ----
    int row0 = mrow + gr, row1 = row0 + 8;
    int tr0 = tk[row0], tr1 = tk[row1];
    float sc0 = qsc[row0], sc1 = qsc[row1];
    float m0 = -1e30f, m1 = -1e30f;
    #pragma unroll
    for (int n = 0; n < 8; n++) {
        int j0 = ncol + 8*n + 2*cl;
        int tj0 = tk[j0], tj1 = tk[j0 + 1];
        float d0 = (tj0 == tr0) ? NEGV : acc[n][0]*sc0;
        float d1 = (tj1 == tr0) ? NEGV : acc[n][1]*sc0;
        float d2 = (tj0 == tr1) ? NEGV : acc[n][2]*sc1;
        float d3 = (tj1 == tr1) ? NEGV : acc[n][3]*sc1;
        acc[n][0] = d0; acc[n][1] = d1; acc[n][2] = d2; acc[n][3] = d3;
        m0 = fmaxf(m0, fmaxf(d0, d1));
        m1 = fmaxf(m1, fmaxf(d2, d3));
    }
    #pragma unroll
    for (int s = 1; s < 4; s <<= 1) {
        m0 = fmaxf(m0, __shfl_xor_sync(0xffffffffu, m0, s));
        m1 = fmaxf(m1, __shfl_xor_sync(0xffffffffu, m1, s));
    }
    float s0 = 0.f, s1 = 0.f;
    #pragma unroll
    for (int n = 0; n < 8; n++) {
        float e0 = __expf(acc[n][0] - m0);
        float e1 = __expf(acc[n][1] - m0);
        float e2 = __expf(acc[n][2] - m1);
        float e3 = __expf(acc[n][3] - m1);
        acc[n][0] = e0; acc[n][1] = e1; acc[n][2] = e2; acc[n][3] = e3;
        s0 += e0 + e1;
        s1 += e2 + e3;
    }
    #pragma unroll
    for (int s = 1; s < 4; s <<= 1) {
        s0 += __shfl_xor_sync(0xffffffffu, s0, s);
        s1 += __shfl_xor_sync(0xffffffffu, s1, s);
    }
    if (cl == 0) {
        pm[chalf*64 + row0] = m0;  ps[chalf*64 + row0] = s0;
        pm[chalf*64 + row1] = m1;  ps[chalf*64 + row1] = s1;
    }
    __syncthreads();   // partials visible; ALL warps done reading ks

    float Ma0 = pm[row0], Mb0 = pm[64 + row0];
    float M0  = fmaxf(Ma0, Mb0);
    float S0  = ps[row0]*__expf(Ma0 - M0) + ps[64 + row0]*__expf(Mb0 - M0);
    float lse0 = M0 + __logf(S0);
    float Ma1 = pm[row1], Mb1 = pm[64 + row1];
    float M1  = fmaxf(Ma1, Mb1);
    float S1  = ps[row1]*__expf(Ma1 - M1) + ps[64 + row1]*__expf(Mb1 - M1);
    float lse1 = M1 + __logf(S1);

    if (cl == 0 && chalf == 0) {
        g_logits[pbase + h*Ss + tr0] = lse0;
        g_logits[pbase + h*Ss + tr1] = lse1;
    }

    // probs = e * exp(m - lse) as single fp16x2 packed pairs (overlay ks)
    {
        float f0 = __expf(m0 - lse0);
        float f1 = __expf(m1 - lse1);
        int pw0 = row0*PH_LD + (ncol >> 1) + cl;
        int pw1 = row1*PH_LD + (ncol >> 1) + cl;
        #pragma unroll
        for (int n = 0; n < 8; n++) {
            ph2[pw0 + 4*n] = pack_f16x2(acc[n][0] * f0, acc[n][1] * f0);
            ph2[pw1 + 4*n] = pack_f16x2(acc[n][2] * f1, acc[n][3] * f1);
        }
    }
    __syncthreads();

    // ---- PV : 64x64x128, fp16 2 terms (P*Vh + P*Vl), m16n8k16, m16 x n32 ----
    int ocol = 32*chalf;
    float oacc[4][4];
    #pragma unroll
    for (int n = 0; n < 4; n++)
        #pragma unroll
        for (int i = 0; i < 4; i++) oacc[n][i] = 0.f;

    int ebase[4], sxor[4];
    #pragma unroll
    for (int n = 0; n < 4; n++) {
        int e = ocol + 8*n + gr;
        ebase[n] = e*68;        // word stride = 68 (136 halves)
        sxor[n]  = e >> 2;
    }
    const uint* ph2r0 = ph2 + row0*PH_LD;
    const uint* ph2r1 = ph2 + row1*PH_LD;

    #pragma unroll 1
    for (int k0 = 0; k0 < 8; k0++) {
        int wa = 8*k0 + cl;
        uint ah0 = ph2r0[wa], ah1 = ph2r1[wa], ah2 = ph2r0[wa+4], ah3 = ph2r1[wa+4];
        #pragma unroll
        for (int n = 0; n < 4; n++) {
            int w0 = ebase[n] + (wa ^ sxor[n]);
            int w1 = ebase[n] + ((wa + 4) ^ sxor[n]);
            uint bh0 = vhw[w0], bh1 = vhw[w1];
            uint bl0 = vlw[w0], bl1 = vlw[w1];
            mma_f16(oacc[n], ah0, ah1, ah2, ah3, bh0, bh1);
            mma_f16(oacc[n], ah0, ah1, ah2, ah3, bl0, bl1);
        }
    }

    // ---- scatter to g_o16 (fp16x2) ----
    {
        uint* orow0 = g_o16 + (size_t)(pbase + h*Ss + tr0)*(Dd/2);
        uint* orow1 = g_o16 + (size_t)(pbase + h*Ss + tr1)*(Dd/2);
        #pragma unroll
        for (int n = 0; n < 4; n++) {
            int wcol = (ocol >> 1) + 4*n + cl;
            orow0[wcol] = pack_f16x2(oacc[n][0], oacc[n][1]);
            orow1[wcol] = pack_f16x2(oacc[n][2], oacc[n][3]);
        }
    }
}

// ---------------- 4) combine hash rounds via softmax(logits) ----------------
__global__ void __launch_bounds__(256) combine_kernel(float* __restrict__ out)
{
    size_t gid = (size_t)blockIdx.x*256 + threadIdx.x;
    if (gid >= (size_t)Bb*Ss*Dd/8) return;
    int pair = (int)(gid & 7);
    size_t bt = gid >> 3;
    int t = (int)(bt & (Ss - 1));
    int b = (int)(bt >> 12);

    float l[Hh];
    float m = -1e30f;
    #pragma unroll
    for (int h = 0; h < Hh; h++) {
        l[h] = g_logits[((size_t)(b*Hh + h))*Ss + t];
        m = fmaxf(m, l[h]);
    }
    float ssum = 0.f;
    #pragma unroll
    for (int h = 0; h < Hh; h++) { l[h] = __expf(l[h] - m); ssum += l[h]; }
    float inv = 1.f / ssum;

    float4 acc0 = make_float4(0.f, 0.f, 0.f, 0.f);
    float4 acc1 = make_float4(0.f, 0.f, 0.f, 0.f);
    #pragma unroll
    for (int h = 0; h < Hh; h++) {
        float w = l[h]*inv;
        const uint4 ow = *(const uint4*)(g_o16 + (((size_t)(b*Hh + h))*Ss + t)*(Dd/2) + pair*4);
        float2 f0 = __half22float2(*(const __half2*)&ow.x);
        float2 f1 = __half22float2(*(const __half2*)&ow.y);
        float2 f2 = __half22float2(*(const __half2*)&ow.z);
        float2 f3 = __half22float2(*(const __half2*)&ow.w);
        acc0.x += w*f0.x; acc0.y += w*f0.y; acc0.z += w*f1.x; acc0.w += w*f1.y;
        acc1.x += w*f2.x; acc1.y += w*f2.y; acc1.z += w*f3.x; acc1.w += w*f3.y;
    }
    float* dst = out + bt*Dd + pair*8;
    *(float4*)(dst)     = acc0;
    *(float4*)(dst + 4) = acc1;
}

// ---------------- launch ------------------------------------------------------
extern "C" void kernel_launch(void* const* d_in, const int* in_sizes, int n_in,
                              void* d_out, int out_size)
{
    const float* qk  = (const float*)d_in[0];
    const float* v   = (const float*)d_in[1];
    const float* rot = (const float*)d_in[2];
    float* out = (float*)d_out;

    cudaFuncSetAttribute(attn_kernel, cudaFuncAttributeMaxDynamicSharedMemorySize, ATTN_SMEM);

    float* outb = (out_size >= Bb*Ss*Dd + Bb*Hh*Ss) ? (out + (size_t)Bb*Ss*Dd) : nullptr;

    hash_kernel<<<Bb*(Ss/TT), 256>>>(qk, rot, outb);
    sort_kernel<<<Bb*Hh, 256>>>();
    attn_kernel<<<Bb*NCHUNK, 256, ATTN_SMEM>>>(qk, v);
    combine_kernel<<<(int)(((size_t)Bb*Ss*Dd/8 + 255)/256), 256>>>(out);
}

// round 14
// speedup vs baseline: 2.4515x; 1.1101x over previous
#include <cuda_runtime.h>
#include <cuda_bf16.h>
#include <cuda_fp16.h>
#include <math.h>
#include <stdint.h>

#define Bb 16
#define Ss 4096
#define Dd 64
#define Hh 8
#define NB 64          // buckets per hash
#define NCHUNK 512     // Hh * NB
#define NEGV (-50000.0f)

typedef unsigned long long ull;
typedef unsigned int uint;

// ---------------- f32x2 packed-math helpers (sm_103a) -----------------------
__device__ __forceinline__ ull ffma2(ull a, ull b, ull c) {
    ull d;
    asm("fma.rn.f32x2 %0, %1, %2, %3;" : "=l"(d) : "l"(a), "l"(b), "l"(c));
    return d;
}
__device__ __forceinline__ ull pack2(float lo, float hi) {
    ull r;
    asm("mov.b64 %0, {%1, %2};" : "=l"(r) : "f"(lo), "f"(hi));
    return r;
}
__device__ __forceinline__ void unpack2(ull v, float& lo, float& hi) {
    asm("mov.b64 {%0, %1}, %2;" : "=f"(lo), "=f"(hi) : "l"(v));
}
__device__ __forceinline__ ull ld64s(const float* p) {
    return *(const ull*)p;
}

// ---------------- mma helpers -------------------------------------------------
__device__ __forceinline__ void mma_f16(float* c,
    uint a0, uint a1, uint a2, uint a3, uint b0, uint b1)
{
    asm("mma.sync.aligned.m16n8k16.row.col.f32.f16.f16.f32 "
        "{%0,%1,%2,%3}, {%4,%5,%6,%7}, {%8,%9}, {%0,%1,%2,%3};"
        : "+f"(c[0]), "+f"(c[1]), "+f"(c[2]), "+f"(c[3])
        : "r"(a0), "r"(a1), "r"(a2), "r"(a3), "r"(b0), "r"(b1));
}
// pack two f32 -> f16x2 word: lower half = 'lo' (even k), upper half = 'hi'
__device__ __forceinline__ uint pack_f16x2(float lo, float hi) {
    __half2 h = __floats2half2_rn(lo, hi);
    return *(uint*)&h;
}

// ---------------- device scratch ---------------------------------------------
__device__ int   g_bucket[Bb*Hh*Ss];
__device__ int   g_perm  [Bb*Hh*Ss];
__device__ uint  g_o16 [(size_t)Bb*Hh*Ss*(Dd/2)];   // per-hash outputs, fp16x2
__device__ float g_logits[Bb*Hh*Ss];

// ---------------- 1) LSH hashing (bit-exact f-sequential accumulation) -------
#define TT 32
#define QT_STRIDE 34
__global__ void __launch_bounds__(256) hash_kernel(
    const float* __restrict__ qk, const float* __restrict__ rot,
    float* __restrict__ outb)
{
    __shared__ float qsT[64*QT_STRIDE];

    int blocksPerB = Ss / TT;                 // 128
    int b  = blockIdx.x / blocksPerB;
    int t0 = (blockIdx.x % blocksPerB) * TT;
    int tid = threadIdx.x;

    {
        int f = tid & 63;
        int i0 = tid >> 6;
        #pragma unroll
        for (int i = i0; i < TT; i += 4)
            qsT[f*QT_STRIDE + i] = qk[((size_t)b*Ss + t0 + i)*Dd + f];
    }
    __syncthreads();

    const float* rb = rot + (size_t)b*64*256 + tid;

    ull acc2[TT/2];
    #pragma unroll
    for (int ip = 0; ip < TT/2; ip++) acc2[ip] = 0ull;
    #pragma unroll 4
    for (int f = 0; f < 64; f++) {
        float rv = __ldg(rb + f*256);
        ull rv2 = pack2(rv, rv);
        #pragma unroll
        for (int ip = 0; ip < TT/2; ip++)
            acc2[ip] = ffma2(ld64s(qsT + f*QT_STRIDE + 2*ip), rv2, acc2[ip]);
    }

    int lane = tid & 31;
    int h    = tid >> 5;
    #pragma unroll
    for (int ip = 0; ip < TT/2; ip++) {
        float va[2];
        unpack2(acc2[ip], va[0], va[1]);
        #pragma unroll
        for (int s = 0; s < 2; s++) {
            float v = va[s];
            float val; int idx;
            if (v >= -v) { val = v;  idx = lane; }
            else         { val = -v; idx = lane + 32; }
            #pragma unroll
            for (int m = 16; m > 0; m >>= 1) {
                float ov = __shfl_xor_sync(0xffffffffu, val, m);
                int   oi = __shfl_xor_sync(0xffffffffu, idx, m);
                if (ov > val || (ov == val && oi < idx)) { val = ov; idx = oi; }
            }
            if (lane == 0) {
                int pos = ((size_t)b*Hh + h)*Ss + t0 + 2*ip + s;
                g_bucket[pos] = idx;
                if (outb) outb[pos] = (float)(idx + h*NB);
            }
        }
    }
}

// ---------------- 2) stable counting sort per (b,h), ballot-ranked ----------
__global__ void __launch_bounds__(256) sort_kernel()
{
    __shared__ int sb[Ss];
    __shared__ int cnt[NB];
    __shared__ int offs[NB + 1];
    int bh   = blockIdx.x;
    int tid  = threadIdx.x;
    int lane = tid & 31;
    int w    = tid >> 5;
    const int base = bh * Ss;

    if (tid < NB) cnt[tid] = 0;
    __syncthreads();
    for (int i = tid; i < Ss; i += 256) {
        int v = g_bucket[base + i];
        sb[i] = v;
        atomicAdd(&cnt[v], 1);
    }
    __syncthreads();
    if (tid == 0) {
        offs[0] = 0;
        for (int k = 0; k < NB; k++) offs[k+1] = offs[k] + cnt[k];
    }
    __syncthreads();

    int off[8];
    #pragma unroll
    for (int k = 0; k < 8; k++) off[k] = offs[8*w + k];

    for (int step = 0; step < Ss/32; step++) {
        int t   = step*32 + lane;
        int rel = sb[t] - 8*w;
        #pragma unroll
        for (int k = 0; k < 8; k++) {
            unsigned mask = __ballot_sync(0xffffffffu, rel == k);
            if (rel == k) {
                int pos = off[k] + __popc(mask & ((1u << lane) - 1u));
                g_perm[base + pos] = t;
            }
            off[k] += __popc(mask);
        }
    }
}

// ---------------- 3) chunked attention: fp16 QK + fp16 PV (2-term V) --------
// ks16[128][36w] : normalized K as fp16x2 f-pairs; rows 0..63 double as Q
// ph2[64][68w]   : fp16x2 probs (overlays ks16 after QK)
// vhw/vlw        : V split fp16 hi/lo, transposed [col][k-pair], swizzled
// All offsets in 32-bit words.
#define KS16_LD 36
#define PH_LD 68
#define SM_KS16 0
#define SM_PH   0                       // overlay
#define SM_VH   (128*KS16_LD)           // 4608
#define SM_VL   (SM_VH + 64*68)         // 8960
#define SM_PM   (SM_VL + 64*68)         // 13312
#define SM_PS   (SM_PM + 128)
#define SM_QSC  (SM_PS + 128)
#define SM_TK   (SM_QSC + 64)
#define ATTN_SMEM ((SM_TK + 128) * 4)   // 55040 bytes
__global__ void __launch_bounds__(256, 4) attn_kernel(
    const float* __restrict__ qk, const float* __restrict__ v)
{
    extern __shared__ float sm[];
    uint*  ks16 = (uint*)(sm + SM_KS16);
    uint*  ph2  = (uint*)(sm + SM_PH);
    uint*  vhw  = (uint*)(sm + SM_VH);
    uint*  vlw  = (uint*)(sm + SM_VL);
    float* pm   = sm + SM_PM;
    float* ps   = sm + SM_PS;
    float* qsc  = sm + SM_QSC;
    int*   tk   = (int*)(sm + SM_TK);

    int b = blockIdx.x >> 9;
    int c = blockIdx.x & (NCHUNK - 1);
    int h = c >> 6;
    int cprev = (c + NCHUNK - 1) & (NCHUNK - 1);
    int tid = threadIdx.x;
    const int pbase = b * (Hh * Ss);

    if (tid < 64)        tk[tid] = g_perm[pbase + c*64 + tid];
    else if (tid < 128)  tk[tid] = g_perm[pbase + cprev*64 + (tid - 64)];
    __syncthreads();

    const float* qkb = qk + (size_t)b*Ss*Dd;
    const float* vb  = v  + (size_t)b*Ss*Dd;

    // ---- fused gather + normalize ----
    // thread = (col-quad q4, row-pair rp); half-warp holds a full row -> norms
    // via width-16 shfl. K stored normalized fp16x2 f-pairs; V split fp16 hi/lo.
    {
        int q4 = tid & 15;
        int rp = tid >> 4;
        int c0 = q4*4;
        #pragma unroll
        for (int halfp = 0; halfp < 2; halfp++) {
            float4 xq[2][2], xv[2][2];
            int r0s[2];
            #pragma unroll
            for (int p = 0; p < 2; p++) {
                int r0 = 32*(2*halfp + p) + 2*rp;
                r0s[p] = r0;
                int t0 = tk[r0], t1 = tk[r0 + 1];
                xq[p][0] = *(const float4*)(qkb + (size_t)t0*Dd + c0);
                xq[p][1] = *(const float4*)(qkb + (size_t)t1*Dd + c0);
                xv[p][0] = *(const float4*)(vb  + (size_t)t0*Dd + c0);
                xv[p][1] = *(const float4*)(vb  + (size_t)t1*Dd + c0);
            }
            #pragma unroll
            for (int p = 0; p < 2; p++) {
                int r0 = r0s[p], r1 = r0 + 1;
                float ss0 = xq[p][0].x*xq[p][0].x + xq[p][0].y*xq[p][0].y
                          + xq[p][0].z*xq[p][0].z + xq[p][0].w*xq[p][0].w;
                float ss1 = xq[p][1].x*xq[p][1].x + xq[p][1].y*xq[p][1].y
                          + xq[p][1].z*xq[p][1].z + xq[p][1].w*xq[p][1].w;
                #pragma unroll
                for (int s = 1; s < 16; s <<= 1) {
                    ss0 += __shfl_xor_sync(0xffffffffu, ss0, s, 16);
                    ss1 += __shfl_xor_sync(0xffffffffu, ss1, s, 16);
                }
                float n0 = sqrtf(ss0) + 1e-6f, n1 = sqrtf(ss1) + 1e-6f;
                float i0 = 1.0f/n0, i1 = 1.0f/n1;
                // normalized K rows as fp16x2 (f-pairs c0/2, c0/2+1)
                int kw = c0 >> 1;
                ks16[r0*KS16_LD + kw    ] = pack_f16x2(xq[p][0].x*i0, xq[p][0].y*i0);
                ks16[r0*KS16_LD + kw + 1] = pack_f16x2(xq[p][0].z*i0, xq[p][0].w*i0);
                ks16[r1*KS16_LD + kw    ] = pack_f16x2(xq[p][1].x*i1, xq[p][1].y*i1);
                ks16[r1*KS16_LD + kw + 1] = pack_f16x2(xq[p][1].z*i1, xq[p][1].w*i1);
                if (r0 < 64 && q4 == 0) {
                    qsc[r0] = n0 * 0.125f;
                    qsc[r1] = n1 * 0.125f;
                }
                int kp = r0 >> 1;
                float v0a[4] = {xv[p][0].x, xv[p][0].y, xv[p][0].z, xv[p][0].w};
                float v1a[4] = {xv[p][1].x, xv[p][1].y, xv[p][1].z, xv[p][1].w};
                #pragma unroll
                for (int cc = 0; cc < 4; cc++) {
                    int e = c0 + cc;
                    int w = e*68 + (kp ^ (e >> 2));
                    float h0f = __half2float(__float2half_rn(v0a[cc]));
                    float h1f = __half2float(__float2half_rn(v1a[cc]));
                    vhw[w] = pack_f16x2(h0f, h1f);
                    vlw[w] = pack_f16x2(v0a[cc] - h0f, v1a[cc] - h1f);
                }
            }
        }
    }
    __syncthreads();

    // ---- QK^T : 64x128x64 fp16 m16n8k16, per warp m16 x n64 ----
    int wid   = tid >> 5;
    int lane  = tid & 31;
    int gr    = lane >> 2;
    int cl    = lane & 3;
    int mrow  = 16*(wid & 3);
    int chalf = wid >> 2;
    int ncol  = 64*chalf;

    float acc[8][4];
    #pragma unroll
    for (int n = 0; n < 8; n++)
        #pragma unroll
        for (int i = 0; i < 4; i++) acc[n][i] = 0.f;

    {
        const uint* ar0 = ks16 + (mrow + gr)*KS16_LD;
        const uint* ar1 = ar0 + 8*KS16_LD;
        #pragma unroll
        for (int k0 = 0; k0 < 4; k0++) {
            int wa = 8*k0 + cl;
            uint a0 = ar0[wa], a1 = ar1[wa], a2 = ar0[wa+4], a3 = ar1[wa+4];
            #pragma unroll
            for (int n = 0; n < 8; n++) {
                const uint* bp = ks16 + (ncol + 8*n + gr)*KS16_LD;
                uint b0 = bp[wa], b1 = bp[wa+4];
                mma_f16(acc[n], a0, a1, a2, a3, b0, b1);
            }
        }
    }

    // ---- mask + scale + per-half softmax partials ----
    int row0 = mrow + gr, row1 = row0 + 8;
    int tr0 = tk[row0], tr1 = tk[row1];
    float sc0 = qsc[row0], sc1 = qsc[row1];
    float m0 = -1e30f, m1 = -1e30f;
    #pragma unroll
    for (int n = 0; n < 8; n++) {
        int j0 = ncol + 8*n + 2*cl;
        int tj0 = tk[j0], tj1 = tk[j0 + 1];
        float d0 = (tj0 == tr0) ? NEGV : acc[n][0]*sc0;
        float d1 = (tj1 == tr0) ? NEGV : acc[n][1]*sc0;
        float d2 = (tj0 == tr1) ? NEGV : acc[n][2]*sc1;
        float d3 = (tj1 == tr1) ? NEGV : acc[n][3]*sc1;
        acc[n][0] = d0; acc[n][1] = d1; acc[n][2] = d2; acc[n][3] = d3;
        m0 = fmaxf(m0, fmaxf(d0, d1));
        m1 = fmaxf(m1, fmaxf(d2, d3));
    }
    #pragma unroll
    for (int s = 1; s < 4; s <<= 1) {
        m0 = fmaxf(m0, __shfl_xor_sync(0xffffffffu, m0, s));
        m1 = fmaxf(m1, __shfl_xor_sync(0xffffffffu, m1, s));
    }
    float s0 = 0.f, s1 = 0.f;
    #pragma unroll
    for (int n = 0; n < 8; n++) {
        float e0 = __expf(acc[n][0] - m0);
        float e1 = __expf(acc[n][1] - m0);
        float e2 = __expf(acc[n][2] - m1);
        float e3 = __expf(acc[n][3] - m1);
        acc[n][0] = e0; acc[n][1] = e1; acc[n][2] = e2; acc[n][3] = e3;
        s0 += e0 + e1;
        s1 += e2 + e3;
    }
    #pragma unroll
    for (int s = 1; s < 4; s <<= 1) {
        s0 += __shfl_xor_sync(0xffffffffu, s0, s);
        s1 += __shfl_xor_sync(0xffffffffu, s1, s);
    }
    if (cl == 0) {
        pm[chalf*64 + row0] = m0;  ps[chalf*64 + row0] = s0;
        pm[chalf*64 + row1] = m1;  ps[chalf*64 + row1] = s1;
    }
    __syncthreads();   // partials visible; ALL warps done reading ks16

    float Ma0 = pm[row0], Mb0 = pm[64 + row0];
    float M0  = fmaxf(Ma0, Mb0);
    float S0  = ps[row0]*__expf(Ma0 - M0) + ps[64 + row0]*__expf(Mb0 - M0);
    float lse0 = M0 + __logf(S0);
    float Ma1 = pm[row1], Mb1 = pm[64 + row1];
    float M1  = fmaxf(Ma1, Mb1);
    float S1  = ps[row1]*__expf(Ma1 - M1) + ps[64 + row1]*__expf(Mb1 - M1);
    float lse1 = M1 + __logf(S1);

    if (cl == 0 && chalf == 0) {
        g_logits[pbase + h*Ss + tr0] = lse0;
        g_logits[pbase + h*Ss + tr1] = lse1;
    }

    // probs = e * exp(m - lse) as single fp16x2 packed pairs (overlay ks16)
    {
        float f0 = __expf(m0 - lse0);
        float f1 = __expf(m1 - lse1);
        int pw0 = row0*PH_LD + (ncol >> 1) + cl;
        int pw1 = row1*PH_LD + (ncol >> 1) + cl;
        #pragma unroll
        for (int n = 0; n < 8; n++) {
            ph2[pw0 + 4*n] = pack_f16x2(acc[n][0] * f0, acc[n][1] * f0);
            ph2[pw1 + 4*n] = pack_f16x2(acc[n][2] * f1, acc[n][3] * f1);
        }
    }
    __syncthreads();

    // ---- PV : 64x64x128, fp16 2 terms (P*Vh + P*Vl), m16n8k16, m16 x n32 ----
    int ocol = 32*chalf;
    float oacc[4][4];
    #pragma unroll
    for (int n = 0; n < 4; n++)
        #pragma unroll
        for (int i = 0; i < 4; i++) oacc[n][i] = 0.f;

    int ebase[4], sxor[4];
    #pragma unroll
    for (int n = 0; n < 4; n++) {
        int e = ocol + 8*n + gr;
        ebase[n] = e*68;
        sxor[n]  = e >> 2;
    }
    const uint* ph2r0 = ph2 + row0*PH_LD;
    const uint* ph2r1 = ph2 + row1*PH_LD;

    #pragma unroll 1
    for (int k0 = 0; k0 < 8; k0++) {
        int wa = 8*k0 + cl;
        uint ah0 = ph2r0[wa], ah1 = ph2r1[wa], ah2 = ph2r0[wa+4], ah3 = ph2r1[wa+4];
        #pragma unroll
        for (int n = 0; n < 4; n++) {
            int w0 = ebase[n] + (wa ^ sxor[n]);
            int w1 = ebase[n] + ((wa + 4) ^ sxor[n]);
            uint bh0 = vhw[w0], bh1 = vhw[w1];
            uint bl0 = vlw[w0], bl1 = vlw[w1];
            mma_f16(oacc[n], ah0, ah1, ah2, ah3, bh0, bh1);
            mma_f16(oacc[n], ah0, ah1, ah2, ah3, bl0, bl1);
        }
    }

    // ---- scatter to g_o16 (fp16x2) ----
    {
        uint* orow0 = g_o16 + (size_t)(pbase + h*Ss + tr0)*(Dd/2);
        uint* orow1 = g_o16 + (size_t)(pbase + h*Ss + tr1)*(Dd/2);
        #pragma unroll
        for (int n = 0; n < 4; n++) {
            int wcol = (ocol >> 1) + 4*n + cl;
            orow0[wcol] = pack_f16x2(oacc[n][0], oacc[n][1]);
            orow1[wcol] = pack_f16x2(oacc[n][2], oacc[n][3]);
        }
    }
}

// ---------------- 4) combine hash rounds via softmax(logits) ----------------
__global__ void __launch_bounds__(256) combine_kernel(float* __restrict__ out)
{
    size_t gid = (size_t)blockIdx.x*256 + threadIdx.x;
    if (gid >= (size_t)Bb*Ss*Dd/8) return;
    int pair = (int)(gid & 7);
    size_t bt = gid >> 3;
    int t = (int)(bt & (Ss - 1));
    int b = (int)(bt >> 12);

    float l[Hh];
    float m = -1e30f;
    #pragma unroll
    for (int h = 0; h < Hh; h++) {
        l[h] = g_logits[((size_t)(b*Hh + h))*Ss + t];
        m = fmaxf(m, l[h]);
    }
    float ssum = 0.f;
    #pragma unroll
    for (int h = 0; h < Hh; h++) { l[h] = __expf(l[h] - m); ssum += l[h]; }
    float inv = 1.f / ssum;

    float4 acc0 = make_float4(0.f, 0.f, 0.f, 0.f);
    float4 acc1 = make_float4(0.f, 0.f, 0.f, 0.f);
    #pragma unroll
    for (int h = 0; h < Hh; h++) {
        float w = l[h]*inv;
        const uint4 ow = *(const uint4*)(g_o16 + (((size_t)(b*Hh + h))*Ss + t)*(Dd/2) + pair*4);
        float2 f0 = __half22float2(*(const __half2*)&ow.x);
        float2 f1 = __half22float2(*(const __half2*)&ow.y);
        float2 f2 = __half22float2(*(const __half2*)&ow.z);
        float2 f3 = __half22float2(*(const __half2*)&ow.w);
        acc0.x += w*f0.x; acc0.y += w*f0.y; acc0.z += w*f1.x; acc0.w += w*f1.y;
        acc1.x += w*f2.x; acc1.y += w*f2.y; acc1.z += w*f3.x; acc1.w += w*f3.y;
    }
    float* dst = out + bt*Dd + pair*8;
    *(float4*)(dst)     = acc0;
    *(float4*)(dst + 4) = acc1;
}

// ---------------- launch ------------------------------------------------------
extern "C" void kernel_launch(void* const* d_in, const int* in_sizes, int n_in,
                              void* d_out, int out_size)
{
    const float* qk  = (const float*)d_in[0];
    const float* v   = (const float*)d_in[1];
    const float* rot = (const float*)d_in[2];
    float* out = (float*)d_out;

    cudaFuncSetAttribute(attn_kernel, cudaFuncAttributeMaxDynamicSharedMemorySize, ATTN_SMEM);

    float* outb = (out_size >= Bb*Ss*Dd + Bb*Hh*Ss) ? (out + (size_t)Bb*Ss*Dd) : nullptr;

    hash_kernel<<<Bb*(Ss/TT), 256>>>(qk, rot, outb);
    sort_kernel<<<Bb*Hh, 256>>>();
    attn_kernel<<<Bb*NCHUNK, 256, ATTN_SMEM>>>(qk, v);
    combine_kernel<<<(int)(((size_t)Bb*Ss*Dd/8 + 255)/256), 256>>>(out);
}

// round 15
// speedup vs baseline: 2.7748x; 1.1318x over previous
#include <cuda_runtime.h>
#include <cuda_fp16.h>
#include <math.h>
#include <stdint.h>

#define Bb 16
#define Ss 4096
#define Dd 64
#define Hh 8
#define NB 64          // buckets per hash
#define NCHUNK 512     // Hh * NB
#define NEGV (-50000.0f)

typedef unsigned long long ull;
typedef unsigned int uint;

// ---------------- f32x2 packed-math helpers (sm_103a) -----------------------
__device__ __forceinline__ ull ffma2(ull a, ull b, ull c) {
    ull d;
    asm("fma.rn.f32x2 %0, %1, %2, %3;" : "=l"(d) : "l"(a), "l"(b), "l"(c));
    return d;
}
__device__ __forceinline__ ull pack2(float lo, float hi) {
    ull r;
    asm("mov.b64 %0, {%1, %2};" : "=l"(r) : "f"(lo), "f"(hi));
    return r;
}
__device__ __forceinline__ void unpack2(ull v, float& lo, float& hi) {
    asm("mov.b64 {%0, %1}, %2;" : "=f"(lo), "=f"(hi) : "l"(v));
}
__device__ __forceinline__ ull ld64s(const float* p) {
    return *(const ull*)p;
}

// ---------------- mma helpers -------------------------------------------------
__device__ __forceinline__ void mma_f16(float* c,
    uint a0, uint a1, uint a2, uint a3, uint b0, uint b1)
{
    asm("mma.sync.aligned.m16n8k16.row.col.f32.f16.f16.f32 "
        "{%0,%1,%2,%3}, {%4,%5,%6,%7}, {%8,%9}, {%0,%1,%2,%3};"
        : "+f"(c[0]), "+f"(c[1]), "+f"(c[2]), "+f"(c[3])
        : "r"(a0), "r"(a1), "r"(a2), "r"(a3), "r"(b0), "r"(b1));
}
// pack two f32 -> f16x2 word: lower half = 'lo' (even k), upper half = 'hi'
__device__ __forceinline__ uint pack_f16x2(float lo, float hi) {
    __half2 h = __floats2half2_rn(lo, hi);
    return *(uint*)&h;
}

// ---------------- device scratch ---------------------------------------------
__device__ int   g_bucket[Bb*Hh*Ss];
__device__ int   g_perm  [Bb*Hh*Ss];
__device__ uint  g_o16 [(size_t)Bb*Hh*Ss*(Dd/2)];   // per-hash outputs, fp16x2
__device__ float g_logits[Bb*Hh*Ss];
__device__ uint  g_kn16[(size_t)Bb*Ss*(Dd/2)];      // normalized K-hat, fp16x2
__device__ uint  g_v16 [(size_t)Bb*Ss*(Dd/2)];      // V, fp16x2
__device__ float g_qs  [Bb*Ss];                     // (||q||+eps)*0.125

// ---------------- 0) per-token prep: normalize + fp16 conversion (once) ------
__global__ void __launch_bounds__(256) prep_kernel(
    const float* __restrict__ qk, const float* __restrict__ v)
{
    int tid = threadIdx.x;
    int q4  = tid & 15;
    size_t row = (size_t)blockIdx.x*16 + (tid >> 4);
    int c0 = q4*4;

    float4 xq = *(const float4*)(qk + row*Dd + c0);
    float4 xv = *(const float4*)(v  + row*Dd + c0);

    float ss = xq.x*xq.x + xq.y*xq.y + xq.z*xq.z + xq.w*xq.w;
    #pragma unroll
    for (int s = 1; s < 16; s <<= 1)
        ss += __shfl_xor_sync(0xffffffffu, ss, s, 16);
    float n = sqrtf(ss) + 1e-6f;
    float i = 1.0f / n;

    uint* kn = g_kn16 + row*(Dd/2) + q4*2;
    kn[0] = pack_f16x2(xq.x*i, xq.y*i);
    kn[1] = pack_f16x2(xq.z*i, xq.w*i);
    uint* vo = g_v16 + row*(Dd/2) + q4*2;
    vo[0] = pack_f16x2(xv.x, xv.y);
    vo[1] = pack_f16x2(xv.z, xv.w);
    if (q4 == 0) g_qs[row] = n * 0.125f;
}

// ---------------- 1) LSH hashing (bit-exact f-sequential accumulation) -------
#define TT 32
#define QT_STRIDE 34
__global__ void __launch_bounds__(256) hash_kernel(
    const float* __restrict__ qk, const float* __restrict__ rot,
    float* __restrict__ outb)
{
    __shared__ float qsT[64*QT_STRIDE];

    int blocksPerB = Ss / TT;                 // 128
    int b  = blockIdx.x / blocksPerB;
    int t0 = (blockIdx.x % blocksPerB) * TT;
    int tid = threadIdx.x;

    {
        int f = tid & 63;
        int i0 = tid >> 6;
        #pragma unroll
        for (int i = i0; i < TT; i += 4)
            qsT[f*QT_STRIDE + i] = qk[((size_t)b*Ss + t0 + i)*Dd + f];
    }
    __syncthreads();

    const float* rb = rot + (size_t)b*64*256 + tid;

    ull acc2[TT/2];
    #pragma unroll
    for (int ip = 0; ip < TT/2; ip++) acc2[ip] = 0ull;
    #pragma unroll 4
    for (int f = 0; f < 64; f++) {
        float rv = __ldg(rb + f*256);
        ull rv2 = pack2(rv, rv);
        #pragma unroll
        for (int ip = 0; ip < TT/2; ip++)
            acc2[ip] = ffma2(ld64s(qsT + f*QT_STRIDE + 2*ip), rv2, acc2[ip]);
    }

    int lane = tid & 31;
    int h    = tid >> 5;
    #pragma unroll
    for (int ip = 0; ip < TT/2; ip++) {
        float va[2];
        unpack2(acc2[ip], va[0], va[1]);
        #pragma unroll
        for (int s = 0; s < 2; s++) {
            float v = va[s];
            float val; int idx;
            if (v >= -v) { val = v;  idx = lane; }
            else         { val = -v; idx = lane + 32; }
            #pragma unroll
            for (int m = 16; m > 0; m >>= 1) {
                float ov = __shfl_xor_sync(0xffffffffu, val, m);
                int   oi = __shfl_xor_sync(0xffffffffu, idx, m);
                if (ov > val || (ov == val && oi < idx)) { val = ov; idx = oi; }
            }
            if (lane == 0) {
                int pos = ((size_t)b*Hh + h)*Ss + t0 + 2*ip + s;
                g_bucket[pos] = idx;
                if (outb) outb[pos] = (float)(idx + h*NB);
            }
        }
    }
}

// ---------------- 2) stable counting sort per (b,h), ballot-ranked ----------
__global__ void __launch_bounds__(256) sort_kernel()
{
    __shared__ int sb[Ss];
    __shared__ int cnt[NB];
    __shared__ int offs[NB + 1];
    int bh   = blockIdx.x;
    int tid  = threadIdx.x;
    int lane = tid & 31;
    int w    = tid >> 5;
    const int base = bh * Ss;

    if (tid < NB) cnt[tid] = 0;
    __syncthreads();
    for (int i = tid; i < Ss; i += 256) {
        int v = g_bucket[base + i];
        sb[i] = v;
        atomicAdd(&cnt[v], 1);
    }
    __syncthreads();
    if (tid == 0) {
        offs[0] = 0;
        for (int k = 0; k < NB; k++) offs[k+1] = offs[k] + cnt[k];
    }
    __syncthreads();

    int off[8];
    #pragma unroll
    for (int k = 0; k < 8; k++) off[k] = offs[8*w + k];

    for (int step = 0; step < Ss/32; step++) {
        int t   = step*32 + lane;
        int rel = sb[t] - 8*w;
        #pragma unroll
        for (int k = 0; k < 8; k++) {
            unsigned mask = __ballot_sync(0xffffffffu, rel == k);
            if (rel == k) {
                int pos = off[k] + __popc(mask & ((1u << lane) - 1u));
                g_perm[base + pos] = t;
            }
            off[k] += __popc(mask);
        }
    }
}

// ---------------- 3) chunked attention: fp16 QK + fp16 PV (prepped) ---------
// ks16[128][36w] : normalized K fp16x2 (rows 0..63 double as Q), from g_kn16
// ph2[64][68w]   : fp16x2 probs (overlays ks16 after QK)
// vhw            : V fp16, transposed [col][k-pair], swizzled
#define KS16_LD 36
#define PH_LD 68
#define SM_KS16 0
#define SM_PH   0                       // overlay
#define SM_VH   (128*KS16_LD)           // 4608
#define SM_PM   (SM_VH + 64*68)         // 8960
#define SM_PS   (SM_PM + 128)
#define SM_QSC  (SM_PS + 128)
#define SM_TK   (SM_QSC + 64)
#define ATTN_SMEM ((SM_TK + 128) * 4)   // 37632 bytes
__global__ void __launch_bounds__(256, 4) attn_kernel()
{
    extern __shared__ float sm[];
    uint*  ks16 = (uint*)(sm + SM_KS16);
    uint*  ph2  = (uint*)(sm + SM_PH);
    uint*  vhw  = (uint*)(sm + SM_VH);
    float* pm   = sm + SM_PM;
    float* ps   = sm + SM_PS;
    float* qsc  = sm + SM_QSC;
    int*   tk   = (int*)(sm + SM_TK);

    int b = blockIdx.x >> 9;
    int c = blockIdx.x & (NCHUNK - 1);
    int h = c >> 6;
    int cprev = (c + NCHUNK - 1) & (NCHUNK - 1);
    int tid = threadIdx.x;
    const int pbase = b * (Hh * Ss);
    const size_t tokbase = (size_t)b*Ss;

    if (tid < 64)        tk[tid] = g_perm[pbase + c*64 + tid];
    else if (tid < 128)  tk[tid] = g_perm[pbase + cprev*64 + (tid - 64)];
    __syncthreads();

    // ---- gather: pure LDG -> (PRMT) -> STS; all math prehoisted ----
    // thread = (col-quad q4, row-pair rp); 4 pairs = 8 rows each.
    {
        int q4 = tid & 15;
        int rp = tid >> 4;
        int kw = q4*2;
        if (tid < 64) qsc[tid] = g_qs[tokbase + tk[tid]];
        #pragma unroll
        for (int pp = 0; pp < 4; pp++) {
            int r0 = 32*pp + 2*rp, r1 = r0 + 1;
            size_t t0 = tokbase + tk[r0], t1 = tokbase + tk[r1];
            uint2 kn0 = *(const uint2*)(g_kn16 + t0*(Dd/2) + kw);
            uint2 kn1 = *(const uint2*)(g_kn16 + t1*(Dd/2) + kw);
            uint2 v0  = *(const uint2*)(g_v16  + t0*(Dd/2) + kw);
            uint2 v1  = *(const uint2*)(g_v16  + t1*(Dd/2) + kw);
            *(uint2*)(ks16 + r0*KS16_LD + kw) = kn0;
            *(uint2*)(ks16 + r1*KS16_LD + kw) = kn1;
            // V transpose repack: word (col e) = (v[r0][e], v[r1][e])
            int kp = r0 >> 1;
            int e0 = q4*4;
            vhw[(e0+0)*68 + (kp ^ ((e0+0) >> 2))] = __byte_perm(v0.x, v1.x, 0x5410);
            vhw[(e0+1)*68 + (kp ^ ((e0+1) >> 2))] = __byte_perm(v0.x, v1.x, 0x7632);
            vhw[(e0+2)*68 + (kp ^ ((e0+2) >> 2))] = __byte_perm(v0.y, v1.y, 0x5410);
            vhw[(e0+3)*68 + (kp ^ ((e0+3) >> 2))] = __byte_perm(v0.y, v1.y, 0x7632);
        }
    }
    __syncthreads();

    // ---- QK^T : 64x128x64 fp16 m16n8k16, per warp m16 x n64 ----
    int wid   = tid >> 5;
    int lane  = tid & 31;
    int gr    = lane >> 2;
    int cl    = lane & 3;
    int mrow  = 16*(wid & 3);
    int chalf = wid >> 2;
    int ncol  = 64*chalf;

    float acc[8][4];
    #pragma unroll
    for (int n = 0; n < 8; n++)
        #pragma unroll
        for (int i = 0; i < 4; i++) acc[n][i] = 0.f;

    {
        const uint* ar0 = ks16 + (mrow + gr)*KS16_LD;
        const uint* ar1 = ar0 + 8*KS16_LD;
        #pragma unroll
        for (int k0 = 0; k0 < 4; k0++) {
            int wa = 8*k0 + cl;
            uint a0 = ar0[wa], a1 = ar1[wa], a2 = ar0[wa+4], a3 = ar1[wa+4];
            #pragma unroll
            for (int n = 0; n < 8; n++) {
                const uint* bp = ks16 + (ncol + 8*n + gr)*KS16_LD;
                uint b0 = bp[wa], b1 = bp[wa+4];
                mma_f16(acc[n], a0, a1, a2, a3, b0, b1);
            }
        }
    }

    // ---- mask + scale + per-half softmax partials ----
    int row0 = mrow + gr, row1 = row0 + 8;
    int tr0 = tk[row0], tr1 = tk[row1];
    float sc0 = qsc[row0], sc1 = qsc[row1];
    float m0 = -1e30f, m1 = -1e30f;
    #pragma unroll
    for (int n = 0; n < 8; n++) {
        int j0 = ncol + 8*n + 2*cl;
        int tj0 = tk[j0], tj1 = tk[j0 + 1];
        float d0 = (tj0 == tr0) ? NEGV : acc[n][0]*sc0;
        float d1 = (tj1 == tr0) ? NEGV : acc[n][1]*sc0;
        float d2 = (tj0 == tr1) ? NEGV : acc[n][2]*sc1;
        float d3 = (tj1 == tr1) ? NEGV : acc[n][3]*sc1;
        acc[n][0] = d0; acc[n][1] = d1; acc[n][2] = d2; acc[n][3] = d3;
        m0 = fmaxf(m0, fmaxf(d0, d1));
        m1 = fmaxf(m1, fmaxf(d2, d3));
    }
    #pragma unroll
    for (int s = 1; s < 4; s <<= 1) {
        m0 = fmaxf(m0, __shfl_xor_sync(0xffffffffu, m0, s));
        m1 = fmaxf(m1, __shfl_xor_sync(0xffffffffu, m1, s));
    }
    float s0 = 0.f, s1 = 0.f;
    #pragma unroll
    for (int n = 0; n < 8; n++) {
        float e0 = __expf(acc[n][0] - m0);
        float e1 = __expf(acc[n][1] - m0);
        float e2 = __expf(acc[n][2] - m1);
        float e3 = __expf(acc[n][3] - m1);
        acc[n][0] = e0; acc[n][1] = e1; acc[n][2] = e2; acc[n][3] = e3;
        s0 += e0 + e1;
        s1 += e2 + e3;
    }
    #pragma unroll
    for (int s = 1; s < 4; s <<= 1) {
        s0 += __shfl_xor_sync(0xffffffffu, s0, s);
        s1 += __shfl_xor_sync(0xffffffffu, s1, s);
    }
    if (cl == 0) {
        pm[chalf*64 + row0] = m0;  ps[chalf*64 + row0] = s0;
        pm[chalf*64 + row1] = m1;  ps[chalf*64 + row1] = s1;
    }
    __syncthreads();   // partials visible; ALL warps done reading ks16

    float Ma0 = pm[row0], Mb0 = pm[64 + row0];
    float M0  = fmaxf(Ma0, Mb0);
    float S0  = ps[row0]*__expf(Ma0 - M0) + ps[64 + row0]*__expf(Mb0 - M0);
    float lse0 = M0 + __logf(S0);
    float Ma1 = pm[row1], Mb1 = pm[64 + row1];
    float M1  = fmaxf(Ma1, Mb1);
    float S1  = ps[row1]*__expf(Ma1 - M1) + ps[64 + row1]*__expf(Mb1 - M1);
    float lse1 = M1 + __logf(S1);

    if (cl == 0 && chalf == 0) {
        g_logits[pbase + h*Ss + tr0] = lse0;
        g_logits[pbase + h*Ss + tr1] = lse1;
    }

    // probs = e * exp(m - lse) as fp16x2 packed pairs (overlay ks16)
    {
        float f0 = __expf(m0 - lse0);
        float f1 = __expf(m1 - lse1);
        int pw0 = row0*PH_LD + (ncol >> 1) + cl;
        int pw1 = row1*PH_LD + (ncol >> 1) + cl;
        #pragma unroll
        for (int n = 0; n < 8; n++) {
            ph2[pw0 + 4*n] = pack_f16x2(acc[n][0] * f0, acc[n][1] * f0);
            ph2[pw1 + 4*n] = pack_f16x2(acc[n][2] * f1, acc[n][3] * f1);
        }
    }
    __syncthreads();

    // ---- PV : 64x64x128 fp16 single-term, m16n8k16, per warp m16 x n32 ----
    int ocol = 32*chalf;
    float oacc[4][4];
    #pragma unroll
    for (int n = 0; n < 4; n++)
        #pragma unroll
        for (int i = 0; i < 4; i++) oacc[n][i] = 0.f;

    int ebase[4], sxor[4];
    #pragma unroll
    for (int n = 0; n < 4; n++) {
        int e = ocol + 8*n + gr;
        ebase[n] = e*68;
        sxor[n]  = e >> 2;
    }
    const uint* ph2r0 = ph2 + row0*PH_LD;
    const uint* ph2r1 = ph2 + row1*PH_LD;

    #pragma unroll 2
    for (int k0 = 0; k0 < 8; k0++) {
        int wa = 8*k0 + cl;
        uint ah0 = ph2r0[wa], ah1 = ph2r1[wa], ah2 = ph2r0[wa+4], ah3 = ph2r1[wa+4];
        #pragma unroll
        for (int n = 0; n < 4; n++) {
            uint bh0 = vhw[ebase[n] + (wa ^ sxor[n])];
            uint bh1 = vhw[ebase[n] + ((wa + 4) ^ sxor[n])];
            mma_f16(oacc[n], ah0, ah1, ah2, ah3, bh0, bh1);
        }
    }

    // ---- scatter to g_o16 (fp16x2) ----
    {
        uint* orow0 = g_o16 + (size_t)(pbase + h*Ss + tr0)*(Dd/2);
        uint* orow1 = g_o16 + (size_t)(pbase + h*Ss + tr1)*(Dd/2);
        #pragma unroll
        for (int n = 0; n < 4; n++) {
            int wcol = (ocol >> 1) + 4*n + cl;
            orow0[wcol] = pack_f16x2(oacc[n][0], oacc[n][1]);
            orow1[wcol] = pack_f16x2(oacc[n][2], oacc[n][3]);
        }
    }
}

// ---------------- 4) combine hash rounds via softmax(logits) ----------------
__global__ void __launch_bounds__(256) combine_kernel(float* __restrict__ out)
{
    size_t gid = (size_t)blockIdx.x*256 + threadIdx.x;
    if (gid >= (size_t)Bb*Ss*Dd/8) return;
    int pair = (int)(gid & 7);
    size_t bt = gid >> 3;
    int t = (int)(bt & (Ss - 1));
    int b = (int)(bt >> 12);

    float l[Hh];
    float m = -1e30f;
    #pragma unroll
    for (int h = 0; h < Hh; h++) {
        l[h] = g_logits[((size_t)(b*Hh + h))*Ss + t];
        m = fmaxf(m, l[h]);
    }
    float ssum = 0.f;
    #pragma unroll
    for (int h = 0; h < Hh; h++) { l[h] = __expf(l[h] - m); ssum += l[h]; }
    float inv = 1.f / ssum;

    float4 acc0 = make_float4(0.f, 0.f, 0.f, 0.f);
    float4 acc1 = make_float4(0.f, 0.f, 0.f, 0.f);
    #pragma unroll
    for (int h = 0; h < Hh; h++) {
        float w = l[h]*inv;
        const uint4 ow = *(const uint4*)(g_o16 + (((size_t)(b*Hh + h))*Ss + t)*(Dd/2) + pair*4);
        float2 f0 = __half22float2(*(const __half2*)&ow.x);
        float2 f1 = __half22float2(*(const __half2*)&ow.y);
        float2 f2 = __half22float2(*(const __half2*)&ow.z);
        float2 f3 = __half22float2(*(const __half2*)&ow.w);
        acc0.x += w*f0.x; acc0.y += w*f0.y; acc0.z += w*f1.x; acc0.w += w*f1.y;
        acc1.x += w*f2.x; acc1.y += w*f2.y; acc1.z += w*f3.x; acc1.w += w*f3.y;
    }
    float* dst = out + bt*Dd + pair*8;
    *(float4*)(dst)     = acc0;
    *(float4*)(dst + 4) = acc1;
}

// ---------------- launch ------------------------------------------------------
extern "C" void kernel_launch(void* const* d_in, const int* in_sizes, int n_in,
                              void* d_out, int out_size)
{
    const float* qk  = (const float*)d_in[0];
    const float* v   = (const float*)d_in[1];
    const float* rot = (const float*)d_in[2];
    float* out = (float*)d_out;

    cudaFuncSetAttribute(attn_kernel, cudaFuncAttributeMaxDynamicSharedMemorySize, ATTN_SMEM);

    float* outb = (out_size >= Bb*Ss*Dd + Bb*Hh*Ss) ? (out + (size_t)Bb*Ss*Dd) : nullptr;

    prep_kernel<<<Bb*Ss/16, 256>>>(qk, v);
    hash_kernel<<<Bb*(Ss/TT), 256>>>(qk, rot, outb);
    sort_kernel<<<Bb*Hh, 256>>>();
    attn_kernel<<<Bb*NCHUNK, 256, ATTN_SMEM>>>();
    combine_kernel<<<(int)(((size_t)Bb*Ss*Dd/8 + 255)/256), 256>>>(out);
}